// round 13
// baseline (speedup 1.0000x reference)
#include <cuda_runtime.h>
#include <cuda_bf16.h>
#include <math.h>
#include <stdint.h>

#define D    512
#define H3   1536
#define NH   8
#define DHD  64
#define NSEQ 10001
#define NPAD 10240
#define PADN 239
#define ML   256
#define NSPL 8
#define KCH  (NPAD/NSPL)

typedef __nv_bfloat16 bf16;

// ------------------------- scratch (device globals) -------------------------
__device__ float g_X  [NSEQ*D];
__device__ float g_X2 [NSEQ*D];
__device__ float g_LN [NPAD*D];
__device__ float g_LNm[ML*D];
__device__ float g_QKV[(size_t)NPAD*H3];
__device__ float g_klT[NH*DHD*ML];
__device__ float g_ql [NH*ML*DHD];
__device__ float g_a1 [(size_t)NH*NPAD*ML];
__device__ float g_a3 [(size_t)NH*ML*NPAD];
__device__ float g_a2 [NH*ML*ML];
__device__ float g_Za [NH*ML*ML];
__device__ float g_Zb [NH*ML*ML];
__device__ float g_XZ [NH*ML*ML];
__device__ float g_M2 [NH*ML*ML];
__device__ float g_M4 [NH*ML*ML];
__device__ float g_ttp[(size_t)NH*NSPL*ML*DHD];
__device__ float g_tt [NH*ML*DHD];
__device__ float g_uu [NH*ML*DHD];
__device__ float g_O  [(size_t)NPAD*D];
__device__ float g_smx [NH*NPAD];
__device__ float g_sinv[NH*NPAD];
__device__ float g_orow[D];
__device__ float g_rsum[NH*ML];
__device__ float g_csum[NH*ML];
__device__ float g_invden;
// bf16 hi/lo operand buffers
__device__ bf16 g_Ah[(size_t)NPAD*1024];
__device__ bf16 g_Al[(size_t)NPAD*1024];
__device__ bf16 g_Wth[1536*512];
__device__ bf16 g_Wtl[1536*512];
__device__ bf16 g_KVh[(size_t)NPAD*H3];
__device__ bf16 g_KVl[(size_t)NPAD*H3];
__device__ bf16 g_qlh[NH*ML*DHD];
__device__ bf16 g_qll[NH*ML*DHD];
__device__ bf16 g_klh[NH*ML*DHD];
__device__ bf16 g_kll[NH*ML*DHD];
__device__ bf16 g_Ph [(size_t)NH*NPAD*ML];
__device__ bf16 g_Pl [(size_t)NH*NPAD*ML];
__device__ bf16 g_uuh[NH*ML*DHD];
__device__ bf16 g_uul[NH*ML*DHD];
// pinv chain bf16 pairs
__device__ bf16 g_a2h[NH*ML*ML];
__device__ bf16 g_a2l[NH*ML*ML];
__device__ bf16 g_Zah[NH*ML*ML];
__device__ bf16 g_Zal[NH*ML*ML];
__device__ bf16 g_Zbh[NH*ML*ML];
__device__ bf16 g_Zbl[NH*ML*ML];
__device__ bf16 g_XZh[NH*ML*ML];
__device__ bf16 g_XZl[NH*ML*ML];
__device__ bf16 g_M2h[NH*ML*ML];
__device__ bf16 g_M2l[NH*ML*ML];
__device__ bf16 g_M4h[NH*ML*ML];
__device__ bf16 g_M4l[NH*ML*ML];

// ------------------------- f32x2 helpers -------------------------
typedef unsigned long long ull;
__device__ __forceinline__ void fma2(ull& d, ull a, ull b){
    asm("fma.rn.f32x2 %0, %1, %2, %0;" : "+l"(d) : "l"(a), "l"(b));
}
__device__ __forceinline__ ull dup2(float b){
    ull r; asm("mov.b64 %0, {%1, %1};" : "=l"(r) : "f"(b)); return r;
}
__device__ __forceinline__ float lof(ull v){ return __uint_as_float((unsigned)v); }
__device__ __forceinline__ float hif(ull v){ return __uint_as_float((unsigned)(v>>32)); }

__device__ __forceinline__ uint32_t s2u(const void* p){
    uint32_t a;
    asm("{ .reg .u64 t; cvta.to.shared.u64 t, %1; cvt.u32.u64 %0, t; }" : "=r"(a) : "l"(p));
    return a;
}
#define LDSM4(r0,r1,r2,r3,addr) \
    asm volatile("ldmatrix.sync.aligned.m8n8.x4.shared.b16 {%0,%1,%2,%3}, [%4];" \
        : "=r"(r0),"=r"(r1),"=r"(r2),"=r"(r3) : "r"(addr))
#define LDSM4T(r0,r1,r2,r3,addr) \
    asm volatile("ldmatrix.sync.aligned.m8n8.x4.trans.shared.b16 {%0,%1,%2,%3}, [%4];" \
        : "=r"(r0),"=r"(r1),"=r"(r2),"=r"(r3) : "r"(addr))
#define MMA16816(d, a, b) \
    asm volatile("mma.sync.aligned.m16n8k16.row.col.f32.bf16.bf16.f32 " \
        "{%0,%1,%2,%3},{%4,%5,%6,%7},{%8,%9},{%0,%1,%2,%3};" \
        : "+f"((d)[0]),"+f"((d)[1]),"+f"((d)[2]),"+f"((d)[3]) \
        : "r"((a)[0]),"r"((a)[1]),"r"((a)[2]),"r"((a)[3]), "r"((b)[0]),"r"((b)[1]))
#define CPA(dst, src, sz) \
    asm volatile("cp.async.ca.shared.global [%0], [%1], 16, %2;" \
        :: "r"(dst), "l"(src), "r"(sz) : "memory")
#define CPA_COMMIT() asm volatile("cp.async.commit_group;" ::: "memory")
#define CPA_WAIT0()  asm volatile("cp.async.wait_group 0;" ::: "memory")

// ------------------------- block reductions (256 thr) -------------------------
__device__ __forceinline__ float blkSum256(float v, float* sh){
#pragma unroll
    for(int o=16;o;o>>=1) v += __shfl_xor_sync(0xffffffffu, v, o);
    __syncthreads();
    if((threadIdx.x&31)==0) sh[threadIdx.x>>5]=v;
    __syncthreads();
    float r = sh[0];
#pragma unroll
    for(int i=1;i<8;i++) r += sh[i];
    return r;
}
__device__ __forceinline__ float blkMax256(float v, float* sh){
#pragma unroll
    for(int o=16;o;o>>=1) v = fmaxf(v, __shfl_xor_sync(0xffffffffu, v, o));
    __syncthreads();
    if((threadIdx.x&31)==0) sh[threadIdx.x>>5]=v;
    __syncthreads();
    float r = sh[0];
#pragma unroll
    for(int i=1;i<8;i++) r = fmaxf(r, sh[i]);
    return r;
}

// ------------------------- bf16 hi/lo converters -------------------------
__device__ __forceinline__ void split_bf(float a, bf16& h, bf16& l){
    h = __float2bfloat16_rn(a);
    l = __float2bfloat16_rn(a - __bfloat162float(h));
}
__global__ void cvt_rows_k(const float* __restrict__ s, bf16* __restrict__ dh,
                           bf16* __restrict__ dl){
    size_t i = ((size_t)blockIdx.x*256 + threadIdx.x)*4;
    float4 v = *reinterpret_cast<const float4*>(s+i);
    bf16 h[4], l[4];
    split_bf(v.x,h[0],l[0]); split_bf(v.y,h[1],l[1]);
    split_bf(v.z,h[2],l[2]); split_bf(v.w,h[3],l[3]);
    *reinterpret_cast<uint2*>(dh+i) = *reinterpret_cast<uint2*>(h);
    *reinterpret_cast<uint2*>(dl+i) = *reinterpret_cast<uint2*>(l);
}
__global__ void cvt_T_k(const float* __restrict__ W, bf16* __restrict__ dh,
                        bf16* __restrict__ dl, int Kd, int Nd){
    __shared__ float sm[32][33];
    int k0 = blockIdx.x*32, n0 = blockIdx.y*32;
    int c = threadIdx.x & 31, r = threadIdx.x >> 5;
#pragma unroll
    for(int p=0;p<4;p++)
        sm[p*8+r][c] = W[(size_t)(k0+p*8+r)*Nd + n0 + c];
    __syncthreads();
#pragma unroll
    for(int p=0;p<4;p++){
        int nn = p*8 + r;
        float v = sm[c][nn];
        bf16 h,l; split_bf(v,h,l);
        dh[(size_t)(n0+nn)*Kd + k0 + c] = h;
        dl[(size_t)(n0+nn)*Kd + k0 + c] = l;
    }
}

// ---------- bf16x3 tensor-core GEMM, 2-stage cp.async pipeline (2 CTA/SM) ----------
#define MS  (128*40)
#define SM_MMA (2*4*MS*2)
__global__ __launch_bounds__(256,2)
void gemm_mma_k(const bf16* __restrict__ Ahp, const bf16* __restrict__ Alp,
                const bf16* __restrict__ Bhp, const bf16* __restrict__ Blp,
                const float* __restrict__ bias, const float* __restrict__ R,
                float* __restrict__ C, int M, int N, int K, int ldc,
                int DOBIAS, int DORES, int DORELU,
                bf16* __restrict__ Chp, bf16* __restrict__ Clp)
{
    extern __shared__ bf16 smp[];
    int tid = threadIdx.x, lane = tid & 31, wid = tid >> 5;
    int wm = wid >> 2, wn = wid & 3;
    int bm = blockIdx.y * 128, bn = blockIdx.x * 128;
    uint32_t sbase = s2u(smp);
    float acc[4][4][4];
#pragma unroll
    for(int i=0;i<4;i++)
#pragma unroll
        for(int j=0;j<4;j++)
#pragma unroll
            for(int q=0;q<4;q++) acc[i][j][q]=0.f;

    int lr = tid >> 1, ls = (tid & 1) * 16;
    int aok = (bm + lr < M) ? 16 : 0;
    const bf16* gAh = Ahp + (size_t)(bm+lr)*K + ls;
    const bf16* gAl = Alp + (size_t)(bm+lr)*K + ls;
    const bf16* gBh = Bhp + (size_t)(bn+lr)*K + ls;
    const bf16* gBl = Blp + (size_t)(bn+lr)*K + ls;
    uint32_t dOff = (uint32_t)((lr*40 + ls)*2);

    int aRow = wm*64 + (lane&7) + ((lane>>3)&1)*8;
    int aCol = (lane>>4)*8;
    int bRow = wn*32 + (lane&7) + (lane>>4)*8;
    int bCol = ((lane>>3)&1)*8;

    int nch = K >> 5;
#define PREF(ch, st) do{ \
    uint32_t db = sbase + (uint32_t)(st)*(4*MS*2) + dOff; \
    size_t go = (size_t)(ch)*32; \
    CPA(db,          gAh+go, aok); CPA(db+16,          gAh+go+8, aok); \
    CPA(db+MS*2,     gAl+go, aok); CPA(db+MS*2+16,     gAl+go+8, aok); \
    CPA(db+MS*4,     gBh+go, 16);  CPA(db+MS*4+16,     gBh+go+8, 16); \
    CPA(db+MS*6,     gBl+go, 16);  CPA(db+MS*6+16,     gBl+go+8, 16); \
    CPA_COMMIT(); }while(0)

    PREF(0, 0);

    for(int ch=0; ch<nch; ch++){
        CPA_WAIT0();
        __syncthreads();
        if(ch+1 < nch) PREF(ch+1, (ch+1)&1);
        uint32_t stb = sbase + (uint32_t)(ch&1)*(4*MS*2);
        uint32_t bAh = stb, bAl = stb + MS*2, bBh = stb + MS*4, bBl = stb + MS*6;
#pragma unroll
        for(int ks=0; ks<2; ks++){
            int kc = ks*16;
            uint32_t bh[4][2], bl[4][2];
#pragma unroll
            for(int ntp=0; ntp<2; ntp++){
                uint32_t off = (uint32_t)(((bRow + ntp*16)*40 + kc + bCol)*2);
                LDSM4(bh[2*ntp][0], bh[2*ntp][1], bh[2*ntp+1][0], bh[2*ntp+1][1], bBh + off);
                LDSM4(bl[2*ntp][0], bl[2*ntp][1], bl[2*ntp+1][0], bl[2*ntp+1][1], bBl + off);
            }
#pragma unroll
            for(int mt=0; mt<4; mt++){
                uint32_t off = (uint32_t)(((aRow + mt*16)*40 + kc + aCol)*2);
                uint32_t ah[4], al[4];
                LDSM4(ah[0],ah[1],ah[2],ah[3], bAh + off);
                LDSM4(al[0],al[1],al[2],al[3], bAl + off);
#pragma unroll
                for(int nt=0; nt<4; nt++){
                    MMA16816(acc[mt][nt], ah, bh[nt]);
                    MMA16816(acc[mt][nt], ah, bl[nt]);
                    MMA16816(acc[mt][nt], al, bh[nt]);
                }
            }
        }
    }
#undef PREF
#pragma unroll
    for(int mt=0; mt<4; mt++){
#pragma unroll
        for(int nt=0; nt<4; nt++){
            int n = bn + wn*32 + nt*8 + (lane&3)*2;
#pragma unroll
            for(int h=0; h<2; h++){
                int m = bm + wm*64 + mt*16 + (lane>>2) + h*8;
                if(m < M){
                    float v0 = acc[mt][nt][h*2], v1 = acc[mt][nt][h*2+1];
                    if(DOBIAS){ v0 += bias[n]; v1 += bias[n+1]; }
                    if(DORES){
                        const float* rp = R + (size_t)m*ldc + n;
                        v0 += rp[0]; v1 += rp[1];
                    }
                    if(DORELU){ v0 = fmaxf(v0,0.f); v1 = fmaxf(v1,0.f); }
                    float2 o; o.x = v0; o.y = v1;
                    *reinterpret_cast<float2*>(C + (size_t)m*ldc + n) = o;
                    if(Chp){
                        bf16 hh[2], ll[2];
                        split_bf(v0, hh[0], ll[0]);
                        split_bf(v1, hh[1], ll[1]);
                        *reinterpret_cast<uint32_t*>(Chp + (size_t)m*ldc + n) = *reinterpret_cast<uint32_t*>(hh);
                        *reinterpret_cast<uint32_t*>(Clp + (size_t)m*ldc + n) = *reinterpret_cast<uint32_t*>(ll);
                    }
                }
            }
        }
    }
}

// ---------- batched/strided bf16x3 MMA GEMM: C = scale*(A@B), B [N][K] rows ----------
__global__ __launch_bounds__(256,2)
void gemm_mma_b_k(const bf16* __restrict__ Ahp, const bf16* __restrict__ Alp,
                  const bf16* __restrict__ Bhp, const bf16* __restrict__ Blp,
                  float* __restrict__ C, int N, int K,
                  int lda, int ldb, int ldc,
                  long long sA, long long sB, long long sC, float scale)
{
    extern __shared__ bf16 smp[];
    int tid = threadIdx.x, lane = tid & 31, wid = tid >> 5;
    int wm = wid >> 2, wn = wid & 3;
    int bm = blockIdx.y * 128, bn = blockIdx.x * 128;
    int z = blockIdx.z;
    uint32_t sbase = s2u(smp);
    float acc[4][4][4];
#pragma unroll
    for(int i=0;i<4;i++)
#pragma unroll
        for(int j=0;j<4;j++)
#pragma unroll
            for(int q=0;q<4;q++) acc[i][j][q]=0.f;

    int lr = tid >> 1, ls = (tid & 1) * 16;
    const bf16* gAh = Ahp + (size_t)z*sA + (size_t)(bm+lr)*lda + ls;
    const bf16* gAl = Alp + (size_t)z*sA + (size_t)(bm+lr)*lda + ls;
    const bf16* gBh = Bhp + (size_t)z*sB + (size_t)(bn+lr)*ldb + ls;
    const bf16* gBl = Blp + (size_t)z*sB + (size_t)(bn+lr)*ldb + ls;
    uint32_t dOff = (uint32_t)((lr*40 + ls)*2);

    int aRow = wm*64 + (lane&7) + ((lane>>3)&1)*8;
    int aCol = (lane>>4)*8;
    int bRow = wn*32 + (lane&7) + (lane>>4)*8;
    int bCol = ((lane>>3)&1)*8;

    int nch = K >> 5;
#define PREF(ch, st) do{ \
    uint32_t db = sbase + (uint32_t)(st)*(4*MS*2) + dOff; \
    size_t go = (size_t)(ch)*32; \
    CPA(db,          gAh+go, 16); CPA(db+16,          gAh+go+8, 16); \
    CPA(db+MS*2,     gAl+go, 16); CPA(db+MS*2+16,     gAl+go+8, 16); \
    CPA(db+MS*4,     gBh+go, 16); CPA(db+MS*4+16,     gBh+go+8, 16); \
    CPA(db+MS*6,     gBl+go, 16); CPA(db+MS*6+16,     gBl+go+8, 16); \
    CPA_COMMIT(); }while(0)

    PREF(0, 0);

    for(int ch=0; ch<nch; ch++){
        CPA_WAIT0();
        __syncthreads();
        if(ch+1 < nch) PREF(ch+1, (ch+1)&1);
        uint32_t stb = sbase + (uint32_t)(ch&1)*(4*MS*2);
        uint32_t bAh = stb, bAl = stb + MS*2, bBh = stb + MS*4, bBl = stb + MS*6;
#pragma unroll
        for(int ks=0; ks<2; ks++){
            int kc = ks*16;
            uint32_t bh[4][2], bl[4][2];
#pragma unroll
            for(int ntp=0; ntp<2; ntp++){
                uint32_t off = (uint32_t)(((bRow + ntp*16)*40 + kc + bCol)*2);
                LDSM4(bh[2*ntp][0], bh[2*ntp][1], bh[2*ntp+1][0], bh[2*ntp+1][1], bBh + off);
                LDSM4(bl[2*ntp][0], bl[2*ntp][1], bl[2*ntp+1][0], bl[2*ntp+1][1], bBl + off);
            }
#pragma unroll
            for(int mt=0; mt<4; mt++){
                uint32_t off = (uint32_t)(((aRow + mt*16)*40 + kc + aCol)*2);
                uint32_t ah[4], al[4];
                LDSM4(ah[0],ah[1],ah[2],ah[3], bAh + off);
                LDSM4(al[0],al[1],al[2],al[3], bAl + off);
#pragma unroll
                for(int nt=0; nt<4; nt++){
                    MMA16816(acc[mt][nt], ah, bh[nt]);
                    MMA16816(acc[mt][nt], ah, bl[nt]);
                    MMA16816(acc[mt][nt], al, bh[nt]);
                }
            }
        }
    }
#undef PREF
    float* Cb = C + (size_t)z*sC;
#pragma unroll
    for(int mt=0; mt<4; mt++){
#pragma unroll
        for(int nt=0; nt<4; nt++){
            int n = bn + wn*32 + nt*8 + (lane&3)*2;
#pragma unroll
            for(int h=0; h<2; h++){
                int m = bm + wm*64 + mt*16 + (lane>>2) + h*8;
                float2 o;
                o.x = scale * acc[mt][nt][h*2];
                o.y = scale * acc[mt][nt][h*2+1];
                *reinterpret_cast<float2*>(Cb + (size_t)m*ldc + n) = o;
            }
        }
    }
}

// ---------- bf16x3 MMA GEMM, tile 128x64, B stored K-MAJOR (ldmatrix.trans) ----------
#define MSA (128*40)
#define MSB (32*72)
#define STG64 (2*MSA + 2*MSB)
#define SM_N64 (2*STG64*2)
__global__ __launch_bounds__(256,2)
void gemm_mma_n64t_k(const bf16* __restrict__ Ahp, const bf16* __restrict__ Alp,
                     const bf16* __restrict__ Bhp, const bf16* __restrict__ Blp,
                     float* __restrict__ C, int lda, int ldb, int ldc,
                     long long sA, long long sB, long long sC,
                     const float* __restrict__ AUX, float beta,
                     int kc, long long sSplit)
{
    extern __shared__ bf16 smp[];
    int tid = threadIdx.x, lane = tid & 31, wid = tid >> 5;
    int wm = wid >> 1, wn = wid & 1;
    int bm = blockIdx.y * 128;
    int sp = blockIdx.x, z = blockIdx.z;
    uint32_t sbase = s2u(smp);
    float acc[2][4][4];
#pragma unroll
    for(int i=0;i<2;i++)
#pragma unroll
        for(int j=0;j<4;j++)
#pragma unroll
            for(int q=0;q<4;q++) acc[i][j][q]=0.f;

    int ks = sp * kc;
    int lr = tid >> 1, lsa = (tid & 1) * 16;
    const bf16* gAh = Ahp + (size_t)z*sA + (size_t)(bm+lr)*lda + ks + lsa;
    const bf16* gAl = Alp + (size_t)z*sA + (size_t)(bm+lr)*lda + ks + lsa;
    uint32_t aOff = (uint32_t)((lr*40 + lsa)*2);
    int brow = tid >> 3, bcs = (tid & 7) * 8;
    const bf16* gBh = Bhp + (size_t)z*sB + (size_t)(ks+brow)*ldb + bcs;
    const bf16* gBl = Blp + (size_t)z*sB + (size_t)(ks+brow)*ldb + bcs;
    uint32_t bOff = (uint32_t)((brow*72 + bcs)*2);

    int aCol = (lane>>4)*8;
    int bKr = (lane&7) + ((lane>>3)&1)*8;
    int bNc = (lane>>4)*8;

    int nch = kc >> 5;
#define PREF(ch, st) do{ \
    uint32_t stb = sbase + (uint32_t)(st)*(STG64*2); \
    size_t goA = (size_t)(ch)*32; \
    size_t goB = (size_t)(ch)*32*ldb; \
    CPA(stb + aOff,             gAh+goA, 16); CPA(stb + aOff + 16,             gAh+goA+8, 16); \
    CPA(stb + MSA*2 + aOff,     gAl+goA, 16); CPA(stb + MSA*2 + aOff + 16,     gAl+goA+8, 16); \
    CPA(stb + MSA*4 + bOff,     gBh+goB, 16); \
    CPA(stb + MSA*4 + MSB*2 + bOff, gBl+goB, 16); \
    CPA_COMMIT(); }while(0)

    PREF(0, 0);

    for(int ch=0; ch<nch; ch++){
        CPA_WAIT0();
        __syncthreads();
        if(ch+1 < nch) PREF(ch+1, (ch+1)&1);
        uint32_t stb = sbase + (uint32_t)(ch&1)*(STG64*2);
        uint32_t bAh = stb, bAl = stb + MSA*2;
        uint32_t bBh = stb + MSA*4, bBl = stb + MSA*4 + MSB*2;
#pragma unroll
        for(int ksu=0; ksu<2; ksu++){
            int kb = ksu*16;
            uint32_t bh[4][2], bl[4][2];
#pragma unroll
            for(int ntp=0; ntp<2; ntp++){
                uint32_t off = (uint32_t)(((kb + bKr)*72 + wn*32 + ntp*16 + bNc)*2);
                LDSM4T(bh[2*ntp][0], bh[2*ntp][1], bh[2*ntp+1][0], bh[2*ntp+1][1], bBh + off);
                LDSM4T(bl[2*ntp][0], bl[2*ntp][1], bl[2*ntp+1][0], bl[2*ntp+1][1], bBl + off);
            }
#pragma unroll
            for(int mt=0; mt<2; mt++){
                uint32_t off = (uint32_t)(((wm*32 + mt*16 + (lane&7) + ((lane>>3)&1)*8)*40 + kb + aCol)*2);
                uint32_t ah[4], al[4];
                LDSM4(ah[0],ah[1],ah[2],ah[3], bAh + off);
                LDSM4(al[0],al[1],al[2],al[3], bAl + off);
#pragma unroll
                for(int nt=0; nt<4; nt++){
                    MMA16816(acc[mt][nt], ah, bh[nt]);
                    MMA16816(acc[mt][nt], ah, bl[nt]);
                    MMA16816(acc[mt][nt], al, bh[nt]);
                }
            }
        }
    }
#undef PREF
    float* Cb = C + (size_t)z*sC + (size_t)sp*sSplit;
    const float* Xb = AUX ? AUX + (size_t)z*sC : nullptr;
#pragma unroll
    for(int mt=0; mt<2; mt++){
#pragma unroll
        for(int nt=0; nt<4; nt++){
            int n = wn*32 + nt*8 + (lane&3)*2;
#pragma unroll
            for(int h=0; h<2; h++){
                int m = bm + wm*32 + mt*16 + (lane>>2) + h*8;
                float v0 = acc[mt][nt][h*2], v1 = acc[mt][nt][h*2+1];
                if(Xb){
                    const float* xp = Xb + (size_t)m*ldc + n;
                    v0 += beta*xp[0]; v1 += beta*xp[1];
                }
                float2 o; o.x = v0; o.y = v1;
                *reinterpret_cast<float2*>(Cb + (size_t)m*ldc + n) = o;
            }
        }
    }
}

// ---------- batched square bf16x3 MMA GEMM (pinv): 256x256x256, B K-MAJOR ----------
// C = scale*(A@B) + beta*AUX + diag*I; writes fp32 C and bf16 hi/lo Ch/Cl.
#define SQA (128*40)
#define SQB (32*136)
#define SQSTG (2*SQA + 2*SQB)
#define SM_SQ (2*SQSTG*2)
__global__ __launch_bounds__(256,2)
void gemm_mma_sq_k(const bf16* __restrict__ Ahp, const bf16* __restrict__ Alp,
                   const bf16* __restrict__ Bhp, const bf16* __restrict__ Blp,
                   float* __restrict__ C, bf16* __restrict__ Chp, bf16* __restrict__ Clp,
                   float scale, float diag, const float* __restrict__ AUX, float beta)
{
    extern __shared__ bf16 smp[];
    int tid = threadIdx.x, lane = tid & 31, wid = tid >> 5;
    int wm = wid >> 2, wn = wid & 3;
    int bm = blockIdx.y * 128, bn = blockIdx.x * 128;
    size_t zo = (size_t)blockIdx.z * (ML*ML);
    uint32_t sbase = s2u(smp);
    float acc[4][4][4];
#pragma unroll
    for(int i=0;i<4;i++)
#pragma unroll
        for(int j=0;j<4;j++)
#pragma unroll
            for(int q=0;q<4;q++) acc[i][j][q]=0.f;

    int lr = tid >> 1, lsa = (tid & 1) * 16;
    const bf16* gAh = Ahp + zo + (size_t)(bm+lr)*ML + lsa;
    const bf16* gAl = Alp + zo + (size_t)(bm+lr)*ML + lsa;
    uint32_t aOff = (uint32_t)((lr*40 + lsa)*2);
    int brow = tid >> 3, bcs = (tid & 7) * 16;
    const bf16* gBh = Bhp + zo + (size_t)brow*ML + bn + bcs;
    const bf16* gBl = Blp + zo + (size_t)brow*ML + bn + bcs;
    uint32_t bOff = (uint32_t)((brow*136 + bcs)*2);

    int aCol = (lane>>4)*8;
    int bKr = (lane&7) + ((lane>>3)&1)*8;
    int bNc = (lane>>4)*8;

#define PREF(ch, st) do{ \
    uint32_t stb = sbase + (uint32_t)(st)*(SQSTG*2); \
    size_t goA = (size_t)(ch)*32; \
    size_t goB = (size_t)(ch)*32*ML; \
    CPA(stb + aOff,         gAh+goA, 16); CPA(stb + aOff + 16,         gAh+goA+8, 16); \
    CPA(stb + SQA*2 + aOff, gAl+goA, 16); CPA(stb + SQA*2 + aOff + 16, gAl+goA+8, 16); \
    CPA(stb + SQA*4 + bOff,         gBh+goB, 16); CPA(stb + SQA*4 + bOff + 16,         gBh+goB+8, 16); \
    CPA(stb + SQA*4 + SQB*2 + bOff, gBl+goB, 16); CPA(stb + SQA*4 + SQB*2 + bOff + 16, gBl+goB+8, 16); \
    CPA_COMMIT(); }while(0)

    PREF(0, 0);

    for(int ch=0; ch<8; ch++){
        CPA_WAIT0();
        __syncthreads();
        if(ch+1 < 8) PREF(ch+1, (ch+1)&1);
        uint32_t stb = sbase + (uint32_t)(ch&1)*(SQSTG*2);
        uint32_t bAh = stb, bAl = stb + SQA*2;
        uint32_t bBh = stb + SQA*4, bBl = stb + SQA*4 + SQB*2;
#pragma unroll
        for(int ksu=0; ksu<2; ksu++){
            int kb = ksu*16;
            uint32_t bh[4][2], bl[4][2];
#pragma unroll
            for(int ntp=0; ntp<2; ntp++){
                uint32_t off = (uint32_t)(((kb + bKr)*136 + wn*32 + ntp*16 + bNc)*2);
                LDSM4T(bh[2*ntp][0], bh[2*ntp][1], bh[2*ntp+1][0], bh[2*ntp+1][1], bBh + off);
                LDSM4T(bl[2*ntp][0], bl[2*ntp][1], bl[2*ntp+1][0], bl[2*ntp+1][1], bBl + off);
            }
#pragma unroll
            for(int mt=0; mt<4; mt++){
                uint32_t off = (uint32_t)(((wm*64 + mt*16 + (lane&7) + ((lane>>3)&1)*8)*40 + kb + aCol)*2);
                uint32_t ah[4], al[4];
                LDSM4(ah[0],ah[1],ah[2],ah[3], bAh + off);
                LDSM4(al[0],al[1],al[2],al[3], bAl + off);
#pragma unroll
                for(int nt=0; nt<4; nt++){
                    MMA16816(acc[mt][nt], ah, bh[nt]);
                    MMA16816(acc[mt][nt], ah, bl[nt]);
                    MMA16816(acc[mt][nt], al, bh[nt]);
                }
            }
        }
    }
#undef PREF
#pragma unroll
    for(int mt=0; mt<4; mt++){
#pragma unroll
        for(int nt=0; nt<4; nt++){
            int n = bn + wn*32 + nt*8 + (lane&3)*2;
#pragma unroll
            for(int h=0; h<2; h++){
                int m = bm + wm*64 + mt*16 + (lane>>2) + h*8;
                float v0 = scale*acc[mt][nt][h*2], v1 = scale*acc[mt][nt][h*2+1];
                if(AUX){
                    const float* xp = AUX + zo + (size_t)m*ML + n;
                    v0 += beta*xp[0]; v1 += beta*xp[1];
                }
                if(m == n)   v0 += diag;
                if(m == n+1) v1 += diag;
                size_t off = zo + (size_t)m*ML + n;
                float2 o; o.x = v0; o.y = v1;
                *reinterpret_cast<float2*>(C + off) = o;
                bf16 hh[2], ll[2];
                split_bf(v0, hh[0], ll[0]);
                split_bf(v1, hh[1], ll[1]);
                *reinterpret_cast<uint32_t*>(Chp + off) = *reinterpret_cast<uint32_t*>(hh);
                *reinterpret_cast<uint32_t*>(Clp + off) = *reinterpret_cast<uint32_t*>(ll);
            }
        }
    }
}

// ---- batched strided GEMM 64x64 (f32x2) ----
__global__ __launch_bounds__(128,4)
void gemm64_k(const float* __restrict__ A, const float* __restrict__ B, float* __restrict__ C,
              int M, int N, int K, int lda, int ldb, int ldc,
              long long sA, long long sB, long long sC,
              float scale, float diag, const float* __restrict__ AUX, float beta,
              int nsplit, int kc, long long sSplit,
              bf16* __restrict__ Ch, bf16* __restrict__ Cl)
{
    __shared__ __align__(16) float As[16][64];
    __shared__ __align__(16) float Bs[16][64];
    int z = blockIdx.z;
    int sp = z % nsplit, bidx = z / nsplit;
    const float* Ab = A + (size_t)bidx * sA;
    const float* Bb = B + (size_t)bidx * sB;
    size_t cOff = (size_t)bidx * sC + (size_t)sp * sSplit;
    const float* Xb = AUX ? AUX + cOff : nullptr;
    int bm = blockIdx.y*64, bn = blockIdx.x*64;
    int tid = threadIdx.x;
    int tx = tid & 15, ty = tid >> 4;
    ull acc[4][4];
#pragma unroll
    for(int i=0;i<4;i++)
#pragma unroll
        for(int j=0;j<4;j++) acc[i][j]=0ull;

    int am = tid & 63, akq = (tid >> 6) * 8;
    int bkk = tid >> 4, bn4 = (tid & 15) * 4;
    int ks = sp*kc, ke = ks + kc;

    for(int k0=ks;k0<ke;k0+=16){
        {
            const float* p = Ab + (size_t)(bm+am)*lda + k0 + akq;
            float4 v0 = *reinterpret_cast<const float4*>(p);
            float4 v1 = *reinterpret_cast<const float4*>(p+4);
            As[akq+0][am]=v0.x; As[akq+1][am]=v0.y; As[akq+2][am]=v0.z; As[akq+3][am]=v0.w;
            As[akq+4][am]=v1.x; As[akq+5][am]=v1.y; As[akq+6][am]=v1.z; As[akq+7][am]=v1.w;
        }
        {
            float4 b0 = *reinterpret_cast<const float4*>(Bb + (size_t)(k0+bkk)*ldb + bn + bn4);
            float4 b1 = *reinterpret_cast<const float4*>(Bb + (size_t)(k0+bkk+8)*ldb + bn + bn4);
            *reinterpret_cast<float4*>(&Bs[bkk][bn4])   = b0;
            *reinterpret_cast<float4*>(&Bs[bkk+8][bn4]) = b1;
        }
        __syncthreads();
#pragma unroll
        for(int kk=0;kk<16;kk++){
            ulonglong2 a01 = *reinterpret_cast<const ulonglong2*>(&As[kk][ty*8]);
            ulonglong2 a23 = *reinterpret_cast<const ulonglong2*>(&As[kk][ty*8+4]);
            ull av[4] = {a01.x, a01.y, a23.x, a23.y};
            float4 b4 = *reinterpret_cast<const float4*>(&Bs[kk][tx*4]);
            ull bd[4] = {dup2(b4.x),dup2(b4.y),dup2(b4.z),dup2(b4.w)};
#pragma unroll
            for(int i=0;i<4;i++)
#pragma unroll
                for(int j=0;j<4;j++) fma2(acc[i][j], av[i], bd[j]);
        }
        __syncthreads();
    }
#pragma unroll
    for(int i=0;i<4;i++){
#pragma unroll
        for(int rr=0;rr<2;rr++){
            int m = bm + ty*8 + i*2 + rr;
            float v[4];
            float4 xv = make_float4(0,0,0,0);
            if(Xb) xv = *reinterpret_cast<const float4*>(Xb + (size_t)m*ldc + bn + tx*4);
            float xa[4] = {xv.x, xv.y, xv.z, xv.w};
#pragma unroll
            for(int j=0;j<4;j++){
                v[j] = scale * (rr ? hif(acc[i][j]) : lof(acc[i][j]));
                if(Xb) v[j] += beta * xa[j];
                if(m == bn + tx*4 + j) v[j] += diag;
            }
            size_t off = cOff + (size_t)m*ldc + bn + tx*4;
            *reinterpret_cast<float4*>(C + off) = make_float4(v[0],v[1],v[2],v[3]);
            if(Ch){
                bf16 h[4], l[4];
#pragma unroll
                for(int j=0;j<4;j++) split_bf(v[j], h[j], l[j]);
                *reinterpret_cast<uint2*>(Ch + off) = *reinterpret_cast<uint2*>(h);
                *reinterpret_cast<uint2*>(Cl + off) = *reinterpret_cast<uint2*>(l);
            }
        }
    }
}

// ------------------------- small kernels -------------------------
__global__ void zero_pad_k(){ g_LN[blockIdx.x*256 + threadIdx.x] = 0.f; }
__global__ void set_cls_k(const float* __restrict__ c){
    int i = blockIdx.x*256 + threadIdx.x; g_X[i] = c[i];
}
__global__ void cls_copy_k(){
    int i = blockIdx.x*256 + threadIdx.x; g_X2[i] = g_X[i];
}

__global__ void ln_k(const float* __restrict__ X, const float* __restrict__ g,
                     const float* __restrict__ b, float* __restrict__ Y)
{
    __shared__ float sh[8];
    int row = blockIdx.x, t = threadIdx.x;
    const float* x = X + (size_t)row*D;
    float2 v = *reinterpret_cast<const float2*>(x + 2*t);
    float mu = blkSum256(v.x+v.y, sh) * (1.f/(float)D);
    float d0 = v.x-mu, d1 = v.y-mu;
    float var = blkSum256(d0*d0 + d1*d1, sh) * (1.f/(float)D);
    float rs = rsqrtf(var + 1e-5f);
    float2 gg = *reinterpret_cast<const float2*>(g + 2*t);
    float2 bb = *reinterpret_cast<const float2*>(b + 2*t);
    float2 o; o.x = d0*rs*gg.x + bb.x; o.y = d1*rs*gg.y + bb.y;
    *reinterpret_cast<float2*>(Y + (size_t)row*D + 2*t) = o;
}

__global__ void landmarks_k(){
    int j = blockIdx.x, h = blockIdx.y, d = threadIdx.x;
    float sq = 0.f, sk = 0.f;
    const float* base = g_QKV + (size_t)(j*40)*H3 + h*64 + d;
#pragma unroll 8
    for(int t=0;t<40;t++){ sq += base[(size_t)t*H3]; sk += base[(size_t)t*H3 + 512]; }
    float qv = sq * (0.125f/40.f), kv = sk * (1.f/40.f);
    int idx = h*ML*DHD + j*DHD + d;
    g_ql [idx] = qv;
    g_klT[h*DHD*ML + d*ML + j] = kv;
    bf16 hh,ll;
    split_bf(qv,hh,ll); g_qlh[idx]=hh; g_qll[idx]=ll;
    split_bf(kv,hh,ll); g_klh[idx]=hh; g_kll[idx]=ll;
}
__global__ void landmarksK_k(){
    int j = blockIdx.x, h = blockIdx.y, d = threadIdx.x;
    float sk = 0.f;
    const float* base = g_QKV + (size_t)(j*40)*H3 + h*64 + d + 512;
#pragma unroll 8
    for(int t=0;t<40;t++) sk += base[(size_t)t*H3];
    float kv = sk * (1.f/40.f);
    g_klT[h*DHD*ML + d*ML + j] = kv;
    bf16 hh,ll; split_bf(kv,hh,ll);
    int idx = h*ML*DHD + j*DHD + d;
    g_klh[idx]=hh; g_kll[idx]=ll;
}
__global__ void meanrows_k(){
    int j = blockIdx.x, c = threadIdx.x;
    const float* base = g_LN + (size_t)j*40*D + c;
    float s0 = 0.f, s1 = 0.f;
#pragma unroll 8
    for(int t=0;t<40;t++){ s0 += base[(size_t)t*D]; s1 += base[(size_t)t*D + 256]; }
    g_LNm[j*D + c] = s0; g_LNm[j*D + c + 256] = s1;
}

// softmax for a2 with bf16 hi/lo output
__global__ void softmax256_k(float* __restrict__ Xp, long long hs){
    __shared__ float sh[8];
    size_t base = (size_t)blockIdx.y*hs + (size_t)blockIdx.x*ML;
    float* x = Xp + base;
    float v = x[threadIdx.x];
    float mx = blkMax256(v, sh);
    float e = __expf(v-mx);
    float s = blkSum256(e, sh);
    float p = e/s;
    x[threadIdx.x] = p;
    bf16 hh,ll; split_bf(p,hh,ll);
    g_a2h[base + threadIdx.x] = hh;
    g_a2l[base + threadIdx.x] = ll;
}

__global__ void stats256_k(const float* __restrict__ Xp, long long hs, int rows){
    __shared__ float sh[8];
    size_t base = (size_t)blockIdx.y*hs + (size_t)blockIdx.x*ML;
    const float* x = Xp + base;
    float v = x[threadIdx.x];
    float mx = blkMax256(v, sh);
    float e = __expf(v-mx);
    float s = blkSum256(e, sh);
    float p = e/s;
    bf16 hh,ll; split_bf(p,hh,ll);
    g_Ph[base + threadIdx.x] = hh;
    g_Pl[base + threadIdx.x] = ll;
    if(!threadIdx.x){
        int g = blockIdx.y*rows + blockIdx.x;
        g_smx[g] = mx; g_sinv[g] = 1.f/s;
    }
}
__global__ void stats_long_k(const float* __restrict__ Xp, long long hs, int rows){
    __shared__ float sh[8];
    size_t base = (size_t)blockIdx.y*hs + (size_t)blockIdx.x*NPAD;
    const float* x = Xp + base;
    float sc[40]; float mx = -3.0e38f;
#pragma unroll
    for(int c=0;c<40;c++){ sc[c] = x[c*256+threadIdx.x]; mx = fmaxf(mx, sc[c]); }
    mx = blkMax256(mx, sh);
    float s = 0.f;
#pragma unroll
    for(int c=0;c<40;c++){ sc[c] = __expf(sc[c]-mx); s += sc[c]; }
    s = blkSum256(s, sh);
    float inv = 1.f/s;
#pragma unroll
    for(int c=0;c<40;c++){
        float p = sc[c]*inv;
        bf16 hh,ll; split_bf(p,hh,ll);
        g_Ph[base + c*256 + threadIdx.x] = hh;
        g_Pl[base + c*256 + threadIdx.x] = ll;
    }
    if(!threadIdx.x){
        int g = blockIdx.y*rows + blockIdx.x;
        g_smx[g] = mx; g_sinv[g] = 1.f/s;
    }
}

__global__ void rowsum_k(){
    __shared__ float sh[8];
    float v = fabsf(g_a2[(size_t)blockIdx.x*ML + threadIdx.x]);
    v = blkSum256(v, sh);
    if(!threadIdx.x) g_rsum[blockIdx.x] = v;
}
__global__ void colsum_k(){
    __shared__ float sm[8][33];
    int h = blockIdx.x, j0 = blockIdx.y*32;
    int c = threadIdx.x & 31, r0 = threadIdx.x >> 5;
    float acc = 0.f;
    for(int r=r0; r<ML; r+=8) acc += fabsf(g_a2[h*ML*ML + r*ML + j0 + c]);
    sm[r0][c] = acc; __syncthreads();
    if(threadIdx.x < 32){
        float s = 0.f;
#pragma unroll
        for(int q=0;q<8;q++) s += sm[q][threadIdx.x];
        g_csum[h*ML + j0 + threadIdx.x] = s;
    }
}
__global__ void maxred_k(){
    __shared__ float sh[8];
    float mr = 0.f, mc = 0.f;
    for(int i=threadIdx.x; i<NH*ML; i+=256){ mr = fmaxf(mr, g_rsum[i]); mc = fmaxf(mc, g_csum[i]); }
    mr = blkMax256(mr, sh);
    mc = blkMax256(mc, sh);
    if(!threadIdx.x) g_invden = 1.f/(mr*mc);
}

// z0 = a2^T * invden, fp32 + bf16 hi/lo
__global__ void zt_k(){
    __shared__ float t[32][33];
    int h = blockIdx.z, i0 = blockIdx.x*32, j0 = blockIdx.y*32;
    int tx = threadIdx.x & 31, ty = threadIdx.x >> 5;
    float inv = g_invden;
#pragma unroll
    for(int rr=0; rr<32; rr+=8)
        t[ty+rr][tx] = g_a2[h*ML*ML + (i0+ty+rr)*ML + j0+tx];
    __syncthreads();
#pragma unroll
    for(int rr=0; rr<32; rr+=8){
        float v = t[tx][ty+rr]*inv;
        size_t off = (size_t)h*ML*ML + (j0+ty+rr)*ML + i0+tx;
        g_Za[off] = v;
        bf16 hh,ll; split_bf(v,hh,ll);
        g_Zah[off]=hh; g_Zal[off]=ll;
    }
}

__global__ void reduce_tt_k(){
    int i = blockIdx.x*256 + threadIdx.x;
    int b = i >> 14, r = i & 16383;
    float s = 0.f;
#pragma unroll
    for(int t=0;t<NSPL;t++) s += g_ttp[((size_t)b*NSPL + t)*16384 + r];
    g_tt[(size_t)b*16384 + r] = s;
}

__global__ __launch_bounds__(256)
void conv_res_k(const float* __restrict__ w){
    __shared__ float sv[96][64];
    __shared__ float swt[33];
    int s0 = blockIdx.x*64, c0 = blockIdx.y*64, h = blockIdx.y;
    int tid = threadIdx.x;
    for(int idx=tid; idx<96*64; idx+=256){
        int r = idx >> 6, c = idx & 63;
        int sp = s0 - 16 + r;
        sv[r][c] = ((unsigned)sp < (unsigned)NPAD) ? g_QKV[(size_t)sp*H3 + 1024 + c0 + c] : 0.f;
    }
    if(tid < 33) swt[tid] = w[h*33 + tid];
    __syncthreads();
    int c = tid & 63, sg = tid >> 6;
    int sb2 = sg*16;
    float acc[16];
#pragma unroll
    for(int s=0;s<16;s++) acc[s] = 0.f;
    for(int r=0;r<48;r++){
        float v = sv[sb2 + r][c];
#pragma unroll
        for(int s=0;s<16;s++){
            int k = r - s;
            if(k >= 0 && k < 33) acc[s] += swt[k]*v;
        }
    }
#pragma unroll
    for(int s=0;s<16;s++) g_O[(size_t)(s0+sb2+s)*D + c0 + c] = acc[s];
}

__global__ __launch_bounds__(256)
void ppeg_k(const float* __restrict__ w7, const float* __restrict__ b7,
            const float* __restrict__ w5, const float* __restrict__ b5,
            const float* __restrict__ w3, const float* __restrict__ b3)
{
    __shared__ float st[14][14][32];
    __shared__ float sw[83][32];
    __shared__ float sb[32];
    int cg = blockIdx.z*32;
    int ti0 = blockIdx.y*8, tj0 = blockIdx.x*8;
    int tid = threadIdx.x;
    for(int idx=tid; idx<14*14*32; idx+=256){
        int r = idx/(14*32); int rem = idx - r*14*32; int col = rem>>5; int cc = rem&31;
        int gi = ti0-3+r, gj = tj0-3+col;
        float v = 0.f;
        if((unsigned)gi < 100u && (unsigned)gj < 100u)
            v = g_X[(size_t)(1 + gi*100 + gj)*D + cg + cc];
        st[r][col][cc] = v;
    }
    for(int idx=tid; idx<83*32; idx+=256){
        int t = idx>>5, cc = idx&31; int ch = cg+cc; float w;
        if(t<49) w = w7[ch*49 + t];
        else if(t<74) w = w5[ch*25 + t-49];
        else w = w3[ch*9 + t-74];
        sw[t][cc] = w;
    }
    if(tid < 32) sb[tid] = b7[cg+tid] + b5[cg+tid] + b3[cg+tid];
    __syncthreads();
    int c = tid & 31, i = tid >> 5;
    float acc[8];
#pragma unroll
    for(int j=0;j<8;j++) acc[j] = st[3+i][3+j][c] + sb[c];
#pragma unroll
    for(int di=-3; di<=3; di++){
        float rv[14];
#pragma unroll
        for(int q=0;q<14;q++) rv[q] = st[3+i+di][q][c];
#pragma unroll
        for(int dj=0;dj<7;dj++){
            float w = sw[(di+3)*7+dj][c];
#pragma unroll
            for(int j=0;j<8;j++) acc[j] += w*rv[j+dj];
        }
        if(di>=-2 && di<=2){
#pragma unroll
            for(int dj=0;dj<5;dj++){
                float w = sw[49+(di+2)*5+dj][c];
#pragma unroll
                for(int j=0;j<8;j++) acc[j] += w*rv[j+dj+1];
            }
        }
        if(di>=-1 && di<=1){
#pragma unroll
            for(int dj=0;dj<3;dj++){
                float w = sw[74+(di+1)*3+dj][c];
#pragma unroll
                for(int j=0;j<8;j++) acc[j] += w*rv[j+dj+2];
            }
        }
    }
    int gi = ti0+i;
    if(gi < 100){
#pragma unroll
        for(int j=0;j<8;j++){
            int gj = tj0+j;
            if(gj < 100) g_X2[(size_t)(1 + gi*100 + gj)*D + cg + c] = acc[j];
        }
    }
}

__global__ void l2row_k(const float* __restrict__ rw, const float* __restrict__ qw){
    __shared__ float q[64];
    __shared__ float p[256];
    __shared__ float sh[8];
    int h = blockIdx.x, j = threadIdx.x;
    if(j < 64){
        const float* x = g_LN + (size_t)PADN*D;
        const float* w = qw + h*64 + j;
        float a = 0.f;
        for(int c=0;c<512;c++) a += x[c]*w[(size_t)c*H3];
        q[j] = a;
    }
    __syncthreads();
    float s = 0.f;
#pragma unroll
    for(int d=0; d<64; d++) s += q[d]*g_klT[h*DHD*ML + d*ML + j];
    s *= 0.125f;
    float mx = blkMax256(s, sh);
    float e = __expf(s - mx);
    float sum = blkSum256(e, sh);
    p[j] = e/sum;
    __syncthreads();
    if(j < 64){
        float acc = 0.f;
        for(int t=0;t<256;t++) acc += p[t]*g_uu[h*ML*DHD + t*64 + j];
#pragma unroll
        for(int t=0;t<33;t++)
            acc += rw[h*33+t] * g_QKV[(size_t)(PADN-16+t)*H3 + 1024 + h*64 + j];
        g_orow[h*64 + j] = acc;
    }
}

__global__ void final_head_k(const float* __restrict__ ow, const float* __restrict__ ob,
                             const float* __restrict__ ng, const float* __restrict__ nb,
                             const float* __restrict__ fw, const float* __restrict__ fb,
                             float* __restrict__ out)
{
    __shared__ float o[512];
    __shared__ float f[512];
    __shared__ float sh[8];
    int t = threadIdx.x;
    o[t] = g_orow[t]; o[t+256] = g_orow[t+256];
    __syncthreads();
#pragma unroll
    for(int half=0; half<2; half++){
        int n = t + half*256;
        float v = ob[n] + g_LN[(size_t)PADN*D + n];
        for(int c=0;c<512;c++) v += o[c]*ow[(size_t)c*D + n];
        f[n] = v;
    }
    __syncthreads();
    float v0 = f[t], v1 = f[t+256];
    float mu = blkSum256(v0+v1, sh)*(1.f/512.f);
    float d0 = v0-mu, d1 = v1-mu;
    float var = blkSum256(d0*d0+d1*d1, sh)*(1.f/512.f);
    float rs = rsqrtf(var + 1e-5f);
    float l0 = d0*rs*ng[t]     + nb[t];
    float l1 = d1*rs*ng[t+256] + nb[t+256];
    float s0 = l0*fw[t*2]   + l1*fw[(t+256)*2];
    float s1 = l0*fw[t*2+1] + l1*fw[(t+256)*2+1];
    s0 = blkSum256(s0, sh);
    s1 = blkSum256(s1, sh);
    if(!t){ out[0] = s0 + fb[0]; out[1] = s1 + fb[1]; }
}

// ------------------------- host -------------------------
#define SYMADDR(T, p, s) do{ void* _t; cudaGetSymbolAddress(&_t, s); p = (T*)_t; }while(0)

extern "C" void kernel_launch(void* const* d_in, const int* in_sizes, int n_in,
                              void* d_out, int out_size)
{
    bool sig = (in_sizes[10] == 25088);
    const float* h_in = (const float*)d_in[0];
    const float* fc1w = (const float*)d_in[1];
    const float* fc1b = (const float*)d_in[2];
    const float* cls  = (const float*)d_in[3];
    const float* g1 = (const float*)d_in[4];
    const float* b1 = (const float*)d_in[5];
    const float* qkv1 = (const float*)d_in[6];
    const float* ow1 = (const float*)d_in[7];
    const float* ob1 = (const float*)d_in[8];
    const float* rw1 = (const float*)d_in[9];
    const float *w7,*b7,*w5,*b5,*w3,*b3,*g2,*b2,*qkv2,*ow2,*ob2,*rw2,*ng,*nb,*f2w,*f2b;
    if(sig){
        w7=(const float*)d_in[10]; b7=(const float*)d_in[11];
        w5=(const float*)d_in[12]; b5=(const float*)d_in[13];
        w3=(const float*)d_in[14]; b3=(const float*)d_in[15];
        g2=(const float*)d_in[16]; b2=(const float*)d_in[17];
        qkv2=(const float*)d_in[18]; ow2=(const float*)d_in[19];
        ob2=(const float*)d_in[20]; rw2=(const float*)d_in[21];
    } else {
        g2=(const float*)d_in[10]; b2=(const float*)d_in[11];
        qkv2=(const float*)d_in[12]; ow2=(const float*)d_in[13];
        ob2=(const float*)d_in[14]; rw2=(const float*)d_in[15];
        w7=(const float*)d_in[16]; b7=(const float*)d_in[17];
        w5=(const float*)d_in[18]; b5=(const float*)d_in[19];
        w3=(const float*)d_in[20]; b3=(const float*)d_in[21];
    }
    ng=(const float*)d_in[22]; nb=(const float*)d_in[23];
    f2w=(const float*)d_in[24]; f2b=(const float*)d_in[25];

    float *X,*X2,*LN,*LNm,*QKV,*klT,*ql,*a1,*a3,*a2,*Za,*Zb,*XZ,*M2p,*M4p,*ttp,*tt,*uu,*Ob,*smx,*sinv;
    bf16 *Ah,*Al,*Wth,*Wtl,*KVh,*KVl,*qlh,*qll,*klh,*kll,*Ph,*Pl,*uuh,*uul;
    bf16 *a2h,*a2l,*Zah,*Zal,*Zbh,*Zbl,*XZh,*XZl,*M2h,*M2l,*M4h,*M4l;
    SYMADDR(float,X,g_X); SYMADDR(float,X2,g_X2); SYMADDR(float,LN,g_LN); SYMADDR(float,LNm,g_LNm);
    SYMADDR(float,QKV,g_QKV); SYMADDR(float,klT,g_klT); SYMADDR(float,ql,g_ql);
    SYMADDR(float,a1,g_a1); SYMADDR(float,a3,g_a3); SYMADDR(float,a2,g_a2);
    SYMADDR(float,Za,g_Za); SYMADDR(float,Zb,g_Zb); SYMADDR(float,XZ,g_XZ);
    SYMADDR(float,M2p,g_M2); SYMADDR(float,M4p,g_M4); SYMADDR(float,ttp,g_ttp);
    SYMADDR(float,tt,g_tt); SYMADDR(float,uu,g_uu); SYMADDR(float,Ob,g_O);
    SYMADDR(float,smx,g_smx); SYMADDR(float,sinv,g_sinv);
    SYMADDR(bf16,Ah,g_Ah); SYMADDR(bf16,Al,g_Al); SYMADDR(bf16,Wth,g_Wth); SYMADDR(bf16,Wtl,g_Wtl);
    SYMADDR(bf16,KVh,g_KVh); SYMADDR(bf16,KVl,g_KVl);
    SYMADDR(bf16,qlh,g_qlh); SYMADDR(bf16,qll,g_qll);
    SYMADDR(bf16,klh,g_klh); SYMADDR(bf16,kll,g_kll);
    SYMADDR(bf16,Ph,g_Ph); SYMADDR(bf16,Pl,g_Pl);
    SYMADDR(bf16,uuh,g_uuh); SYMADDR(bf16,uul,g_uul);
    SYMADDR(bf16,a2h,g_a2h); SYMADDR(bf16,a2l,g_a2l);
    SYMADDR(bf16,Zah,g_Zah); SYMADDR(bf16,Zal,g_Zal);
    SYMADDR(bf16,Zbh,g_Zbh); SYMADDR(bf16,Zbl,g_Zbl);
    SYMADDR(bf16,XZh,g_XZh); SYMADDR(bf16,XZl,g_XZl);
    SYMADDR(bf16,M2h,g_M2h); SYMADDR(bf16,M2l,g_M2l);
    SYMADDR(bf16,M4h,g_M4h); SYMADDR(bf16,M4l,g_M4l);

    static cudaStream_t s1 = nullptr, s2 = nullptr;
    static cudaEvent_t ev[8];
    if(!s1){
        cudaStreamCreateWithFlags(&s1, cudaStreamNonBlocking);
        cudaStreamCreateWithFlags(&s2, cudaStreamNonBlocking);
        for(int i=0;i<8;i++) cudaEventCreateWithFlags(&ev[i], cudaEventDisableTiming);
        cudaFuncSetAttribute(gemm_mma_k, cudaFuncAttributeMaxDynamicSharedMemorySize, SM_MMA);
        cudaFuncSetAttribute(gemm_mma_b_k, cudaFuncAttributeMaxDynamicSharedMemorySize, SM_MMA);
        cudaFuncSetAttribute(gemm_mma_n64t_k, cudaFuncAttributeMaxDynamicSharedMemorySize, SM_N64);
        cudaFuncSetAttribute(gemm_mma_sq_k, cudaFuncAttributeMaxDynamicSharedMemorySize, SM_SQ);
    }

    zero_pad_k<<<PADN*D/256, 256>>>();
    cvt_rows_k<<<10000*1024/1024, 256>>>(h_in, Ah, Al);
    cvt_T_k<<<dim3(32,16),256>>>(fc1w, Wth, Wtl, 1024, 512);
    gemm_mma_k<<<dim3(4,79),256,SM_MMA>>>(Ah, Al, Wth, Wtl, fc1b, nullptr, X+D,
                                          10000, 512, 1024, D, 1, 0, 1, nullptr, nullptr);
    set_cls_k<<<2,256>>>(cls);

    long long sM = (long long)ML*ML;
    for(int layer=0; layer<2; layer++){
        const float* xin = layer ? X2 : X;
        const float* gg = layer ? g2 : g1;
        const float* bb = layer ? b2 : b1;
        const float* qw = layer ? qkv2 : qkv1;
        cudaEvent_t evF = ev[layer*4+0], evA = ev[layer*4+1], evB = ev[layer*4+2];

        ln_k<<<NSEQ,256>>>(xin, gg, bb, LN + (size_t)PADN*D);
        cvt_rows_k<<<NPAD*512/1024, 256>>>(LN, Ah, Al);

        const float* Aq; int ldaQ; long long sAQ;
        const bf16 *AqH, *AqL; int ldaQb; long long sAQb;
        if(layer == 0){
            cvt_T_k<<<dim3(16,48),256>>>(qw, Wth, Wtl, 512, 1536);
            gemm_mma_k<<<dim3(12,80),256,SM_MMA>>>(Ah, Al, Wth, Wtl, nullptr, nullptr, QKV,
                                                   NPAD, 1536, 512, H3, 0, 0, 0, KVh, KVl);
            landmarks_k<<<dim3(ML,NH),64>>>();
            Aq = ql; ldaQ = DHD; sAQ = (long long)ML*DHD;
            AqH = qlh; AqL = qll; ldaQb = DHD; sAQb = (long long)ML*DHD;
        } else {
            cvt_T_k<<<dim3(16,32),256>>>(qw+512, Wth, Wtl, 512, 1536);
            gemm_mma_k<<<dim3(8,80),256,SM_MMA>>>(Ah, Al, Wth, Wtl, nullptr, nullptr, QKV+512,
                                                  NPAD, 1024, 512, H3, 0, 0, 0, KVh+512, KVl+512);
            meanrows_k<<<ML,256>>>();
            gemm64_k<<<dim3(8,4,1),128>>>(LNm, qw, ql, ML, 512, 512, 512, H3, 512,
                        0,0,0, 0.125f/40.f, 0.f, nullptr, 0.f, 1, 512, 0, qlh, qll);
            landmarksK_k<<<dim3(ML,NH),64>>>();
            Aq = ql; ldaQ = 512; sAQ = 64;
            AqH = qlh; AqL = qll; ldaQb = 512; sAQb = 64;
        }

        // a2 = softmax(ql @ kl^T), emits bf16 hi/lo
        gemm64_k<<<dim3(4,4,NH),128>>>(Aq, klT, a2, ML,ML,DHD, ldaQ,ML,ML,
                    sAQ,(long long)DHD*ML,sM, 1.f,0.f, nullptr,0.f, 1,DHD,0, nullptr,nullptr);
        softmax256_k<<<dim3(ML,NH),256>>>(a2, sM);

        // ---- fork: pinv chain (HMMA) on s1, conv on s2 (layer 0) ----
        cudaEventRecord(evF, 0);
        cudaStreamWaitEvent(s1, evF, 0);
        rowsum_k<<<NH*ML,256,0,s1>>>();
        colsum_k<<<dim3(NH,8),256,0,s1>>>();
        maxred_k<<<1,256,0,s1>>>();
        zt_k<<<dim3(8,8,NH),256,0,s1>>>();
        float* za = Za; float* zb = Zb;
        bf16 *zah=Zah, *zal=Zal, *zbh=Zbh, *zbl=Zbl;
        for(int it=0; it<6; it++){
            gemm_mma_sq_k<<<dim3(2,2,NH),256,SM_SQ,s1>>>(a2h,a2l, zah,zal, XZ, XZh,XZl,
                        1.f, 0.f, nullptr, 0.f);
            gemm_mma_sq_k<<<dim3(2,2,NH),256,SM_SQ,s1>>>(XZh,XZl, XZh,XZl, M2p, M2h,M2l,
                        -1.f, -15.f, XZ, 7.f);
            gemm_mma_sq_k<<<dim3(2,2,NH),256,SM_SQ,s1>>>(XZh,XZl, M2h,M2l, M4p, M4h,M4l,
                        1.f, 13.f, nullptr, 0.f);
            gemm_mma_sq_k<<<dim3(2,2,NH),256,SM_SQ,s1>>>(zah,zal, M4h,M4l, zb, zbh,zbl,
                        0.25f, 0.f, nullptr, 0.f);
            float* t1 = za; za = zb; zb = t1;
            bf16* t2 = zah; zah = zbh; zbh = t2;
            t2 = zal; zal = zbl; zbl = t2;
        }
        cudaEventRecord(evA, s1);

        if(layer == 0){
            cudaStreamWaitEvent(s2, evF, 0);
            conv_res_k<<<dim3(NPAD/64, NH),256,0,s2>>>(rw1);
            cudaEventRecord(evB, s2);
        }

        // ---- main stream: a3 (MMA) -> stats+P3 -> tt (MMA, split-K) ----
        gemm_mma_b_k<<<dim3(NPAD/128, ML/128, NH),256,SM_MMA>>>(AqH, AqL, KVh+512, KVl+512,
                    a3, NPAD, DHD, ldaQb, H3, NPAD, sAQb, 64LL, (long long)ML*NPAD, 1.f);
        stats_long_k<<<dim3(ML,NH),256>>>(a3, (long long)ML*NPAD, ML);
        gemm_mma_n64t_k<<<dim3(NSPL, ML/128, NH),256,SM_N64>>>(Ph, Pl, KVh+1024, KVl+1024,
                    ttp, NPAD, H3, DHD, (long long)ML*NPAD, 64LL, (long long)NSPL*ML*DHD,
                    nullptr, 0.f, KCH, (long long)ML*DHD);
        reduce_tt_k<<<NH*ML*DHD/256,256>>>();
        if(layer == 0){
            gemm_mma_b_k<<<dim3(ML/128, NPAD/128, NH),256,SM_MMA>>>(KVh, KVl, klh, kll,
                    a1, ML, DHD, H3, DHD, ML, 64LL, (long long)ML*DHD, (long long)NPAD*ML, 0.125f);
            stats256_k<<<dim3(NPAD,NH),256>>>(a1, (long long)NPAD*ML, NPAD);
        }

        // ---- join pinv, compute uu (+bf16 split) ----
        cudaStreamWaitEvent(0, evA, 0);
        gemm64_k<<<dim3(1,4,NH),128>>>(za, tt, uu, ML,DHD,ML, ML,DHD,DHD,
                    sM,(long long)ML*DHD,(long long)ML*DHD, 1.f,0.f, nullptr,0.f, 1,ML,0,
                    uuh, uul);

        if(layer == 0){
            cudaStreamWaitEvent(0, evB, 0);
            gemm_mma_n64t_k<<<dim3(1, NPAD/128, NH),256,SM_N64>>>(Ph, Pl, uuh, uul,
                    Ob, ML, DHD, D, (long long)NPAD*ML, (long long)ML*DHD, 64LL,
                    Ob, 1.f, ML, 0);
            cvt_rows_k<<<NPAD*512/1024, 256>>>(Ob, Ah, Al);
            cvt_T_k<<<dim3(16,16),256>>>(ow1, Wth, Wtl, 512, 512);
            gemm_mma_k<<<dim3(4,79),256,SM_MMA>>>(Ah + (size_t)PADN*D, Al + (size_t)PADN*D,
                                                  Wth, Wtl, ob1, LN + (size_t)PADN*D, X,
                                                  NSEQ, 512, 512, D, 1, 1, 0, nullptr, nullptr);
            ppeg_k<<<dim3(13,13,16),256>>>(w7,b7,w5,b5,w3,b3);
            cls_copy_k<<<2,256>>>();
        } else {
            l2row_k<<<NH,256>>>(rw2, qw);
            final_head_k<<<1,256>>>(ow2, ob2, ng, nb, f2w, f2b, (float*)d_out);
        }
    }
}

// round 14
// speedup vs baseline: 1.0028x; 1.0028x over previous
#include <cuda_runtime.h>
#include <cuda_bf16.h>
#include <math.h>
#include <stdint.h>

#define D    512
#define H3   1536
#define NH   8
#define DHD  64
#define NSEQ 10001
#define NPAD 10240
#define PADN 239
#define ML   256
#define NSPL 8
#define KCH  (NPAD/NSPL)

typedef __nv_bfloat16 bf16;

// ------------------------- scratch (device globals) -------------------------
__device__ float g_X  [NSEQ*D];
__device__ float g_X2 [NSEQ*D];
__device__ float g_LN [NPAD*D];
__device__ float g_LNm[ML*D];
__device__ float g_QKV[(size_t)NPAD*H3];
__device__ float g_klT[NH*DHD*ML];
__device__ float g_ql [NH*ML*DHD];
__device__ float g_a1 [(size_t)NH*NPAD*ML];
__device__ float g_a3 [(size_t)NH*ML*NPAD];
__device__ float g_a2 [NH*ML*ML];
__device__ float g_Za [NH*ML*ML];
__device__ float g_Zb [NH*ML*ML];
__device__ float g_XZ [NH*ML*ML];
__device__ float g_M2 [NH*ML*ML];
__device__ float g_M4 [NH*ML*ML];
__device__ float g_ttp[(size_t)NH*NSPL*ML*DHD];
__device__ float g_tt [NH*ML*DHD];
__device__ float g_uu [NH*ML*DHD];
__device__ float g_O  [(size_t)NPAD*D];
__device__ float g_smx [NH*NPAD];
__device__ float g_sinv[NH*NPAD];
__device__ float g_orow[D];
__device__ float g_rsum[NH*ML];
__device__ float g_csum[NH*ML];
__device__ float g_invden;
// bf16 hi/lo operand buffers
__device__ bf16 g_Ah[(size_t)NPAD*1024];
__device__ bf16 g_Al[(size_t)NPAD*1024];
__device__ bf16 g_Wth[1536*512];
__device__ bf16 g_Wtl[1536*512];
__device__ bf16 g_KVh[(size_t)NPAD*H3];
__device__ bf16 g_KVl[(size_t)NPAD*H3];
__device__ bf16 g_qlh[NH*ML*DHD];
__device__ bf16 g_qll[NH*ML*DHD];
__device__ bf16 g_klh[NH*ML*DHD];
__device__ bf16 g_kll[NH*ML*DHD];
__device__ bf16 g_Ph [(size_t)NH*NPAD*ML];
__device__ bf16 g_Pl [(size_t)NH*NPAD*ML];
__device__ bf16 g_uuh[NH*ML*DHD];
__device__ bf16 g_uul[NH*ML*DHD];

// ------------------------- f32x2 helpers -------------------------
typedef unsigned long long ull;
__device__ __forceinline__ void fma2(ull& d, ull a, ull b){
    asm("fma.rn.f32x2 %0, %1, %2, %0;" : "+l"(d) : "l"(a), "l"(b));
}
__device__ __forceinline__ ull dup2(float b){
    ull r; asm("mov.b64 %0, {%1, %1};" : "=l"(r) : "f"(b)); return r;
}
__device__ __forceinline__ float lof(ull v){ return __uint_as_float((unsigned)v); }
__device__ __forceinline__ float hif(ull v){ return __uint_as_float((unsigned)(v>>32)); }

__device__ __forceinline__ uint32_t s2u(const void* p){
    uint32_t a;
    asm("{ .reg .u64 t; cvta.to.shared.u64 t, %1; cvt.u32.u64 %0, t; }" : "=r"(a) : "l"(p));
    return a;
}
#define LDSM4(r0,r1,r2,r3,addr) \
    asm volatile("ldmatrix.sync.aligned.m8n8.x4.shared.b16 {%0,%1,%2,%3}, [%4];" \
        : "=r"(r0),"=r"(r1),"=r"(r2),"=r"(r3) : "r"(addr))
#define LDSM4T(r0,r1,r2,r3,addr) \
    asm volatile("ldmatrix.sync.aligned.m8n8.x4.trans.shared.b16 {%0,%1,%2,%3}, [%4];" \
        : "=r"(r0),"=r"(r1),"=r"(r2),"=r"(r3) : "r"(addr))
#define MMA16816(d, a, b) \
    asm volatile("mma.sync.aligned.m16n8k16.row.col.f32.bf16.bf16.f32 " \
        "{%0,%1,%2,%3},{%4,%5,%6,%7},{%8,%9},{%0,%1,%2,%3};" \
        : "+f"((d)[0]),"+f"((d)[1]),"+f"((d)[2]),"+f"((d)[3]) \
        : "r"((a)[0]),"r"((a)[1]),"r"((a)[2]),"r"((a)[3]), "r"((b)[0]),"r"((b)[1]))
#define CPA(dst, src, sz) \
    asm volatile("cp.async.ca.shared.global [%0], [%1], 16, %2;" \
        :: "r"(dst), "l"(src), "r"(sz) : "memory")
#define CPA_COMMIT() asm volatile("cp.async.commit_group;" ::: "memory")
#define CPA_WAIT0()  asm volatile("cp.async.wait_group 0;" ::: "memory")

// ------------------------- block reductions (256 thr) -------------------------
__device__ __forceinline__ float blkSum256(float v, float* sh){
#pragma unroll
    for(int o=16;o;o>>=1) v += __shfl_xor_sync(0xffffffffu, v, o);
    __syncthreads();
    if((threadIdx.x&31)==0) sh[threadIdx.x>>5]=v;
    __syncthreads();
    float r = sh[0];
#pragma unroll
    for(int i=1;i<8;i++) r += sh[i];
    return r;
}
__device__ __forceinline__ float blkMax256(float v, float* sh){
#pragma unroll
    for(int o=16;o;o>>=1) v = fmaxf(v, __shfl_xor_sync(0xffffffffu, v, o));
    __syncthreads();
    if((threadIdx.x&31)==0) sh[threadIdx.x>>5]=v;
    __syncthreads();
    float r = sh[0];
#pragma unroll
    for(int i=1;i<8;i++) r = fmaxf(r, sh[i]);
    return r;
}

// ------------------------- bf16 hi/lo converters -------------------------
__device__ __forceinline__ void split_bf(float a, bf16& h, bf16& l){
    h = __float2bfloat16_rn(a);
    l = __float2bfloat16_rn(a - __bfloat162float(h));
}
__global__ void cvt_rows_k(const float* __restrict__ s, bf16* __restrict__ dh,
                           bf16* __restrict__ dl){
    size_t i = ((size_t)blockIdx.x*256 + threadIdx.x)*4;
    float4 v = *reinterpret_cast<const float4*>(s+i);
    bf16 h[4], l[4];
    split_bf(v.x,h[0],l[0]); split_bf(v.y,h[1],l[1]);
    split_bf(v.z,h[2],l[2]); split_bf(v.w,h[3],l[3]);
    *reinterpret_cast<uint2*>(dh+i) = *reinterpret_cast<uint2*>(h);
    *reinterpret_cast<uint2*>(dl+i) = *reinterpret_cast<uint2*>(l);
}
__global__ void cvt_T_k(const float* __restrict__ W, bf16* __restrict__ dh,
                        bf16* __restrict__ dl, int Kd, int Nd){
    __shared__ float sm[32][33];
    int k0 = blockIdx.x*32, n0 = blockIdx.y*32;
    int c = threadIdx.x & 31, r = threadIdx.x >> 5;
#pragma unroll
    for(int p=0;p<4;p++)
        sm[p*8+r][c] = W[(size_t)(k0+p*8+r)*Nd + n0 + c];
    __syncthreads();
#pragma unroll
    for(int p=0;p<4;p++){
        int nn = p*8 + r;
        float v = sm[c][nn];
        bf16 h,l; split_bf(v,h,l);
        dh[(size_t)(n0+nn)*Kd + k0 + c] = h;
        dl[(size_t)(n0+nn)*Kd + k0 + c] = l;
    }
}

// ---------- bf16x3 tensor-core GEMM, 2-stage cp.async pipeline (2 CTA/SM) ----------
#define MS  (128*40)
#define SM_MMA (2*4*MS*2)
__global__ __launch_bounds__(256,2)
void gemm_mma_k(const bf16* __restrict__ Ahp, const bf16* __restrict__ Alp,
                const bf16* __restrict__ Bhp, const bf16* __restrict__ Blp,
                const float* __restrict__ bias, const float* __restrict__ R,
                float* __restrict__ C, int M, int N, int K, int ldc,
                int DOBIAS, int DORES, int DORELU,
                bf16* __restrict__ Chp, bf16* __restrict__ Clp)
{
    extern __shared__ bf16 smp[];
    int tid = threadIdx.x, lane = tid & 31, wid = tid >> 5;
    int wm = wid >> 2, wn = wid & 3;
    int bm = blockIdx.y * 128, bn = blockIdx.x * 128;
    uint32_t sbase = s2u(smp);
    float acc[4][4][4];
#pragma unroll
    for(int i=0;i<4;i++)
#pragma unroll
        for(int j=0;j<4;j++)
#pragma unroll
            for(int q=0;q<4;q++) acc[i][j][q]=0.f;

    int lr = tid >> 1, ls = (tid & 1) * 16;
    int aok = (bm + lr < M) ? 16 : 0;
    const bf16* gAh = Ahp + (size_t)(bm+lr)*K + ls;
    const bf16* gAl = Alp + (size_t)(bm+lr)*K + ls;
    const bf16* gBh = Bhp + (size_t)(bn+lr)*K + ls;
    const bf16* gBl = Blp + (size_t)(bn+lr)*K + ls;
    uint32_t dOff = (uint32_t)((lr*40 + ls)*2);

    int aRow = wm*64 + (lane&7) + ((lane>>3)&1)*8;
    int aCol = (lane>>4)*8;
    int bRow = wn*32 + (lane&7) + (lane>>4)*8;
    int bCol = ((lane>>3)&1)*8;

    int nch = K >> 5;
#define PREF(ch, st) do{ \
    uint32_t db = sbase + (uint32_t)(st)*(4*MS*2) + dOff; \
    size_t go = (size_t)(ch)*32; \
    CPA(db,          gAh+go, aok); CPA(db+16,          gAh+go+8, aok); \
    CPA(db+MS*2,     gAl+go, aok); CPA(db+MS*2+16,     gAl+go+8, aok); \
    CPA(db+MS*4,     gBh+go, 16);  CPA(db+MS*4+16,     gBh+go+8, 16); \
    CPA(db+MS*6,     gBl+go, 16);  CPA(db+MS*6+16,     gBl+go+8, 16); \
    CPA_COMMIT(); }while(0)

    PREF(0, 0);

    for(int ch=0; ch<nch; ch++){
        CPA_WAIT0();
        __syncthreads();
        if(ch+1 < nch) PREF(ch+1, (ch+1)&1);
        uint32_t stb = sbase + (uint32_t)(ch&1)*(4*MS*2);
        uint32_t bAh = stb, bAl = stb + MS*2, bBh = stb + MS*4, bBl = stb + MS*6;
#pragma unroll
        for(int ks=0; ks<2; ks++){
            int kc = ks*16;
            uint32_t bh[4][2], bl[4][2];
#pragma unroll
            for(int ntp=0; ntp<2; ntp++){
                uint32_t off = (uint32_t)(((bRow + ntp*16)*40 + kc + bCol)*2);
                LDSM4(bh[2*ntp][0], bh[2*ntp][1], bh[2*ntp+1][0], bh[2*ntp+1][1], bBh + off);
                LDSM4(bl[2*ntp][0], bl[2*ntp][1], bl[2*ntp+1][0], bl[2*ntp+1][1], bBl + off);
            }
#pragma unroll
            for(int mt=0; mt<4; mt++){
                uint32_t off = (uint32_t)(((aRow + mt*16)*40 + kc + aCol)*2);
                uint32_t ah[4], al[4];
                LDSM4(ah[0],ah[1],ah[2],ah[3], bAh + off);
                LDSM4(al[0],al[1],al[2],al[3], bAl + off);
#pragma unroll
                for(int nt=0; nt<4; nt++){
                    MMA16816(acc[mt][nt], ah, bh[nt]);
                    MMA16816(acc[mt][nt], ah, bl[nt]);
                    MMA16816(acc[mt][nt], al, bh[nt]);
                }
            }
        }
    }
#undef PREF
#pragma unroll
    for(int mt=0; mt<4; mt++){
#pragma unroll
        for(int nt=0; nt<4; nt++){
            int n = bn + wn*32 + nt*8 + (lane&3)*2;
#pragma unroll
            for(int h=0; h<2; h++){
                int m = bm + wm*64 + mt*16 + (lane>>2) + h*8;
                if(m < M){
                    float v0 = acc[mt][nt][h*2], v1 = acc[mt][nt][h*2+1];
                    if(DOBIAS){ v0 += bias[n]; v1 += bias[n+1]; }
                    if(DORES){
                        const float* rp = R + (size_t)m*ldc + n;
                        v0 += rp[0]; v1 += rp[1];
                    }
                    if(DORELU){ v0 = fmaxf(v0,0.f); v1 = fmaxf(v1,0.f); }
                    float2 o; o.x = v0; o.y = v1;
                    *reinterpret_cast<float2*>(C + (size_t)m*ldc + n) = o;
                    if(Chp){
                        bf16 hh[2], ll[2];
                        split_bf(v0, hh[0], ll[0]);
                        split_bf(v1, hh[1], ll[1]);
                        *reinterpret_cast<uint32_t*>(Chp + (size_t)m*ldc + n) = *reinterpret_cast<uint32_t*>(hh);
                        *reinterpret_cast<uint32_t*>(Clp + (size_t)m*ldc + n) = *reinterpret_cast<uint32_t*>(ll);
                    }
                }
            }
        }
    }
}

// ---------- batched/strided bf16x3 MMA GEMM: C = scale*(A@B), B [N][K] rows ----------
__global__ __launch_bounds__(256,2)
void gemm_mma_b_k(const bf16* __restrict__ Ahp, const bf16* __restrict__ Alp,
                  const bf16* __restrict__ Bhp, const bf16* __restrict__ Blp,
                  float* __restrict__ C, int N, int K,
                  int lda, int ldb, int ldc,
                  long long sA, long long sB, long long sC, float scale)
{
    extern __shared__ bf16 smp[];
    int tid = threadIdx.x, lane = tid & 31, wid = tid >> 5;
    int wm = wid >> 2, wn = wid & 3;
    int bm = blockIdx.y * 128, bn = blockIdx.x * 128;
    int z = blockIdx.z;
    uint32_t sbase = s2u(smp);
    float acc[4][4][4];
#pragma unroll
    for(int i=0;i<4;i++)
#pragma unroll
        for(int j=0;j<4;j++)
#pragma unroll
            for(int q=0;q<4;q++) acc[i][j][q]=0.f;

    int lr = tid >> 1, ls = (tid & 1) * 16;
    const bf16* gAh = Ahp + (size_t)z*sA + (size_t)(bm+lr)*lda + ls;
    const bf16* gAl = Alp + (size_t)z*sA + (size_t)(bm+lr)*lda + ls;
    const bf16* gBh = Bhp + (size_t)z*sB + (size_t)(bn+lr)*ldb + ls;
    const bf16* gBl = Blp + (size_t)z*sB + (size_t)(bn+lr)*ldb + ls;
    uint32_t dOff = (uint32_t)((lr*40 + ls)*2);

    int aRow = wm*64 + (lane&7) + ((lane>>3)&1)*8;
    int aCol = (lane>>4)*8;
    int bRow = wn*32 + (lane&7) + (lane>>4)*8;
    int bCol = ((lane>>3)&1)*8;

    int nch = K >> 5;
#define PREF(ch, st) do{ \
    uint32_t db = sbase + (uint32_t)(st)*(4*MS*2) + dOff; \
    size_t go = (size_t)(ch)*32; \
    CPA(db,          gAh+go, 16); CPA(db+16,          gAh+go+8, 16); \
    CPA(db+MS*2,     gAl+go, 16); CPA(db+MS*2+16,     gAl+go+8, 16); \
    CPA(db+MS*4,     gBh+go, 16); CPA(db+MS*4+16,     gBh+go+8, 16); \
    CPA(db+MS*6,     gBl+go, 16); CPA(db+MS*6+16,     gBl+go+8, 16); \
    CPA_COMMIT(); }while(0)

    PREF(0, 0);

    for(int ch=0; ch<nch; ch++){
        CPA_WAIT0();
        __syncthreads();
        if(ch+1 < nch) PREF(ch+1, (ch+1)&1);
        uint32_t stb = sbase + (uint32_t)(ch&1)*(4*MS*2);
        uint32_t bAh = stb, bAl = stb + MS*2, bBh = stb + MS*4, bBl = stb + MS*6;
#pragma unroll
        for(int ks=0; ks<2; ks++){
            int kc = ks*16;
            uint32_t bh[4][2], bl[4][2];
#pragma unroll
            for(int ntp=0; ntp<2; ntp++){
                uint32_t off = (uint32_t)(((bRow + ntp*16)*40 + kc + bCol)*2);
                LDSM4(bh[2*ntp][0], bh[2*ntp][1], bh[2*ntp+1][0], bh[2*ntp+1][1], bBh + off);
                LDSM4(bl[2*ntp][0], bl[2*ntp][1], bl[2*ntp+1][0], bl[2*ntp+1][1], bBl + off);
            }
#pragma unroll
            for(int mt=0; mt<4; mt++){
                uint32_t off = (uint32_t)(((aRow + mt*16)*40 + kc + aCol)*2);
                uint32_t ah[4], al[4];
                LDSM4(ah[0],ah[1],ah[2],ah[3], bAh + off);
                LDSM4(al[0],al[1],al[2],al[3], bAl + off);
#pragma unroll
                for(int nt=0; nt<4; nt++){
                    MMA16816(acc[mt][nt], ah, bh[nt]);
                    MMA16816(acc[mt][nt], ah, bl[nt]);
                    MMA16816(acc[mt][nt], al, bh[nt]);
                }
            }
        }
    }
#undef PREF
    float* Cb = C + (size_t)z*sC;
#pragma unroll
    for(int mt=0; mt<4; mt++){
#pragma unroll
        for(int nt=0; nt<4; nt++){
            int n = bn + wn*32 + nt*8 + (lane&3)*2;
#pragma unroll
            for(int h=0; h<2; h++){
                int m = bm + wm*64 + mt*16 + (lane>>2) + h*8;
                float2 o;
                o.x = scale * acc[mt][nt][h*2];
                o.y = scale * acc[mt][nt][h*2+1];
                *reinterpret_cast<float2*>(Cb + (size_t)m*ldc + n) = o;
            }
        }
    }
}

// ---------- bf16x3 MMA GEMM, tile 128x64, B stored K-MAJOR (ldmatrix.trans) ----------
#define MSA (128*40)
#define MSB (32*72)
#define STG64 (2*MSA + 2*MSB)
#define SM_N64 (2*STG64*2)
__global__ __launch_bounds__(256,2)
void gemm_mma_n64t_k(const bf16* __restrict__ Ahp, const bf16* __restrict__ Alp,
                     const bf16* __restrict__ Bhp, const bf16* __restrict__ Blp,
                     float* __restrict__ C, int lda, int ldb, int ldc,
                     long long sA, long long sB, long long sC,
                     const float* __restrict__ AUX, float beta,
                     int kc, long long sSplit)
{
    extern __shared__ bf16 smp[];
    int tid = threadIdx.x, lane = tid & 31, wid = tid >> 5;
    int wm = wid >> 1, wn = wid & 1;
    int bm = blockIdx.y * 128;
    int sp = blockIdx.x, z = blockIdx.z;
    uint32_t sbase = s2u(smp);
    float acc[2][4][4];
#pragma unroll
    for(int i=0;i<2;i++)
#pragma unroll
        for(int j=0;j<4;j++)
#pragma unroll
            for(int q=0;q<4;q++) acc[i][j][q]=0.f;

    int ks = sp * kc;
    int lr = tid >> 1, lsa = (tid & 1) * 16;
    const bf16* gAh = Ahp + (size_t)z*sA + (size_t)(bm+lr)*lda + ks + lsa;
    const bf16* gAl = Alp + (size_t)z*sA + (size_t)(bm+lr)*lda + ks + lsa;
    uint32_t aOff = (uint32_t)((lr*40 + lsa)*2);
    int brow = tid >> 3, bcs = (tid & 7) * 8;
    const bf16* gBh = Bhp + (size_t)z*sB + (size_t)(ks+brow)*ldb + bcs;
    const bf16* gBl = Blp + (size_t)z*sB + (size_t)(ks+brow)*ldb + bcs;
    uint32_t bOff = (uint32_t)((brow*72 + bcs)*2);

    int aCol = (lane>>4)*8;
    int bKr = (lane&7) + ((lane>>3)&1)*8;
    int bNc = (lane>>4)*8;

    int nch = kc >> 5;
#define PREF(ch, st) do{ \
    uint32_t stb = sbase + (uint32_t)(st)*(STG64*2); \
    size_t goA = (size_t)(ch)*32; \
    size_t goB = (size_t)(ch)*32*ldb; \
    CPA(stb + aOff,             gAh+goA, 16); CPA(stb + aOff + 16,             gAh+goA+8, 16); \
    CPA(stb + MSA*2 + aOff,     gAl+goA, 16); CPA(stb + MSA*2 + aOff + 16,     gAl+goA+8, 16); \
    CPA(stb + MSA*4 + bOff,     gBh+goB, 16); \
    CPA(stb + MSA*4 + MSB*2 + bOff, gBl+goB, 16); \
    CPA_COMMIT(); }while(0)

    PREF(0, 0);

    for(int ch=0; ch<nch; ch++){
        CPA_WAIT0();
        __syncthreads();
        if(ch+1 < nch) PREF(ch+1, (ch+1)&1);
        uint32_t stb = sbase + (uint32_t)(ch&1)*(STG64*2);
        uint32_t bAh = stb, bAl = stb + MSA*2;
        uint32_t bBh = stb + MSA*4, bBl = stb + MSA*4 + MSB*2;
#pragma unroll
        for(int ksu=0; ksu<2; ksu++){
            int kb = ksu*16;
            uint32_t bh[4][2], bl[4][2];
#pragma unroll
            for(int ntp=0; ntp<2; ntp++){
                uint32_t off = (uint32_t)(((kb + bKr)*72 + wn*32 + ntp*16 + bNc)*2);
                LDSM4T(bh[2*ntp][0], bh[2*ntp][1], bh[2*ntp+1][0], bh[2*ntp+1][1], bBh + off);
                LDSM4T(bl[2*ntp][0], bl[2*ntp][1], bl[2*ntp+1][0], bl[2*ntp+1][1], bBl + off);
            }
#pragma unroll
            for(int mt=0; mt<2; mt++){
                uint32_t off = (uint32_t)(((wm*32 + mt*16 + (lane&7) + ((lane>>3)&1)*8)*40 + kb + aCol)*2);
                uint32_t ah[4], al[4];
                LDSM4(ah[0],ah[1],ah[2],ah[3], bAh + off);
                LDSM4(al[0],al[1],al[2],al[3], bAl + off);
#pragma unroll
                for(int nt=0; nt<4; nt++){
                    MMA16816(acc[mt][nt], ah, bh[nt]);
                    MMA16816(acc[mt][nt], ah, bl[nt]);
                    MMA16816(acc[mt][nt], al, bh[nt]);
                }
            }
        }
    }
#undef PREF
    float* Cb = C + (size_t)z*sC + (size_t)sp*sSplit;
    const float* Xb = AUX ? AUX + (size_t)z*sC : nullptr;
#pragma unroll
    for(int mt=0; mt<2; mt++){
#pragma unroll
        for(int nt=0; nt<4; nt++){
            int n = wn*32 + nt*8 + (lane&3)*2;
#pragma unroll
            for(int h=0; h<2; h++){
                int m = bm + wm*32 + mt*16 + (lane>>2) + h*8;
                float v0 = acc[mt][nt][h*2], v1 = acc[mt][nt][h*2+1];
                if(Xb){
                    const float* xp = Xb + (size_t)m*ldc + n;
                    v0 += beta*xp[0]; v1 += beta*xp[1];
                }
                float2 o; o.x = v0; o.y = v1;
                *reinterpret_cast<float2*>(Cb + (size_t)m*ldc + n) = o;
            }
        }
    }
}

// ---- batched strided GEMM 64x64 (f32x2), 256 threads (2 warps/SMSP at 1 CTA/SM) ----
// C = scale*(A@B) + beta*AUX + diag*I, optional bf16 hi/lo outputs.
__global__ __launch_bounds__(256,2)
void gemm64x_k(const float* __restrict__ A, const float* __restrict__ B, float* __restrict__ C,
               int M, int N, int K, int lda, int ldb, int ldc,
               long long sA, long long sB, long long sC,
               float scale, float diag, const float* __restrict__ AUX, float beta,
               bf16* __restrict__ Ch, bf16* __restrict__ Cl)
{
    __shared__ __align__(16) float As[16][64];
    __shared__ __align__(16) float Bs[16][64];
    int z = blockIdx.z;
    const float* Ab = A + (size_t)z * sA;
    const float* Bb = B + (size_t)z * sB;
    size_t cOff = (size_t)z * sC;
    const float* Xb = AUX ? AUX + cOff : nullptr;
    int bm = blockIdx.y*64, bn = blockIdx.x*64;
    int tid = threadIdx.x;
    int tx = tid & 15, ty = tid >> 4;
    ull acc[2][4];
#pragma unroll
    for(int i=0;i<2;i++)
#pragma unroll
        for(int j=0;j<4;j++) acc[i][j]=0ull;

    int am = tid & 63, akq = (tid >> 6) * 4;
    int bkk = tid >> 4, bn4 = (tid & 15) * 4;

    for(int k0=0;k0<K;k0+=16){
        {
            const float* p = Ab + (size_t)(bm+am)*lda + k0 + akq;
            float4 v0 = *reinterpret_cast<const float4*>(p);
            As[akq+0][am]=v0.x; As[akq+1][am]=v0.y; As[akq+2][am]=v0.z; As[akq+3][am]=v0.w;
        }
        {
            float4 b0 = *reinterpret_cast<const float4*>(Bb + (size_t)(k0+bkk)*ldb + bn + bn4);
            *reinterpret_cast<float4*>(&Bs[bkk][bn4]) = b0;
        }
        __syncthreads();
#pragma unroll
        for(int kk=0;kk<16;kk++){
            ulonglong2 a01 = *reinterpret_cast<const ulonglong2*>(&As[kk][ty*4]);
            ull av[2] = {a01.x, a01.y};
            float4 b4 = *reinterpret_cast<const float4*>(&Bs[kk][tx*4]);
            ull bd[4] = {dup2(b4.x),dup2(b4.y),dup2(b4.z),dup2(b4.w)};
#pragma unroll
            for(int i=0;i<2;i++)
#pragma unroll
                for(int j=0;j<4;j++) fma2(acc[i][j], av[i], bd[j]);
        }
        __syncthreads();
    }
#pragma unroll
    for(int i=0;i<2;i++){
#pragma unroll
        for(int rr=0;rr<2;rr++){
            int m = bm + ty*4 + i*2 + rr;
            float v[4];
            float4 xv = make_float4(0,0,0,0);
            if(Xb) xv = *reinterpret_cast<const float4*>(Xb + (size_t)m*ldc + bn + tx*4);
            float xa[4] = {xv.x, xv.y, xv.z, xv.w};
#pragma unroll
            for(int j=0;j<4;j++){
                v[j] = scale * (rr ? hif(acc[i][j]) : lof(acc[i][j]));
                if(Xb) v[j] += beta * xa[j];
                if(m == bn + tx*4 + j) v[j] += diag;
            }
            size_t off = cOff + (size_t)m*ldc + bn + tx*4;
            *reinterpret_cast<float4*>(C + off) = make_float4(v[0],v[1],v[2],v[3]);
            if(Ch){
                bf16 h[4], l[4];
#pragma unroll
                for(int j=0;j<4;j++) split_bf(v[j], h[j], l[j]);
                *reinterpret_cast<uint2*>(Ch + off) = *reinterpret_cast<uint2*>(h);
                *reinterpret_cast<uint2*>(Cl + off) = *reinterpret_cast<uint2*>(l);
            }
        }
    }
}

// ------------------------- small kernels -------------------------
__global__ void zero_pad_k(){ g_LN[blockIdx.x*256 + threadIdx.x] = 0.f; }
__global__ void set_cls_k(const float* __restrict__ c){
    int i = blockIdx.x*256 + threadIdx.x; g_X[i] = c[i];
}
__global__ void cls_copy_k(){
    int i = blockIdx.x*256 + threadIdx.x; g_X2[i] = g_X[i];
}

__global__ void ln_k(const float* __restrict__ X, const float* __restrict__ g,
                     const float* __restrict__ b, float* __restrict__ Y)
{
    __shared__ float sh[8];
    int row = blockIdx.x, t = threadIdx.x;
    const float* x = X + (size_t)row*D;
    float2 v = *reinterpret_cast<const float2*>(x + 2*t);
    float mu = blkSum256(v.x+v.y, sh) * (1.f/(float)D);
    float d0 = v.x-mu, d1 = v.y-mu;
    float var = blkSum256(d0*d0 + d1*d1, sh) * (1.f/(float)D);
    float rs = rsqrtf(var + 1e-5f);
    float2 gg = *reinterpret_cast<const float2*>(g + 2*t);
    float2 bb = *reinterpret_cast<const float2*>(b + 2*t);
    float2 o; o.x = d0*rs*gg.x + bb.x; o.y = d1*rs*gg.y + bb.y;
    *reinterpret_cast<float2*>(Y + (size_t)row*D + 2*t) = o;
}

__global__ void landmarks_k(){
    int j = blockIdx.x, h = blockIdx.y, d = threadIdx.x;
    float sq = 0.f, sk = 0.f;
    const float* base = g_QKV + (size_t)(j*40)*H3 + h*64 + d;
#pragma unroll 8
    for(int t=0;t<40;t++){ sq += base[(size_t)t*H3]; sk += base[(size_t)t*H3 + 512]; }
    float qv = sq * (0.125f/40.f), kv = sk * (1.f/40.f);
    int idx = h*ML*DHD + j*DHD + d;
    g_ql [idx] = qv;
    g_klT[h*DHD*ML + d*ML + j] = kv;
    bf16 hh,ll;
    split_bf(qv,hh,ll); g_qlh[idx]=hh; g_qll[idx]=ll;
    split_bf(kv,hh,ll); g_klh[idx]=hh; g_kll[idx]=ll;
}
__global__ void landmarksK_k(){
    int j = blockIdx.x, h = blockIdx.y, d = threadIdx.x;
    float sk = 0.f;
    const float* base = g_QKV + (size_t)(j*40)*H3 + h*64 + d + 512;
#pragma unroll 8
    for(int t=0;t<40;t++) sk += base[(size_t)t*H3];
    float kv = sk * (1.f/40.f);
    g_klT[h*DHD*ML + d*ML + j] = kv;
    bf16 hh,ll; split_bf(kv,hh,ll);
    int idx = h*ML*DHD + j*DHD + d;
    g_klh[idx]=hh; g_kll[idx]=ll;
}
__global__ void meanrows_k(){
    int j = blockIdx.x, c = threadIdx.x;
    const float* base = g_LN + (size_t)j*40*D + c;
    float s0 = 0.f, s1 = 0.f;
#pragma unroll 8
    for(int t=0;t<40;t++){ s0 += base[(size_t)t*D]; s1 += base[(size_t)t*D + 256]; }
    g_LNm[j*D + c] = s0; g_LNm[j*D + c + 256] = s1;
}

__global__ void softmax256_k(float* __restrict__ Xp, long long hs){
    __shared__ float sh[8];
    float* x = Xp + (size_t)blockIdx.y*hs + (size_t)blockIdx.x*ML;
    float v = x[threadIdx.x];
    float mx = blkMax256(v, sh);
    float e = __expf(v-mx);
    float s = blkSum256(e, sh);
    x[threadIdx.x] = e/s;
}

__global__ void stats256_k(const float* __restrict__ Xp, long long hs, int rows){
    __shared__ float sh[8];
    size_t base = (size_t)blockIdx.y*hs + (size_t)blockIdx.x*ML;
    const float* x = Xp + base;
    float v = x[threadIdx.x];
    float mx = blkMax256(v, sh);
    float e = __expf(v-mx);
    float s = blkSum256(e, sh);
    float p = e/s;
    bf16 hh,ll; split_bf(p,hh,ll);
    g_Ph[base + threadIdx.x] = hh;
    g_Pl[base + threadIdx.x] = ll;
    if(!threadIdx.x){
        int g = blockIdx.y*rows + blockIdx.x;
        g_smx[g] = mx; g_sinv[g] = 1.f/s;
    }
}
__global__ void stats_long_k(const float* __restrict__ Xp, long long hs, int rows){
    __shared__ float sh[8];
    size_t base = (size_t)blockIdx.y*hs + (size_t)blockIdx.x*NPAD;
    const float* x = Xp + base;
    float sc[40]; float mx = -3.0e38f;
#pragma unroll
    for(int c=0;c<40;c++){ sc[c] = x[c*256+threadIdx.x]; mx = fmaxf(mx, sc[c]); }
    mx = blkMax256(mx, sh);
    float s = 0.f;
#pragma unroll
    for(int c=0;c<40;c++){ sc[c] = __expf(sc[c]-mx); s += sc[c]; }
    s = blkSum256(s, sh);
    float inv = 1.f/s;
#pragma unroll
    for(int c=0;c<40;c++){
        float p = sc[c]*inv;
        bf16 hh,ll; split_bf(p,hh,ll);
        g_Ph[base + c*256 + threadIdx.x] = hh;
        g_Pl[base + c*256 + threadIdx.x] = ll;
    }
    if(!threadIdx.x){
        int g = blockIdx.y*rows + blockIdx.x;
        g_smx[g] = mx; g_sinv[g] = 1.f/s;
    }
}

__global__ void rowsum_k(){
    __shared__ float sh[8];
    float v = fabsf(g_a2[(size_t)blockIdx.x*ML + threadIdx.x]);
    v = blkSum256(v, sh);
    if(!threadIdx.x) g_rsum[blockIdx.x] = v;
}
__global__ void colsum_k(){
    __shared__ float sm[8][33];
    int h = blockIdx.x, j0 = blockIdx.y*32;
    int c = threadIdx.x & 31, r0 = threadIdx.x >> 5;
    float acc = 0.f;
    for(int r=r0; r<ML; r+=8) acc += fabsf(g_a2[h*ML*ML + r*ML + j0 + c]);
    sm[r0][c] = acc; __syncthreads();
    if(threadIdx.x < 32){
        float s = 0.f;
#pragma unroll
        for(int q=0;q<8;q++) s += sm[q][threadIdx.x];
        g_csum[h*ML + j0 + threadIdx.x] = s;
    }
}
__global__ void maxred_k(){
    __shared__ float sh[8];
    float mr = 0.f, mc = 0.f;
    for(int i=threadIdx.x; i<NH*ML; i+=256){ mr = fmaxf(mr, g_rsum[i]); mc = fmaxf(mc, g_csum[i]); }
    mr = blkMax256(mr, sh);
    mc = blkMax256(mc, sh);
    if(!threadIdx.x) g_invden = 1.f/(mr*mc);
}

__global__ void zt_k(){
    __shared__ float t[32][33];
    int h = blockIdx.z, i0 = blockIdx.x*32, j0 = blockIdx.y*32;
    int tx = threadIdx.x & 31, ty = threadIdx.x >> 5;
    float inv = g_invden;
#pragma unroll
    for(int rr=0; rr<32; rr+=8)
        t[ty+rr][tx] = g_a2[h*ML*ML + (i0+ty+rr)*ML + j0+tx];
    __syncthreads();
#pragma unroll
    for(int rr=0; rr<32; rr+=8)
        g_Za[(size_t)h*ML*ML + (j0+ty+rr)*ML + i0+tx] = t[tx][ty+rr]*inv;
}

__global__ void reduce_tt_k(){
    int i = blockIdx.x*256 + threadIdx.x;
    int b = i >> 14, r = i & 16383;
    float s = 0.f;
#pragma unroll
    for(int t=0;t<NSPL;t++) s += g_ttp[((size_t)b*NSPL + t)*16384 + r];
    g_tt[(size_t)b*16384 + r] = s;
}

__global__ __launch_bounds__(256)
void conv_res_k(const float* __restrict__ w){
    __shared__ float sv[96][64];
    __shared__ float swt[33];
    int s0 = blockIdx.x*64, c0 = blockIdx.y*64, h = blockIdx.y;
    int tid = threadIdx.x;
    for(int idx=tid; idx<96*64; idx+=256){
        int r = idx >> 6, c = idx & 63;
        int sp = s0 - 16 + r;
        sv[r][c] = ((unsigned)sp < (unsigned)NPAD) ? g_QKV[(size_t)sp*H3 + 1024 + c0 + c] : 0.f;
    }
    if(tid < 33) swt[tid] = w[h*33 + tid];
    __syncthreads();
    int c = tid & 63, sg = tid >> 6;
    int sb2 = sg*16;
    float acc[16];
#pragma unroll
    for(int s=0;s<16;s++) acc[s] = 0.f;
    for(int r=0;r<48;r++){
        float v = sv[sb2 + r][c];
#pragma unroll
        for(int s=0;s<16;s++){
            int k = r - s;
            if(k >= 0 && k < 33) acc[s] += swt[k]*v;
        }
    }
#pragma unroll
    for(int s=0;s<16;s++) g_O[(size_t)(s0+sb2+s)*D + c0 + c] = acc[s];
}

__global__ __launch_bounds__(256)
void ppeg_k(const float* __restrict__ w7, const float* __restrict__ b7,
            const float* __restrict__ w5, const float* __restrict__ b5,
            const float* __restrict__ w3, const float* __restrict__ b3)
{
    __shared__ float st[14][14][32];
    __shared__ float sw[83][32];
    __shared__ float sb[32];
    int cg = blockIdx.z*32;
    int ti0 = blockIdx.y*8, tj0 = blockIdx.x*8;
    int tid = threadIdx.x;
    for(int idx=tid; idx<14*14*32; idx+=256){
        int r = idx/(14*32); int rem = idx - r*14*32; int col = rem>>5; int cc = rem&31;
        int gi = ti0-3+r, gj = tj0-3+col;
        float v = 0.f;
        if((unsigned)gi < 100u && (unsigned)gj < 100u)
            v = g_X[(size_t)(1 + gi*100 + gj)*D + cg + cc];
        st[r][col][cc] = v;
    }
    for(int idx=tid; idx<83*32; idx+=256){
        int t = idx>>5, cc = idx&31; int ch = cg+cc; float w;
        if(t<49) w = w7[ch*49 + t];
        else if(t<74) w = w5[ch*25 + t-49];
        else w = w3[ch*9 + t-74];
        sw[t][cc] = w;
    }
    if(tid < 32) sb[tid] = b7[cg+tid] + b5[cg+tid] + b3[cg+tid];
    __syncthreads();
    int c = tid & 31, i = tid >> 5;
    float acc[8];
#pragma unroll
    for(int j=0;j<8;j++) acc[j] = st[3+i][3+j][c] + sb[c];
#pragma unroll
    for(int di=-3; di<=3; di++){
        float rv[14];
#pragma unroll
        for(int q=0;q<14;q++) rv[q] = st[3+i+di][q][c];
#pragma unroll
        for(int dj=0;dj<7;dj++){
            float w = sw[(di+3)*7+dj][c];
#pragma unroll
            for(int j=0;j<8;j++) acc[j] += w*rv[j+dj];
        }
        if(di>=-2 && di<=2){
#pragma unroll
            for(int dj=0;dj<5;dj++){
                float w = sw[49+(di+2)*5+dj][c];
#pragma unroll
                for(int j=0;j<8;j++) acc[j] += w*rv[j+dj+1];
            }
        }
        if(di>=-1 && di<=1){
#pragma unroll
            for(int dj=0;dj<3;dj++){
                float w = sw[74+(di+1)*3+dj][c];
#pragma unroll
                for(int j=0;j<8;j++) acc[j] += w*rv[j+dj+2];
            }
        }
    }
    int gi = ti0+i;
    if(gi < 100){
#pragma unroll
        for(int j=0;j<8;j++){
            int gj = tj0+j;
            if(gj < 100) g_X2[(size_t)(1 + gi*100 + gj)*D + cg + c] = acc[j];
        }
    }
}

__global__ void l2row_k(const float* __restrict__ rw, const float* __restrict__ qw){
    __shared__ float q[64];
    __shared__ float p[256];
    __shared__ float sh[8];
    int h = blockIdx.x, j = threadIdx.x;
    if(j < 64){
        const float* x = g_LN + (size_t)PADN*D;
        const float* w = qw + h*64 + j;
        float a = 0.f;
        for(int c=0;c<512;c++) a += x[c]*w[(size_t)c*H3];
        q[j] = a;
    }
    __syncthreads();
    float s = 0.f;
#pragma unroll
    for(int d=0; d<64; d++) s += q[d]*g_klT[h*DHD*ML + d*ML + j];
    s *= 0.125f;
    float mx = blkMax256(s, sh);
    float e = __expf(s - mx);
    float sum = blkSum256(e, sh);
    p[j] = e/sum;
    __syncthreads();
    if(j < 64){
        float acc = 0.f;
        for(int t=0;t<256;t++) acc += p[t]*g_uu[h*ML*DHD + t*64 + j];
#pragma unroll
        for(int t=0;t<33;t++)
            acc += rw[h*33+t] * g_QKV[(size_t)(PADN-16+t)*H3 + 1024 + h*64 + j];
        g_orow[h*64 + j] = acc;
    }
}

__global__ void final_head_k(const float* __restrict__ ow, const float* __restrict__ ob,
                             const float* __restrict__ ng, const float* __restrict__ nb,
                             const float* __restrict__ fw, const float* __restrict__ fb,
                             float* __restrict__ out)
{
    __shared__ float o[512];
    __shared__ float f[512];
    __shared__ float sh[8];
    int t = threadIdx.x;
    o[t] = g_orow[t]; o[t+256] = g_orow[t+256];
    __syncthreads();
#pragma unroll
    for(int half=0; half<2; half++){
        int n = t + half*256;
        float v = ob[n] + g_LN[(size_t)PADN*D + n];
        for(int c=0;c<512;c++) v += o[c]*ow[(size_t)c*D + n];
        f[n] = v;
    }
    __syncthreads();
    float v0 = f[t], v1 = f[t+256];
    float mu = blkSum256(v0+v1, sh)*(1.f/512.f);
    float d0 = v0-mu, d1 = v1-mu;
    float var = blkSum256(d0*d0+d1*d1, sh)*(1.f/512.f);
    float rs = rsqrtf(var + 1e-5f);
    float l0 = d0*rs*ng[t]     + nb[t];
    float l1 = d1*rs*ng[t+256] + nb[t+256];
    float s0 = l0*fw[t*2]   + l1*fw[(t+256)*2];
    float s1 = l0*fw[t*2+1] + l1*fw[(t+256)*2+1];
    s0 = blkSum256(s0, sh);
    s1 = blkSum256(s1, sh);
    if(!t){ out[0] = s0 + fb[0]; out[1] = s1 + fb[1]; }
}

// ------------------------- host -------------------------
#define SYMADDR(T, p, s) do{ void* _t; cudaGetSymbolAddress(&_t, s); p = (T*)_t; }while(0)

extern "C" void kernel_launch(void* const* d_in, const int* in_sizes, int n_in,
                              void* d_out, int out_size)
{
    bool sig = (in_sizes[10] == 25088);
    const float* h_in = (const float*)d_in[0];
    const float* fc1w = (const float*)d_in[1];
    const float* fc1b = (const float*)d_in[2];
    const float* cls  = (const float*)d_in[3];
    const float* g1 = (const float*)d_in[4];
    const float* b1 = (const float*)d_in[5];
    const float* qkv1 = (const float*)d_in[6];
    const float* ow1 = (const float*)d_in[7];
    const float* ob1 = (const float*)d_in[8];
    const float* rw1 = (const float*)d_in[9];
    const float *w7,*b7,*w5,*b5,*w3,*b3,*g2,*b2,*qkv2,*ow2,*ob2,*rw2,*ng,*nb,*f2w,*f2b;
    if(sig){
        w7=(const float*)d_in[10]; b7=(const float*)d_in[11];
        w5=(const float*)d_in[12]; b5=(const float*)d_in[13];
        w3=(const float*)d_in[14]; b3=(const float*)d_in[15];
        g2=(const float*)d_in[16]; b2=(const float*)d_in[17];
        qkv2=(const float*)d_in[18]; ow2=(const float*)d_in[19];
        ob2=(const float*)d_in[20]; rw2=(const float*)d_in[21];
    } else {
        g2=(const float*)d_in[10]; b2=(const float*)d_in[11];
        qkv2=(const float*)d_in[12]; ow2=(const float*)d_in[13];
        ob2=(const float*)d_in[14]; rw2=(const float*)d_in[15];
        w7=(const float*)d_in[16]; b7=(const float*)d_in[17];
        w5=(const float*)d_in[18]; b5=(const float*)d_in[19];
        w3=(const float*)d_in[20]; b3=(const float*)d_in[21];
    }
    ng=(const float*)d_in[22]; nb=(const float*)d_in[23];
    f2w=(const float*)d_in[24]; f2b=(const float*)d_in[25];

    float *X,*X2,*LN,*LNm,*QKV,*klT,*ql,*a1,*a3,*a2,*Za,*Zb,*XZ,*M2p,*M4p,*ttp,*tt,*uu,*Ob,*smx,*sinv;
    bf16 *Ah,*Al,*Wth,*Wtl,*KVh,*KVl,*qlh,*qll,*klh,*kll,*Ph,*Pl,*uuh,*uul;
    SYMADDR(float,X,g_X); SYMADDR(float,X2,g_X2); SYMADDR(float,LN,g_LN); SYMADDR(float,LNm,g_LNm);
    SYMADDR(float,QKV,g_QKV); SYMADDR(float,klT,g_klT); SYMADDR(float,ql,g_ql);
    SYMADDR(float,a1,g_a1); SYMADDR(float,a3,g_a3); SYMADDR(float,a2,g_a2);
    SYMADDR(float,Za,g_Za); SYMADDR(float,Zb,g_Zb); SYMADDR(float,XZ,g_XZ);
    SYMADDR(float,M2p,g_M2); SYMADDR(float,M4p,g_M4); SYMADDR(float,ttp,g_ttp);
    SYMADDR(float,tt,g_tt); SYMADDR(float,uu,g_uu); SYMADDR(float,Ob,g_O);
    SYMADDR(float,smx,g_smx); SYMADDR(float,sinv,g_sinv);
    SYMADDR(bf16,Ah,g_Ah); SYMADDR(bf16,Al,g_Al); SYMADDR(bf16,Wth,g_Wth); SYMADDR(bf16,Wtl,g_Wtl);
    SYMADDR(bf16,KVh,g_KVh); SYMADDR(bf16,KVl,g_KVl);
    SYMADDR(bf16,qlh,g_qlh); SYMADDR(bf16,qll,g_qll);
    SYMADDR(bf16,klh,g_klh); SYMADDR(bf16,kll,g_kll);
    SYMADDR(bf16,Ph,g_Ph); SYMADDR(bf16,Pl,g_Pl);
    SYMADDR(bf16,uuh,g_uuh); SYMADDR(bf16,uul,g_uul);

    static cudaStream_t s1 = nullptr, s2 = nullptr;
    static cudaEvent_t ev[8];
    if(!s1){
        cudaStreamCreateWithFlags(&s1, cudaStreamNonBlocking);
        cudaStreamCreateWithFlags(&s2, cudaStreamNonBlocking);
        for(int i=0;i<8;i++) cudaEventCreateWithFlags(&ev[i], cudaEventDisableTiming);
        cudaFuncSetAttribute(gemm_mma_k, cudaFuncAttributeMaxDynamicSharedMemorySize, SM_MMA);
        cudaFuncSetAttribute(gemm_mma_b_k, cudaFuncAttributeMaxDynamicSharedMemorySize, SM_MMA);
        cudaFuncSetAttribute(gemm_mma_n64t_k, cudaFuncAttributeMaxDynamicSharedMemorySize, SM_N64);
    }

    zero_pad_k<<<PADN*D/256, 256>>>();
    cvt_rows_k<<<10000*1024/1024, 256>>>(h_in, Ah, Al);
    cvt_T_k<<<dim3(32,16),256>>>(fc1w, Wth, Wtl, 1024, 512);
    gemm_mma_k<<<dim3(4,79),256,SM_MMA>>>(Ah, Al, Wth, Wtl, fc1b, nullptr, X+D,
                                          10000, 512, 1024, D, 1, 0, 1, nullptr, nullptr);
    set_cls_k<<<2,256>>>(cls);

    long long sM = (long long)ML*ML;
    for(int layer=0; layer<2; layer++){
        const float* xin = layer ? X2 : X;
        const float* gg = layer ? g2 : g1;
        const float* bb = layer ? b2 : b1;
        const float* qw = layer ? qkv2 : qkv1;
        cudaEvent_t evF = ev[layer*4+0], evA = ev[layer*4+1], evB = ev[layer*4+2];

        ln_k<<<NSEQ,256>>>(xin, gg, bb, LN + (size_t)PADN*D);
        cvt_rows_k<<<NPAD*512/1024, 256>>>(LN, Ah, Al);

        const float* Aq; int ldaQ; long long sAQ;
        const bf16 *AqH, *AqL; int ldaQb; long long sAQb;
        if(layer == 0){
            cvt_T_k<<<dim3(16,48),256>>>(qw, Wth, Wtl, 512, 1536);
            gemm_mma_k<<<dim3(12,80),256,SM_MMA>>>(Ah, Al, Wth, Wtl, nullptr, nullptr, QKV,
                                                   NPAD, 1536, 512, H3, 0, 0, 0, KVh, KVl);
            landmarks_k<<<dim3(ML,NH),64>>>();
            Aq = ql; ldaQ = DHD; sAQ = (long long)ML*DHD;
            AqH = qlh; AqL = qll; ldaQb = DHD; sAQb = (long long)ML*DHD;
        } else {
            cvt_T_k<<<dim3(16,32),256>>>(qw+512, Wth, Wtl, 512, 1536);
            gemm_mma_k<<<dim3(8,80),256,SM_MMA>>>(Ah, Al, Wth, Wtl, nullptr, nullptr, QKV+512,
                                                  NPAD, 1024, 512, H3, 0, 0, 0, KVh+512, KVl+512);
            meanrows_k<<<ML,256>>>();
            gemm64x_k<<<dim3(8,4,1),256>>>(LNm, qw, ql, ML, 512, 512, 512, H3, 512,
                        0,0,0, 0.125f/40.f, 0.f, nullptr, 0.f, qlh, qll);
            landmarksK_k<<<dim3(ML,NH),64>>>();
            Aq = ql; ldaQ = 512; sAQ = 64;
            AqH = qlh; AqL = qll; ldaQb = 512; sAQb = 64;
        }

        // a2 = softmax(ql @ kl^T)
        gemm64x_k<<<dim3(4,4,NH),256>>>(Aq, klT, a2, ML,ML,DHD, ldaQ,ML,ML,
                    sAQ,(long long)DHD*ML,sM, 1.f,0.f, nullptr,0.f, nullptr,nullptr);
        softmax256_k<<<dim3(ML,NH),256>>>(a2, sM);

        // ---- fork: pinv chain on s1, conv on s2 (layer 0) ----
        cudaEventRecord(evF, 0);
        cudaStreamWaitEvent(s1, evF, 0);
        rowsum_k<<<NH*ML,256,0,s1>>>();
        colsum_k<<<dim3(NH,8),256,0,s1>>>();
        maxred_k<<<1,256,0,s1>>>();
        zt_k<<<dim3(8,8,NH),256,0,s1>>>();
        float* za = Za; float* zb = Zb;
        for(int it=0; it<6; it++){
            gemm64x_k<<<dim3(4,4,NH),256,0,s1>>>(a2, za, XZ, ML,ML,ML, ML,ML,ML, sM,sM,sM,
                        1.f,0.f, nullptr,0.f, nullptr,nullptr);
            gemm64x_k<<<dim3(4,4,NH),256,0,s1>>>(XZ, XZ, M2p, ML,ML,ML, ML,ML,ML, sM,sM,sM,
                        -1.f,-15.f, XZ,7.f, nullptr,nullptr);
            gemm64x_k<<<dim3(4,4,NH),256,0,s1>>>(XZ, M2p, M4p, ML,ML,ML, ML,ML,ML, sM,sM,sM,
                        1.f,13.f, nullptr,0.f, nullptr,nullptr);
            gemm64x_k<<<dim3(4,4,NH),256,0,s1>>>(za, M4p, zb, ML,ML,ML, ML,ML,ML, sM,sM,sM,
                        0.25f,0.f, nullptr,0.f, nullptr,nullptr);
            float* tmp = za; za = zb; zb = tmp;
        }
        cudaEventRecord(evA, s1);

        if(layer == 0){
            cudaStreamWaitEvent(s2, evF, 0);
            conv_res_k<<<dim3(NPAD/64, NH),256,0,s2>>>(rw1);
            cudaEventRecord(evB, s2);
        }

        // ---- main stream: a3 (MMA) -> stats+P3 -> tt (MMA, split-K) ----
        gemm_mma_b_k<<<dim3(NPAD/128, ML/128, NH),256,SM_MMA>>>(AqH, AqL, KVh+512, KVl+512,
                    a3, NPAD, DHD, ldaQb, H3, NPAD, sAQb, 64LL, (long long)ML*NPAD, 1.f);
        stats_long_k<<<dim3(ML,NH),256>>>(a3, (long long)ML*NPAD, ML);
        gemm_mma_n64t_k<<<dim3(NSPL, ML/128, NH),256,SM_N64>>>(Ph, Pl, KVh+1024, KVl+1024,
                    ttp, NPAD, H3, DHD, (long long)ML*NPAD, 64LL, (long long)NSPL*ML*DHD,
                    nullptr, 0.f, KCH, (long long)ML*DHD);
        reduce_tt_k<<<NH*ML*DHD/256,256>>>();
        if(layer == 0){
            gemm_mma_b_k<<<dim3(ML/128, NPAD/128, NH),256,SM_MMA>>>(KVh, KVl, klh, kll,
                    a1, ML, DHD, H3, DHD, ML, 64LL, (long long)ML*DHD, (long long)NPAD*ML, 0.125f);
            stats256_k<<<dim3(NPAD,NH),256>>>(a1, (long long)NPAD*ML, NPAD);
        }

        // ---- join pinv, compute uu (+bf16 split) ----
        cudaStreamWaitEvent(0, evA, 0);
        gemm64x_k<<<dim3(1,4,NH),256>>>(za, tt, uu, ML,DHD,ML, ML,DHD,DHD,
                    sM,(long long)ML*DHD,(long long)ML*DHD, 1.f,0.f, nullptr,0.f, uuh, uul);

        if(layer == 0){
            cudaStreamWaitEvent(0, evB, 0);
            gemm_mma_n64t_k<<<dim3(1, NPAD/128, NH),256,SM_N64>>>(Ph, Pl, uuh, uul,
                    Ob, ML, DHD, D, (long long)NPAD*ML, (long long)ML*DHD, 64LL,
                    Ob, 1.f, ML, 0);
            cvt_rows_k<<<NPAD*512/1024, 256>>>(Ob, Ah, Al);
            cvt_T_k<<<dim3(16,16),256>>>(ow1, Wth, Wtl, 512, 512);
            gemm_mma_k<<<dim3(4,79),256,SM_MMA>>>(Ah + (size_t)PADN*D, Al + (size_t)PADN*D,
                                                  Wth, Wtl, ob1, LN + (size_t)PADN*D, X,
                                                  NSEQ, 512, 512, D, 1, 1, 0, nullptr, nullptr);
            ppeg_k<<<dim3(13,13,16),256>>>(w7,b7,w5,b5,w3,b3);
            cls_copy_k<<<2,256>>>();
        } else {
            l2row_k<<<NH,256>>>(rw2, qw);
            final_head_k<<<1,256>>>(ow2, ob2, ng, nb, f2w, f2b, (float*)d_out);
        }
    }
}

// round 16
// speedup vs baseline: 1.0535x; 1.0506x over previous
#include <cuda_runtime.h>
#include <cuda_bf16.h>
#include <math.h>
#include <stdint.h>

#define D    512
#define H3   1536
#define NH   8
#define DHD  64
#define NSEQ 10001
#define NPAD 10240
#define PADN 239
#define ML   256
#define NSPL 8
#define KCH  (NPAD/NSPL)

typedef __nv_bfloat16 bf16;

// ------------------------- scratch (device globals) -------------------------
__device__ float g_X  [NSEQ*D];
__device__ float g_X2 [NSEQ*D];
__device__ float g_LN [NPAD*D];
__device__ float g_LNm[ML*D];
__device__ float g_QKV[(size_t)NPAD*H3];
__device__ float g_klT[NH*DHD*ML];
__device__ float g_ql [NH*ML*DHD];
__device__ float g_a1 [(size_t)NH*NPAD*ML];
__device__ float g_a3 [(size_t)NH*ML*NPAD];
__device__ float g_a2 [NH*ML*ML];
__device__ float g_Za [NH*ML*ML];
__device__ float g_Zb [NH*ML*ML];
__device__ float g_XZ [NH*ML*ML];
__device__ float g_M2 [NH*ML*ML];
__device__ float g_M4 [NH*ML*ML];
__device__ float g_ttp[(size_t)NH*NSPL*ML*DHD];
__device__ float g_tt [NH*ML*DHD];
__device__ float g_uu [NH*ML*DHD];
__device__ float g_O  [(size_t)NPAD*D];
__device__ float g_smx [NH*NPAD];
__device__ float g_sinv[NH*NPAD];
__device__ float g_orow[D];
__device__ float g_rsum[NH*ML];
__device__ float g_csum[NH*ML];
__device__ float g_invden;
// bf16 hi/lo operand buffers
__device__ bf16 g_Ah[(size_t)NPAD*1024];
__device__ bf16 g_Al[(size_t)NPAD*1024];
__device__ bf16 g_Wth[1536*512];
__device__ bf16 g_Wtl[1536*512];
__device__ bf16 g_KVh[(size_t)NPAD*H3];
__device__ bf16 g_KVl[(size_t)NPAD*H3];
__device__ bf16 g_qlh[NH*ML*DHD];
__device__ bf16 g_qll[NH*ML*DHD];
__device__ bf16 g_klh[NH*ML*DHD];
__device__ bf16 g_kll[NH*ML*DHD];
__device__ bf16 g_Ph [(size_t)NH*NPAD*ML];
__device__ bf16 g_Pl [(size_t)NH*NPAD*ML];
__device__ bf16 g_uuh[NH*ML*DHD];
__device__ bf16 g_uul[NH*ML*DHD];

// ------------------------- f32x2 helpers -------------------------
typedef unsigned long long ull;
__device__ __forceinline__ void fma2(ull& d, ull a, ull b){
    asm("fma.rn.f32x2 %0, %1, %2, %0;" : "+l"(d) : "l"(a), "l"(b));
}
__device__ __forceinline__ ull dup2(float b){
    ull r; asm("mov.b64 %0, {%1, %1};" : "=l"(r) : "f"(b)); return r;
}
__device__ __forceinline__ float lof(ull v){ return __uint_as_float((unsigned)v); }
__device__ __forceinline__ float hif(ull v){ return __uint_as_float((unsigned)(v>>32)); }

__device__ __forceinline__ uint32_t s2u(const void* p){
    uint32_t a;
    asm("{ .reg .u64 t; cvta.to.shared.u64 t, %1; cvt.u32.u64 %0, t; }" : "=r"(a) : "l"(p));
    return a;
}
#define LDSM4(r0,r1,r2,r3,addr) \
    asm volatile("ldmatrix.sync.aligned.m8n8.x4.shared.b16 {%0,%1,%2,%3}, [%4];" \
        : "=r"(r0),"=r"(r1),"=r"(r2),"=r"(r3) : "r"(addr))
#define LDSM4T(r0,r1,r2,r3,addr) \
    asm volatile("ldmatrix.sync.aligned.m8n8.x4.trans.shared.b16 {%0,%1,%2,%3}, [%4];" \
        : "=r"(r0),"=r"(r1),"=r"(r2),"=r"(r3) : "r"(addr))
#define MMA16816(d, a, b) \
    asm volatile("mma.sync.aligned.m16n8k16.row.col.f32.bf16.bf16.f32 " \
        "{%0,%1,%2,%3},{%4,%5,%6,%7},{%8,%9},{%0,%1,%2,%3};" \
        : "+f"((d)[0]),"+f"((d)[1]),"+f"((d)[2]),"+f"((d)[3]) \
        : "r"((a)[0]),"r"((a)[1]),"r"((a)[2]),"r"((a)[3]), "r"((b)[0]),"r"((b)[1]))
#define CPA(dst, src, sz) \
    asm volatile("cp.async.ca.shared.global [%0], [%1], 16, %2;" \
        :: "r"(dst), "l"(src), "r"(sz) : "memory")
#define CPA_COMMIT() asm volatile("cp.async.commit_group;" ::: "memory")
#define CPA_WAIT0()  asm volatile("cp.async.wait_group 0;" ::: "memory")

// ------------------------- block reductions (256 thr) -------------------------
__device__ __forceinline__ float blkSum256(float v, float* sh){
#pragma unroll
    for(int o=16;o;o>>=1) v += __shfl_xor_sync(0xffffffffu, v, o);
    __syncthreads();
    if((threadIdx.x&31)==0) sh[threadIdx.x>>5]=v;
    __syncthreads();
    float r = sh[0];
#pragma unroll
    for(int i=1;i<8;i++) r += sh[i];
    return r;
}
__device__ __forceinline__ float blkMax256(float v, float* sh){
#pragma unroll
    for(int o=16;o;o>>=1) v = fmaxf(v, __shfl_xor_sync(0xffffffffu, v, o));
    __syncthreads();
    if((threadIdx.x&31)==0) sh[threadIdx.x>>5]=v;
    __syncthreads();
    float r = sh[0];
#pragma unroll
    for(int i=1;i<8;i++) r = fmaxf(r, sh[i]);
    return r;
}

// ------------------------- bf16 hi/lo converters -------------------------
__device__ __forceinline__ void split_bf(float a, bf16& h, bf16& l){
    h = __float2bfloat16_rn(a);
    l = __float2bfloat16_rn(a - __bfloat162float(h));
}
__global__ void cvt_rows_k(const float* __restrict__ s, bf16* __restrict__ dh,
                           bf16* __restrict__ dl){
    size_t i = ((size_t)blockIdx.x*256 + threadIdx.x)*4;
    float4 v = *reinterpret_cast<const float4*>(s+i);
    bf16 h[4], l[4];
    split_bf(v.x,h[0],l[0]); split_bf(v.y,h[1],l[1]);
    split_bf(v.z,h[2],l[2]); split_bf(v.w,h[3],l[3]);
    *reinterpret_cast<uint2*>(dh+i) = *reinterpret_cast<uint2*>(h);
    *reinterpret_cast<uint2*>(dl+i) = *reinterpret_cast<uint2*>(l);
}
__global__ void cvt_T_k(const float* __restrict__ W, bf16* __restrict__ dh,
                        bf16* __restrict__ dl, int Kd, int Nd){
    __shared__ float sm[32][33];
    int k0 = blockIdx.x*32, n0 = blockIdx.y*32;
    int c = threadIdx.x & 31, r = threadIdx.x >> 5;
#pragma unroll
    for(int p=0;p<4;p++)
        sm[p*8+r][c] = W[(size_t)(k0+p*8+r)*Nd + n0 + c];
    __syncthreads();
#pragma unroll
    for(int p=0;p<4;p++){
        int nn = p*8 + r;
        float v = sm[c][nn];
        bf16 h,l; split_bf(v,h,l);
        dh[(size_t)(n0+nn)*Kd + k0 + c] = h;
        dl[(size_t)(n0+nn)*Kd + k0 + c] = l;
    }
}

// ---------- bf16x3 tensor-core GEMM, 2-stage cp.async pipeline (2 CTA/SM) ----------
#define MS  (128*40)
#define SM_MMA (2*4*MS*2)
__global__ __launch_bounds__(256,2)
void gemm_mma_k(const bf16* __restrict__ Ahp, const bf16* __restrict__ Alp,
                const bf16* __restrict__ Bhp, const bf16* __restrict__ Blp,
                const float* __restrict__ bias, const float* __restrict__ R,
                float* __restrict__ C, int M, int N, int K, int ldc,
                int DOBIAS, int DORES, int DORELU,
                bf16* __restrict__ Chp, bf16* __restrict__ Clp)
{
    extern __shared__ bf16 smp[];
    int tid = threadIdx.x, lane = tid & 31, wid = tid >> 5;
    int wm = wid >> 2, wn = wid & 3;
    int bm = blockIdx.y * 128, bn = blockIdx.x * 128;
    uint32_t sbase = s2u(smp);
    float acc[4][4][4];
#pragma unroll
    for(int i=0;i<4;i++)
#pragma unroll
        for(int j=0;j<4;j++)
#pragma unroll
            for(int q=0;q<4;q++) acc[i][j][q]=0.f;

    int lr = tid >> 1, ls = (tid & 1) * 16;
    int aok = (bm + lr < M) ? 16 : 0;
    const bf16* gAh = Ahp + (size_t)(bm+lr)*K + ls;
    const bf16* gAl = Alp + (size_t)(bm+lr)*K + ls;
    const bf16* gBh = Bhp + (size_t)(bn+lr)*K + ls;
    const bf16* gBl = Blp + (size_t)(bn+lr)*K + ls;
    uint32_t dOff = (uint32_t)((lr*40 + ls)*2);

    int aRow = wm*64 + (lane&7) + ((lane>>3)&1)*8;
    int aCol = (lane>>4)*8;
    int bRow = wn*32 + (lane&7) + (lane>>4)*8;
    int bCol = ((lane>>3)&1)*8;

    int nch = K >> 5;
#define PREF(ch, st) do{ \
    uint32_t db = sbase + (uint32_t)(st)*(4*MS*2) + dOff; \
    size_t go = (size_t)(ch)*32; \
    CPA(db,          gAh+go, aok); CPA(db+16,          gAh+go+8, aok); \
    CPA(db+MS*2,     gAl+go, aok); CPA(db+MS*2+16,     gAl+go+8, aok); \
    CPA(db+MS*4,     gBh+go, 16);  CPA(db+MS*4+16,     gBh+go+8, 16); \
    CPA(db+MS*6,     gBl+go, 16);  CPA(db+MS*6+16,     gBl+go+8, 16); \
    CPA_COMMIT(); }while(0)

    PREF(0, 0);

    for(int ch=0; ch<nch; ch++){
        CPA_WAIT0();
        __syncthreads();
        if(ch+1 < nch) PREF(ch+1, (ch+1)&1);
        uint32_t stb = sbase + (uint32_t)(ch&1)*(4*MS*2);
        uint32_t bAh = stb, bAl = stb + MS*2, bBh = stb + MS*4, bBl = stb + MS*6;
#pragma unroll
        for(int ks=0; ks<2; ks++){
            int kc = ks*16;
            uint32_t bh[4][2], bl[4][2];
#pragma unroll
            for(int ntp=0; ntp<2; ntp++){
                uint32_t off = (uint32_t)(((bRow + ntp*16)*40 + kc + bCol)*2);
                LDSM4(bh[2*ntp][0], bh[2*ntp][1], bh[2*ntp+1][0], bh[2*ntp+1][1], bBh + off);
                LDSM4(bl[2*ntp][0], bl[2*ntp][1], bl[2*ntp+1][0], bl[2*ntp+1][1], bBl + off);
            }
#pragma unroll
            for(int mt=0; mt<4; mt++){
                uint32_t off = (uint32_t)(((aRow + mt*16)*40 + kc + aCol)*2);
                uint32_t ah[4], al[4];
                LDSM4(ah[0],ah[1],ah[2],ah[3], bAh + off);
                LDSM4(al[0],al[1],al[2],al[3], bAl + off);
#pragma unroll
                for(int nt=0; nt<4; nt++){
                    MMA16816(acc[mt][nt], ah, bh[nt]);
                    MMA16816(acc[mt][nt], ah, bl[nt]);
                    MMA16816(acc[mt][nt], al, bh[nt]);
                }
            }
        }
    }
#undef PREF
#pragma unroll
    for(int mt=0; mt<4; mt++){
#pragma unroll
        for(int nt=0; nt<4; nt++){
            int n = bn + wn*32 + nt*8 + (lane&3)*2;
#pragma unroll
            for(int h=0; h<2; h++){
                int m = bm + wm*64 + mt*16 + (lane>>2) + h*8;
                if(m < M){
                    float v0 = acc[mt][nt][h*2], v1 = acc[mt][nt][h*2+1];
                    if(DOBIAS){ v0 += bias[n]; v1 += bias[n+1]; }
                    if(DORES){
                        const float* rp = R + (size_t)m*ldc + n;
                        v0 += rp[0]; v1 += rp[1];
                    }
                    if(DORELU){ v0 = fmaxf(v0,0.f); v1 = fmaxf(v1,0.f); }
                    float2 o; o.x = v0; o.y = v1;
                    *reinterpret_cast<float2*>(C + (size_t)m*ldc + n) = o;
                    if(Chp){
                        bf16 hh[2], ll[2];
                        split_bf(v0, hh[0], ll[0]);
                        split_bf(v1, hh[1], ll[1]);
                        *reinterpret_cast<uint32_t*>(Chp + (size_t)m*ldc + n) = *reinterpret_cast<uint32_t*>(hh);
                        *reinterpret_cast<uint32_t*>(Clp + (size_t)m*ldc + n) = *reinterpret_cast<uint32_t*>(ll);
                    }
                }
            }
        }
    }
}

// ---------- batched/strided bf16x3 MMA GEMM: C = scale*(A@B), B [N][K] rows ----------
__global__ __launch_bounds__(256,2)
void gemm_mma_b_k(const bf16* __restrict__ Ahp, const bf16* __restrict__ Alp,
                  const bf16* __restrict__ Bhp, const bf16* __restrict__ Blp,
                  float* __restrict__ C, int N, int K,
                  int lda, int ldb, int ldc,
                  long long sA, long long sB, long long sC, float scale)
{
    extern __shared__ bf16 smp[];
    int tid = threadIdx.x, lane = tid & 31, wid = tid >> 5;
    int wm = wid >> 2, wn = wid & 3;
    int bm = blockIdx.y * 128, bn = blockIdx.x * 128;
    int z = blockIdx.z;
    uint32_t sbase = s2u(smp);
    float acc[4][4][4];
#pragma unroll
    for(int i=0;i<4;i++)
#pragma unroll
        for(int j=0;j<4;j++)
#pragma unroll
            for(int q=0;q<4;q++) acc[i][j][q]=0.f;

    int lr = tid >> 1, ls = (tid & 1) * 16;
    const bf16* gAh = Ahp + (size_t)z*sA + (size_t)(bm+lr)*lda + ls;
    const bf16* gAl = Alp + (size_t)z*sA + (size_t)(bm+lr)*lda + ls;
    const bf16* gBh = Bhp + (size_t)z*sB + (size_t)(bn+lr)*ldb + ls;
    const bf16* gBl = Blp + (size_t)z*sB + (size_t)(bn+lr)*ldb + ls;
    uint32_t dOff = (uint32_t)((lr*40 + ls)*2);

    int aRow = wm*64 + (lane&7) + ((lane>>3)&1)*8;
    int aCol = (lane>>4)*8;
    int bRow = wn*32 + (lane&7) + (lane>>4)*8;
    int bCol = ((lane>>3)&1)*8;

    int nch = K >> 5;
#define PREF(ch, st) do{ \
    uint32_t db = sbase + (uint32_t)(st)*(4*MS*2) + dOff; \
    size_t go = (size_t)(ch)*32; \
    CPA(db,          gAh+go, 16); CPA(db+16,          gAh+go+8, 16); \
    CPA(db+MS*2,     gAl+go, 16); CPA(db+MS*2+16,     gAl+go+8, 16); \
    CPA(db+MS*4,     gBh+go, 16); CPA(db+MS*4+16,     gBh+go+8, 16); \
    CPA(db+MS*6,     gBl+go, 16); CPA(db+MS*6+16,     gBl+go+8, 16); \
    CPA_COMMIT(); }while(0)

    PREF(0, 0);

    for(int ch=0; ch<nch; ch++){
        CPA_WAIT0();
        __syncthreads();
        if(ch+1 < nch) PREF(ch+1, (ch+1)&1);
        uint32_t stb = sbase + (uint32_t)(ch&1)*(4*MS*2);
        uint32_t bAh = stb, bAl = stb + MS*2, bBh = stb + MS*4, bBl = stb + MS*6;
#pragma unroll
        for(int ks=0; ks<2; ks++){
            int kc = ks*16;
            uint32_t bh[4][2], bl[4][2];
#pragma unroll
            for(int ntp=0; ntp<2; ntp++){
                uint32_t off = (uint32_t)(((bRow + ntp*16)*40 + kc + bCol)*2);
                LDSM4(bh[2*ntp][0], bh[2*ntp][1], bh[2*ntp+1][0], bh[2*ntp+1][1], bBh + off);
                LDSM4(bl[2*ntp][0], bl[2*ntp][1], bl[2*ntp+1][0], bl[2*ntp+1][1], bBl + off);
            }
#pragma unroll
            for(int mt=0; mt<4; mt++){
                uint32_t off = (uint32_t)(((aRow + mt*16)*40 + kc + aCol)*2);
                uint32_t ah[4], al[4];
                LDSM4(ah[0],ah[1],ah[2],ah[3], bAh + off);
                LDSM4(al[0],al[1],al[2],al[3], bAl + off);
#pragma unroll
                for(int nt=0; nt<4; nt++){
                    MMA16816(acc[mt][nt], ah, bh[nt]);
                    MMA16816(acc[mt][nt], ah, bl[nt]);
                    MMA16816(acc[mt][nt], al, bh[nt]);
                }
            }
        }
    }
#undef PREF
    float* Cb = C + (size_t)z*sC;
#pragma unroll
    for(int mt=0; mt<4; mt++){
#pragma unroll
        for(int nt=0; nt<4; nt++){
            int n = bn + wn*32 + nt*8 + (lane&3)*2;
#pragma unroll
            for(int h=0; h<2; h++){
                int m = bm + wm*64 + mt*16 + (lane>>2) + h*8;
                float2 o;
                o.x = scale * acc[mt][nt][h*2];
                o.y = scale * acc[mt][nt][h*2+1];
                *reinterpret_cast<float2*>(Cb + (size_t)m*ldc + n) = o;
            }
        }
    }
}

// ---------- bf16x3 MMA GEMM, tile 128x64, B stored K-MAJOR (ldmatrix.trans) ----------
#define MSA (128*40)
#define MSB (32*72)
#define STG64 (2*MSA + 2*MSB)
#define SM_N64 (2*STG64*2)
__global__ __launch_bounds__(256,2)
void gemm_mma_n64t_k(const bf16* __restrict__ Ahp, const bf16* __restrict__ Alp,
                     const bf16* __restrict__ Bhp, const bf16* __restrict__ Blp,
                     float* __restrict__ C, int lda, int ldb, int ldc,
                     long long sA, long long sB, long long sC,
                     const float* __restrict__ AUX, float beta,
                     int kc, long long sSplit)
{
    extern __shared__ bf16 smp[];
    int tid = threadIdx.x, lane = tid & 31, wid = tid >> 5;
    int wm = wid >> 1, wn = wid & 1;
    int bm = blockIdx.y * 128;
    int sp = blockIdx.x, z = blockIdx.z;
    uint32_t sbase = s2u(smp);
    float acc[2][4][4];
#pragma unroll
    for(int i=0;i<2;i++)
#pragma unroll
        for(int j=0;j<4;j++)
#pragma unroll
            for(int q=0;q<4;q++) acc[i][j][q]=0.f;

    int ks = sp * kc;
    int lr = tid >> 1, lsa = (tid & 1) * 16;
    const bf16* gAh = Ahp + (size_t)z*sA + (size_t)(bm+lr)*lda + ks + lsa;
    const bf16* gAl = Alp + (size_t)z*sA + (size_t)(bm+lr)*lda + ks + lsa;
    uint32_t aOff = (uint32_t)((lr*40 + lsa)*2);
    int brow = tid >> 3, bcs = (tid & 7) * 8;
    const bf16* gBh = Bhp + (size_t)z*sB + (size_t)(ks+brow)*ldb + bcs;
    const bf16* gBl = Blp + (size_t)z*sB + (size_t)(ks+brow)*ldb + bcs;
    uint32_t bOff = (uint32_t)((brow*72 + bcs)*2);

    int aCol = (lane>>4)*8;
    int bKr = (lane&7) + ((lane>>3)&1)*8;
    int bNc = (lane>>4)*8;

    int nch = kc >> 5;
#define PREF(ch, st) do{ \
    uint32_t stb = sbase + (uint32_t)(st)*(STG64*2); \
    size_t goA = (size_t)(ch)*32; \
    size_t goB = (size_t)(ch)*32*ldb; \
    CPA(stb + aOff,             gAh+goA, 16); CPA(stb + aOff + 16,             gAh+goA+8, 16); \
    CPA(stb + MSA*2 + aOff,     gAl+goA, 16); CPA(stb + MSA*2 + aOff + 16,     gAl+goA+8, 16); \
    CPA(stb + MSA*4 + bOff,     gBh+goB, 16); \
    CPA(stb + MSA*4 + MSB*2 + bOff, gBl+goB, 16); \
    CPA_COMMIT(); }while(0)

    PREF(0, 0);

    for(int ch=0; ch<nch; ch++){
        CPA_WAIT0();
        __syncthreads();
        if(ch+1 < nch) PREF(ch+1, (ch+1)&1);
        uint32_t stb = sbase + (uint32_t)(ch&1)*(STG64*2);
        uint32_t bAh = stb, bAl = stb + MSA*2;
        uint32_t bBh = stb + MSA*4, bBl = stb + MSA*4 + MSB*2;
#pragma unroll
        for(int ksu=0; ksu<2; ksu++){
            int kb = ksu*16;
            uint32_t bh[4][2], bl[4][2];
#pragma unroll
            for(int ntp=0; ntp<2; ntp++){
                uint32_t off = (uint32_t)(((kb + bKr)*72 + wn*32 + ntp*16 + bNc)*2);
                LDSM4T(bh[2*ntp][0], bh[2*ntp][1], bh[2*ntp+1][0], bh[2*ntp+1][1], bBh + off);
                LDSM4T(bl[2*ntp][0], bl[2*ntp][1], bl[2*ntp+1][0], bl[2*ntp+1][1], bBl + off);
            }
#pragma unroll
            for(int mt=0; mt<2; mt++){
                uint32_t off = (uint32_t)(((wm*32 + mt*16 + (lane&7) + ((lane>>3)&1)*8)*40 + kb + aCol)*2);
                uint32_t ah[4], al[4];
                LDSM4(ah[0],ah[1],ah[2],ah[3], bAh + off);
                LDSM4(al[0],al[1],al[2],al[3], bAl + off);
#pragma unroll
                for(int nt=0; nt<4; nt++){
                    MMA16816(acc[mt][nt], ah, bh[nt]);
                    MMA16816(acc[mt][nt], ah, bl[nt]);
                    MMA16816(acc[mt][nt], al, bh[nt]);
                }
            }
        }
    }
#undef PREF
    float* Cb = C + (size_t)z*sC + (size_t)sp*sSplit;
    const float* Xb = AUX ? AUX + (size_t)z*sC : nullptr;
#pragma unroll
    for(int mt=0; mt<2; mt++){
#pragma unroll
        for(int nt=0; nt<4; nt++){
            int n = wn*32 + nt*8 + (lane&3)*2;
#pragma unroll
            for(int h=0; h<2; h++){
                int m = bm + wm*32 + mt*16 + (lane>>2) + h*8;
                float v0 = acc[mt][nt][h*2], v1 = acc[mt][nt][h*2+1];
                if(Xb){
                    const float* xp = Xb + (size_t)m*ldc + n;
                    v0 += beta*xp[0]; v1 += beta*xp[1];
                }
                float2 o; o.x = v0; o.y = v1;
                *reinterpret_cast<float2*>(Cb + (size_t)m*ldc + n) = o;
            }
        }
    }
}

// ---- batched strided GEMM 64x64 (f32x2): C = scale*(A@B) + beta*AUX + diag*I ----
__global__ __launch_bounds__(128,4)
void gemm64_k(const float* __restrict__ A, const float* __restrict__ B, float* __restrict__ C,
              int M, int N, int K, int lda, int ldb, int ldc,
              long long sA, long long sB, long long sC,
              float scale, float diag, const float* __restrict__ AUX, float beta,
              int nsplit, int kc, long long sSplit,
              bf16* __restrict__ Ch, bf16* __restrict__ Cl)
{
    __shared__ __align__(16) float As[16][64];
    __shared__ __align__(16) float Bs[16][64];
    int z = blockIdx.z;
    int sp = z % nsplit, bidx = z / nsplit;
    const float* Ab = A + (size_t)bidx * sA;
    const float* Bb = B + (size_t)bidx * sB;
    size_t cOff = (size_t)bidx * sC + (size_t)sp * sSplit;
    const float* Xb = AUX ? AUX + cOff : nullptr;
    int bm = blockIdx.y*64, bn = blockIdx.x*64;
    int tid = threadIdx.x;
    int tx = tid & 15, ty = tid >> 4;
    ull acc[4][4];
#pragma unroll
    for(int i=0;i<4;i++)
#pragma unroll
        for(int j=0;j<4;j++) acc[i][j]=0ull;

    int am = tid & 63, akq = (tid >> 6) * 8;
    int bkk = tid >> 4, bn4 = (tid & 15) * 4;
    int ks = sp*kc, ke = ks + kc;

    for(int k0=ks;k0<ke;k0+=16){
        {
            const float* p = Ab + (size_t)(bm+am)*lda + k0 + akq;
            float4 v0 = *reinterpret_cast<const float4*>(p);
            float4 v1 = *reinterpret_cast<const float4*>(p+4);
            As[akq+0][am]=v0.x; As[akq+1][am]=v0.y; As[akq+2][am]=v0.z; As[akq+3][am]=v0.w;
            As[akq+4][am]=v1.x; As[akq+5][am]=v1.y; As[akq+6][am]=v1.z; As[akq+7][am]=v1.w;
        }
        {
            float4 b0 = *reinterpret_cast<const float4*>(Bb + (size_t)(k0+bkk)*ldb + bn + bn4);
            float4 b1 = *reinterpret_cast<const float4*>(Bb + (size_t)(k0+bkk+8)*ldb + bn + bn4);
            *reinterpret_cast<float4*>(&Bs[bkk][bn4])   = b0;
            *reinterpret_cast<float4*>(&Bs[bkk+8][bn4]) = b1;
        }
        __syncthreads();
#pragma unroll
        for(int kk=0;kk<16;kk++){
            ulonglong2 a01 = *reinterpret_cast<const ulonglong2*>(&As[kk][ty*8]);
            ulonglong2 a23 = *reinterpret_cast<const ulonglong2*>(&As[kk][ty*8+4]);
            ull av[4] = {a01.x, a01.y, a23.x, a23.y};
            float4 b4 = *reinterpret_cast<const float4*>(&Bs[kk][tx*4]);
            ull bd[4] = {dup2(b4.x),dup2(b4.y),dup2(b4.z),dup2(b4.w)};
#pragma unroll
            for(int i=0;i<4;i++)
#pragma unroll
                for(int j=0;j<4;j++) fma2(acc[i][j], av[i], bd[j]);
        }
        __syncthreads();
    }
#pragma unroll
    for(int i=0;i<4;i++){
#pragma unroll
        for(int rr=0;rr<2;rr++){
            int m = bm + ty*8 + i*2 + rr;
            float v[4];
            float4 xv = make_float4(0,0,0,0);
            if(Xb) xv = *reinterpret_cast<const float4*>(Xb + (size_t)m*ldc + bn + tx*4);
            float xa[4] = {xv.x, xv.y, xv.z, xv.w};
#pragma unroll
            for(int j=0;j<4;j++){
                v[j] = scale * (rr ? hif(acc[i][j]) : lof(acc[i][j]));
                if(Xb) v[j] += beta * xa[j];
                if(m == bn + tx*4 + j) v[j] += diag;
            }
            size_t off = cOff + (size_t)m*ldc + bn + tx*4;
            *reinterpret_cast<float4*>(C + off) = make_float4(v[0],v[1],v[2],v[3]);
            if(Ch){
                bf16 h[4], l[4];
#pragma unroll
                for(int j=0;j<4;j++) split_bf(v[j], h[j], l[j]);
                *reinterpret_cast<uint2*>(Ch + off) = *reinterpret_cast<uint2*>(h);
                *reinterpret_cast<uint2*>(Cl + off) = *reinterpret_cast<uint2*>(l);
            }
        }
    }
}

// ------------------------- small kernels -------------------------
__global__ void zero_pad_k(){ g_LN[blockIdx.x*256 + threadIdx.x] = 0.f; }
__global__ void set_cls_k(const float* __restrict__ c){
    int i = blockIdx.x*256 + threadIdx.x; g_X[i] = c[i];
}
__global__ void cls_copy_k(){
    int i = blockIdx.x*256 + threadIdx.x; g_X2[i] = g_X[i];
}

__global__ void ln_k(const float* __restrict__ X, const float* __restrict__ g,
                     const float* __restrict__ b, float* __restrict__ Y)
{
    __shared__ float sh[8];
    int row = blockIdx.x, t = threadIdx.x;
    const float* x = X + (size_t)row*D;
    float2 v = *reinterpret_cast<const float2*>(x + 2*t);
    float mu = blkSum256(v.x+v.y, sh) * (1.f/(float)D);
    float d0 = v.x-mu, d1 = v.y-mu;
    float var = blkSum256(d0*d0 + d1*d1, sh) * (1.f/(float)D);
    float rs = rsqrtf(var + 1e-5f);
    float2 gg = *reinterpret_cast<const float2*>(g + 2*t);
    float2 bb = *reinterpret_cast<const float2*>(b + 2*t);
    float2 o; o.x = d0*rs*gg.x + bb.x; o.y = d1*rs*gg.y + bb.y;
    *reinterpret_cast<float2*>(Y + (size_t)row*D + 2*t) = o;
}

__global__ void landmarks_k(){
    int j = blockIdx.x, h = blockIdx.y, d = threadIdx.x;
    float sq = 0.f, sk = 0.f;
    const float* base = g_QKV + (size_t)(j*40)*H3 + h*64 + d;
#pragma unroll 8
    for(int t=0;t<40;t++){ sq += base[(size_t)t*H3]; sk += base[(size_t)t*H3 + 512]; }
    float qv = sq * (0.125f/40.f), kv = sk * (1.f/40.f);
    int idx = h*ML*DHD + j*DHD + d;
    g_ql [idx] = qv;
    g_klT[h*DHD*ML + d*ML + j] = kv;
    bf16 hh,ll;
    split_bf(qv,hh,ll); g_qlh[idx]=hh; g_qll[idx]=ll;
    split_bf(kv,hh,ll); g_klh[idx]=hh; g_kll[idx]=ll;
}
__global__ void landmarksK_k(){
    int j = blockIdx.x, h = blockIdx.y, d = threadIdx.x;
    float sk = 0.f;
    const float* base = g_QKV + (size_t)(j*40)*H3 + h*64 + d + 512;
#pragma unroll 8
    for(int t=0;t<40;t++) sk += base[(size_t)t*H3];
    float kv = sk * (1.f/40.f);
    g_klT[h*DHD*ML + d*ML + j] = kv;
    bf16 hh,ll; split_bf(kv,hh,ll);
    int idx = h*ML*DHD + j*DHD + d;
    g_klh[idx]=hh; g_kll[idx]=ll;
}
__global__ void meanrows_k(){
    int j = blockIdx.x, c = threadIdx.x;
    const float* base = g_LN + (size_t)j*40*D + c;
    float s0 = 0.f, s1 = 0.f;
#pragma unroll 8
    for(int t=0;t<40;t++){ s0 += base[(size_t)t*D]; s1 += base[(size_t)t*D + 256]; }
    g_LNm[j*D + c] = s0; g_LNm[j*D + c + 256] = s1;
}

__global__ void softmax256_k(float* __restrict__ Xp, long long hs){
    __shared__ float sh[8];
    float* x = Xp + (size_t)blockIdx.y*hs + (size_t)blockIdx.x*ML;
    float v = x[threadIdx.x];
    float mx = blkMax256(v, sh);
    float e = __expf(v-mx);
    float s = blkSum256(e, sh);
    x[threadIdx.x] = e/s;
}

__global__ void stats256_k(const float* __restrict__ Xp, long long hs, int rows){
    __shared__ float sh[8];
    size_t base = (size_t)blockIdx.y*hs + (size_t)blockIdx.x*ML;
    const float* x = Xp + base;
    float v = x[threadIdx.x];
    float mx = blkMax256(v, sh);
    float e = __expf(v-mx);
    float s = blkSum256(e, sh);
    float p = e/s;
    bf16 hh,ll; split_bf(p,hh,ll);
    g_Ph[base + threadIdx.x] = hh;
    g_Pl[base + threadIdx.x] = ll;
    if(!threadIdx.x){
        int g = blockIdx.y*rows + blockIdx.x;
        g_smx[g] = mx; g_sinv[g] = 1.f/s;
    }
}
__global__ void stats_long_k(const float* __restrict__ Xp, long long hs, int rows){
    __shared__ float sh[8];
    size_t base = (size_t)blockIdx.y*hs + (size_t)blockIdx.x*NPAD;
    const float* x = Xp + base;
    float sc[40]; float mx = -3.0e38f;
#pragma unroll
    for(int c=0;c<40;c++){ sc[c] = x[c*256+threadIdx.x]; mx = fmaxf(mx, sc[c]); }
    mx = blkMax256(mx, sh);
    float s = 0.f;
#pragma unroll
    for(int c=0;c<40;c++){ sc[c] = __expf(sc[c]-mx); s += sc[c]; }
    s = blkSum256(s, sh);
    float inv = 1.f/s;
#pragma unroll
    for(int c=0;c<40;c++){
        float p = sc[c]*inv;
        bf16 hh,ll; split_bf(p,hh,ll);
        g_Ph[base + c*256 + threadIdx.x] = hh;
        g_Pl[base + c*256 + threadIdx.x] = ll;
    }
    if(!threadIdx.x){
        int g = blockIdx.y*rows + blockIdx.x;
        g_smx[g] = mx; g_sinv[g] = 1.f/s;
    }
}

__global__ void rowsum_k(){
    __shared__ float sh[8];
    float v = fabsf(g_a2[(size_t)blockIdx.x*ML + threadIdx.x]);
    v = blkSum256(v, sh);
    if(!threadIdx.x) g_rsum[blockIdx.x] = v;
}
__global__ void colsum_k(){
    __shared__ float sm[8][33];
    int h = blockIdx.x, j0 = blockIdx.y*32;
    int c = threadIdx.x & 31, r0 = threadIdx.x >> 5;
    float acc = 0.f;
    for(int r=r0; r<ML; r+=8) acc += fabsf(g_a2[h*ML*ML + r*ML + j0 + c]);
    sm[r0][c] = acc; __syncthreads();
    if(threadIdx.x < 32){
        float s = 0.f;
#pragma unroll
        for(int q=0;q<8;q++) s += sm[q][threadIdx.x];
        g_csum[h*ML + j0 + threadIdx.x] = s;
    }
}
__global__ void maxred_k(){
    __shared__ float sh[8];
    float mr = 0.f, mc = 0.f;
    for(int i=threadIdx.x; i<NH*ML; i+=256){ mr = fmaxf(mr, g_rsum[i]); mc = fmaxf(mc, g_csum[i]); }
    mr = blkMax256(mr, sh);
    mc = blkMax256(mc, sh);
    if(!threadIdx.x) g_invden = 1.f/(mr*mc);
}

__global__ void zt_k(){
    __shared__ float t[32][33];
    int h = blockIdx.z, i0 = blockIdx.x*32, j0 = blockIdx.y*32;
    int tx = threadIdx.x & 31, ty = threadIdx.x >> 5;
    float inv = g_invden;
#pragma unroll
    for(int rr=0; rr<32; rr+=8)
        t[ty+rr][tx] = g_a2[h*ML*ML + (i0+ty+rr)*ML + j0+tx];
    __syncthreads();
#pragma unroll
    for(int rr=0; rr<32; rr+=8)
        g_Za[(size_t)h*ML*ML + (j0+ty+rr)*ML + i0+tx] = t[tx][ty+rr]*inv;
}

__global__ void reduce_tt_k(){
    int i = blockIdx.x*256 + threadIdx.x;
    int b = i >> 14, r = i & 16383;
    float s = 0.f;
#pragma unroll
    for(int t=0;t<NSPL;t++) s += g_ttp[((size_t)b*NSPL + t)*16384 + r];
    g_tt[(size_t)b*16384 + r] = s;
}

__global__ __launch_bounds__(256)
void conv_res_k(const float* __restrict__ w){
    __shared__ float sv[96][64];
    __shared__ float swt[33];
    int s0 = blockIdx.x*64, c0 = blockIdx.y*64, h = blockIdx.y;
    int tid = threadIdx.x;
    for(int idx=tid; idx<96*64; idx+=256){
        int r = idx >> 6, c = idx & 63;
        int sp = s0 - 16 + r;
        sv[r][c] = ((unsigned)sp < (unsigned)NPAD) ? g_QKV[(size_t)sp*H3 + 1024 + c0 + c] : 0.f;
    }
    if(tid < 33) swt[tid] = w[h*33 + tid];
    __syncthreads();
    int c = tid & 63, sg = tid >> 6;
    int sb2 = sg*16;
    float acc[16];
#pragma unroll
    for(int s=0;s<16;s++) acc[s] = 0.f;
    for(int r=0;r<48;r++){
        float v = sv[sb2 + r][c];
#pragma unroll
        for(int s=0;s<16;s++){
            int k = r - s;
            if(k >= 0 && k < 33) acc[s] += swt[k]*v;
        }
    }
#pragma unroll
    for(int s=0;s<16;s++) g_O[(size_t)(s0+sb2+s)*D + c0 + c] = acc[s];
}

__global__ __launch_bounds__(256)
void ppeg_k(const float* __restrict__ w7, const float* __restrict__ b7,
            const float* __restrict__ w5, const float* __restrict__ b5,
            const float* __restrict__ w3, const float* __restrict__ b3)
{
    __shared__ float st[14][14][32];
    __shared__ float sw[83][32];
    __shared__ float sb[32];
    int cg = blockIdx.z*32;
    int ti0 = blockIdx.y*8, tj0 = blockIdx.x*8;
    int tid = threadIdx.x;
    for(int idx=tid; idx<14*14*32; idx+=256){
        int r = idx/(14*32); int rem = idx - r*14*32; int col = rem>>5; int cc = rem&31;
        int gi = ti0-3+r, gj = tj0-3+col;
        float v = 0.f;
        if((unsigned)gi < 100u && (unsigned)gj < 100u)
            v = g_X[(size_t)(1 + gi*100 + gj)*D + cg + cc];
        st[r][col][cc] = v;
    }
    for(int idx=tid; idx<83*32; idx+=256){
        int t = idx>>5, cc = idx&31; int ch = cg+cc; float w;
        if(t<49) w = w7[ch*49 + t];
        else if(t<74) w = w5[ch*25 + t-49];
        else w = w3[ch*9 + t-74];
        sw[t][cc] = w;
    }
    if(tid < 32) sb[tid] = b7[cg+tid] + b5[cg+tid] + b3[cg+tid];
    __syncthreads();
    int c = tid & 31, i = tid >> 5;
    float acc[8];
#pragma unroll
    for(int j=0;j<8;j++) acc[j] = st[3+i][3+j][c] + sb[c];
#pragma unroll
    for(int di=-3; di<=3; di++){
        float rv[14];
#pragma unroll
        for(int q=0;q<14;q++) rv[q] = st[3+i+di][q][c];
#pragma unroll
        for(int dj=0;dj<7;dj++){
            float w = sw[(di+3)*7+dj][c];
#pragma unroll
            for(int j=0;j<8;j++) acc[j] += w*rv[j+dj];
        }
        if(di>=-2 && di<=2){
#pragma unroll
            for(int dj=0;dj<5;dj++){
                float w = sw[49+(di+2)*5+dj][c];
#pragma unroll
                for(int j=0;j<8;j++) acc[j] += w*rv[j+dj+1];
            }
        }
        if(di>=-1 && di<=1){
#pragma unroll
            for(int dj=0;dj<3;dj++){
                float w = sw[74+(di+1)*3+dj][c];
#pragma unroll
                for(int j=0;j<8;j++) acc[j] += w*rv[j+dj+2];
            }
        }
    }
    int gi = ti0+i;
    if(gi < 100){
#pragma unroll
        for(int j=0;j<8;j++){
            int gj = tj0+j;
            if(gj < 100) g_X2[(size_t)(1 + gi*100 + gj)*D + cg + c] = acc[j];
        }
    }
}

__global__ void l2row_k(const float* __restrict__ rw, const float* __restrict__ qw){
    __shared__ float q[64];
    __shared__ float p[256];
    __shared__ float sh[8];
    int h = blockIdx.x, j = threadIdx.x;
    if(j < 64){
        const float* x = g_LN + (size_t)PADN*D;
        const float* w = qw + h*64 + j;
        float a = 0.f;
        for(int c=0;c<512;c++) a += x[c]*w[(size_t)c*H3];
        q[j] = a;
    }
    __syncthreads();
    float s = 0.f;
#pragma unroll
    for(int d=0; d<64; d++) s += q[d]*g_klT[h*DHD*ML + d*ML + j];
    s *= 0.125f;
    float mx = blkMax256(s, sh);
    float e = __expf(s - mx);
    float sum = blkSum256(e, sh);
    p[j] = e/sum;
    __syncthreads();
    if(j < 64){
        float acc = 0.f;
        for(int t=0;t<256;t++) acc += p[t]*g_uu[h*ML*DHD + t*64 + j];
#pragma unroll
        for(int t=0;t<33;t++)
            acc += rw[h*33+t] * g_QKV[(size_t)(PADN-16+t)*H3 + 1024 + h*64 + j];
        g_orow[h*64 + j] = acc;
    }
}

__global__ void final_head_k(const float* __restrict__ ow, const float* __restrict__ ob,
                             const float* __restrict__ ng, const float* __restrict__ nb,
                             const float* __restrict__ fw, const float* __restrict__ fb,
                             float* __restrict__ out)
{
    __shared__ float o[512];
    __shared__ float f[512];
    __shared__ float sh[8];
    int t = threadIdx.x;
    o[t] = g_orow[t]; o[t+256] = g_orow[t+256];
    __syncthreads();
#pragma unroll
    for(int half=0; half<2; half++){
        int n = t + half*256;
        float v = ob[n] + g_LN[(size_t)PADN*D + n];
        for(int c=0;c<512;c++) v += o[c]*ow[(size_t)c*D + n];
        f[n] = v;
    }
    __syncthreads();
    float v0 = f[t], v1 = f[t+256];
    float mu = blkSum256(v0+v1, sh)*(1.f/512.f);
    float d0 = v0-mu, d1 = v1-mu;
    float var = blkSum256(d0*d0+d1*d1, sh)*(1.f/512.f);
    float rs = rsqrtf(var + 1e-5f);
    float l0 = d0*rs*ng[t]     + nb[t];
    float l1 = d1*rs*ng[t+256] + nb[t+256];
    float s0 = l0*fw[t*2]   + l1*fw[(t+256)*2];
    float s1 = l0*fw[t*2+1] + l1*fw[(t+256)*2+1];
    s0 = blkSum256(s0, sh);
    s1 = blkSum256(s1, sh);
    if(!t){ out[0] = s0 + fb[0]; out[1] = s1 + fb[1]; }
}

// ------------------------- host -------------------------
#define SYMADDR(T, p, s) do{ void* _t; cudaGetSymbolAddress(&_t, s); p = (T*)_t; }while(0)

extern "C" void kernel_launch(void* const* d_in, const int* in_sizes, int n_in,
                              void* d_out, int out_size)
{
    bool sig = (in_sizes[10] == 25088);
    const float* h_in = (const float*)d_in[0];
    const float* fc1w = (const float*)d_in[1];
    const float* fc1b = (const float*)d_in[2];
    const float* cls  = (const float*)d_in[3];
    const float* g1 = (const float*)d_in[4];
    const float* b1 = (const float*)d_in[5];
    const float* qkv1 = (const float*)d_in[6];
    const float* ow1 = (const float*)d_in[7];
    const float* ob1 = (const float*)d_in[8];
    const float* rw1 = (const float*)d_in[9];
    const float *w7,*b7,*w5,*b5,*w3,*b3,*g2,*b2,*qkv2,*ow2,*ob2,*rw2,*ng,*nb,*f2w,*f2b;
    if(sig){
        w7=(const float*)d_in[10]; b7=(const float*)d_in[11];
        w5=(const float*)d_in[12]; b5=(const float*)d_in[13];
        w3=(const float*)d_in[14]; b3=(const float*)d_in[15];
        g2=(const float*)d_in[16]; b2=(const float*)d_in[17];
        qkv2=(const float*)d_in[18]; ow2=(const float*)d_in[19];
        ob2=(const float*)d_in[20]; rw2=(const float*)d_in[21];
    } else {
        g2=(const float*)d_in[10]; b2=(const float*)d_in[11];
        qkv2=(const float*)d_in[12]; ow2=(const float*)d_in[13];
        ob2=(const float*)d_in[14]; rw2=(const float*)d_in[15];
        w7=(const float*)d_in[16]; b7=(const float*)d_in[17];
        w5=(const float*)d_in[18]; b5=(const float*)d_in[19];
        w3=(const float*)d_in[20]; b3=(const float*)d_in[21];
    }
    ng=(const float*)d_in[22]; nb=(const float*)d_in[23];
    f2w=(const float*)d_in[24]; f2b=(const float*)d_in[25];

    float *X,*X2,*LN,*LNm,*QKV,*klT,*ql,*a1,*a3,*a2,*Za,*Zb,*XZ,*M2p,*M4p,*ttp,*tt,*uu,*Ob,*smx,*sinv;
    bf16 *Ah,*Al,*Wth,*Wtl,*KVh,*KVl,*qlh,*qll,*klh,*kll,*Ph,*Pl,*uuh,*uul;
    SYMADDR(float,X,g_X); SYMADDR(float,X2,g_X2); SYMADDR(float,LN,g_LN); SYMADDR(float,LNm,g_LNm);
    SYMADDR(float,QKV,g_QKV); SYMADDR(float,klT,g_klT); SYMADDR(float,ql,g_ql);
    SYMADDR(float,a1,g_a1); SYMADDR(float,a3,g_a3); SYMADDR(float,a2,g_a2);
    SYMADDR(float,Za,g_Za); SYMADDR(float,Zb,g_Zb); SYMADDR(float,XZ,g_XZ);
    SYMADDR(float,M2p,g_M2); SYMADDR(float,M4p,g_M4); SYMADDR(float,ttp,g_ttp);
    SYMADDR(float,tt,g_tt); SYMADDR(float,uu,g_uu); SYMADDR(float,Ob,g_O);
    SYMADDR(float,smx,g_smx); SYMADDR(float,sinv,g_sinv);
    SYMADDR(bf16,Ah,g_Ah); SYMADDR(bf16,Al,g_Al); SYMADDR(bf16,Wth,g_Wth); SYMADDR(bf16,Wtl,g_Wtl);
    SYMADDR(bf16,KVh,g_KVh); SYMADDR(bf16,KVl,g_KVl);
    SYMADDR(bf16,qlh,g_qlh); SYMADDR(bf16,qll,g_qll);
    SYMADDR(bf16,klh,g_klh); SYMADDR(bf16,kll,g_kll);
    SYMADDR(bf16,Ph,g_Ph); SYMADDR(bf16,Pl,g_Pl);
    SYMADDR(bf16,uuh,g_uuh); SYMADDR(bf16,uul,g_uul);

    static cudaStream_t s1 = nullptr, s2 = nullptr;
    static cudaEvent_t ev[8];
    if(!s1){
        cudaStreamCreateWithFlags(&s1, cudaStreamNonBlocking);
        cudaStreamCreateWithFlags(&s2, cudaStreamNonBlocking);
        for(int i=0;i<8;i++) cudaEventCreateWithFlags(&ev[i], cudaEventDisableTiming);
        cudaFuncSetAttribute(gemm_mma_k, cudaFuncAttributeMaxDynamicSharedMemorySize, SM_MMA);
        cudaFuncSetAttribute(gemm_mma_b_k, cudaFuncAttributeMaxDynamicSharedMemorySize, SM_MMA);
        cudaFuncSetAttribute(gemm_mma_n64t_k, cudaFuncAttributeMaxDynamicSharedMemorySize, SM_N64);
    }
    cudaEvent_t evX = ev[6], evW = ev[7];

    zero_pad_k<<<PADN*D/256, 256>>>();
    cvt_rows_k<<<10000*1024/1024, 256>>>(h_in, Ah, Al);
    cvt_T_k<<<dim3(32,16),256>>>(fc1w, Wth, Wtl, 1024, 512);
    gemm_mma_k<<<dim3(4,79),256,SM_MMA>>>(Ah, Al, Wth, Wtl, fc1b, nullptr, X+D,
                                          10000, 512, 1024, D, 1, 0, 1, nullptr, nullptr);
    set_cls_k<<<2,256>>>(cls);

    long long sM = (long long)ML*ML;
    for(int layer=0; layer<2; layer++){
        const float* xin = layer ? X2 : X;
        const float* gg = layer ? g2 : g1;
        const float* bb = layer ? b2 : b1;
        const float* qw = layer ? qkv2 : qkv1;
        cudaEvent_t evF = ev[layer*3+0], evA = ev[layer*3+1], evB = ev[layer*3+2];

        ln_k<<<NSEQ,256>>>(xin, gg, bb, LN + (size_t)PADN*D);
        cvt_rows_k<<<NPAD*512/1024, 256>>>(LN, Ah, Al);

        const float* Aq; int ldaQ; long long sAQ;
        const bf16 *AqH, *AqL; int ldaQb; long long sAQb;
        if(layer == 0){
            cvt_T_k<<<dim3(16,48),256>>>(qw, Wth, Wtl, 512, 1536);
            gemm_mma_k<<<dim3(12,80),256,SM_MMA>>>(Ah, Al, Wth, Wtl, nullptr, nullptr, QKV,
                                                   NPAD, 1536, 512, H3, 0, 0, 0, KVh, KVl);
            landmarks_k<<<dim3(ML,NH),64>>>();
            Aq = ql; ldaQ = DHD; sAQ = (long long)ML*DHD;
            AqH = qlh; AqL = qll; ldaQb = DHD; sAQb = (long long)ML*DHD;
        } else {
            cvt_T_k<<<dim3(16,32),256>>>(qw+512, Wth, Wtl, 512, 1536);
            gemm_mma_k<<<dim3(8,80),256,SM_MMA>>>(Ah, Al, Wth, Wtl, nullptr, nullptr, QKV+512,
                                                  NPAD, 1024, 512, H3, 0, 0, 0, KVh+512, KVl+512);
            meanrows_k<<<ML,256>>>();
            gemm64_k<<<dim3(8,4,1),128>>>(LNm, qw, ql, ML, 512, 512, 512, H3, 512,
                        0,0,0, 0.125f/40.f, 0.f, nullptr, 0.f, 1, 512, 0, qlh, qll);
            landmarksK_k<<<dim3(ML,NH),64>>>();
            Aq = ql; ldaQ = 512; sAQ = 64;
            AqH = qlh; AqL = qll; ldaQb = 512; sAQb = 64;
        }

        // a2 = softmax(ql @ kl^T)
        gemm64_k<<<dim3(4,4,NH),128>>>(Aq, klT, a2, ML,ML,DHD, ldaQ,ML,ML,
                    sAQ,(long long)DHD*ML,sM, 1.f,0.f, nullptr,0.f, 1,DHD,0, nullptr,nullptr);
        softmax256_k<<<dim3(ML,NH),256>>>(a2, sM);

        // ---- fork: pinv chain on s1 (W sidecar on s2), conv on s2 first (layer 0) ----
        cudaEventRecord(evF, 0);
        cudaStreamWaitEvent(s1, evF, 0);
        if(layer == 0){
            cudaStreamWaitEvent(s2, evF, 0);
            conv_res_k<<<dim3(NPAD/64, NH),256,0,s2>>>(rw1);
            cudaEventRecord(evB, s2);
        } else {
            cudaStreamWaitEvent(s2, evF, 0);
        }
        rowsum_k<<<NH*ML,256,0,s1>>>();
        colsum_k<<<dim3(NH,8),256,0,s1>>>();
        maxred_k<<<1,256,0,s1>>>();
        zt_k<<<dim3(8,8,NH),256,0,s1>>>();
        float* za = Za; float* zb = Zb;
        for(int it=0; it<6; it++){
            // XZ = a2 @ z
            gemm64_k<<<dim3(4,4,NH),128,0,s1>>>(a2, za, XZ, ML,ML,ML, ML,ML,ML, sM,sM,sM,
                        1.f,0.f, nullptr,0.f, 1,ML,0, nullptr,nullptr);
            cudaEventRecord(evX, s1);
            cudaStreamWaitEvent(s2, evX, 0);
            // W = z @ XZ   (on s2, concurrent with M2)
            gemm64_k<<<dim3(4,4,NH),128,0,s2>>>(za, XZ, M4p, ML,ML,ML, ML,ML,ML, sM,sM,sM,
                        1.f,0.f, nullptr,0.f, 1,ML,0, nullptr,nullptr);
            cudaEventRecord(evW, s2);
            // M2 = -XZ@XZ + 7*XZ - 15I   (on s1)
            gemm64_k<<<dim3(4,4,NH),128,0,s1>>>(XZ, XZ, M2p, ML,ML,ML, ML,ML,ML, sM,sM,sM,
                        -1.f,-15.f, XZ,7.f, 1,ML,0, nullptr,nullptr);
            cudaStreamWaitEvent(s1, evW, 0);
            // z' = 0.25*W@M2 + 3.25*z
            gemm64_k<<<dim3(4,4,NH),128,0,s1>>>(M4p, M2p, zb, ML,ML,ML, ML,ML,ML, sM,sM,sM,
                        0.25f,0.f, za,3.25f, 1,ML,0, nullptr,nullptr);
            float* tmp = za; za = zb; zb = tmp;
        }
        cudaEventRecord(evA, s1);

        // ---- main stream: a3 (MMA) -> stats+P3 -> tt (MMA, split-K) ----
        gemm_mma_b_k<<<dim3(NPAD/128, ML/128, NH),256,SM_MMA>>>(AqH, AqL, KVh+512, KVl+512,
                    a3, NPAD, DHD, ldaQb, H3, NPAD, sAQb, 64LL, (long long)ML*NPAD, 1.f);
        stats_long_k<<<dim3(ML,NH),256>>>(a3, (long long)ML*NPAD, ML);
        gemm_mma_n64t_k<<<dim3(NSPL, ML/128, NH),256,SM_N64>>>(Ph, Pl, KVh+1024, KVl+1024,
                    ttp, NPAD, H3, DHD, (long long)ML*NPAD, 64LL, (long long)NSPL*ML*DHD,
                    nullptr, 0.f, KCH, (long long)ML*DHD);
        reduce_tt_k<<<NH*ML*DHD/256,256>>>();
        if(layer == 0){
            gemm_mma_b_k<<<dim3(ML/128, NPAD/128, NH),256,SM_MMA>>>(KVh, KVl, klh, kll,
                    a1, ML, DHD, H3, DHD, ML, 64LL, (long long)ML*DHD, (long long)NPAD*ML, 0.125f);
            stats256_k<<<dim3(NPAD,NH),256>>>(a1, (long long)NPAD*ML, NPAD);
        }

        // ---- join pinv, compute uu (+bf16 split) ----
        cudaStreamWaitEvent(0, evA, 0);
        gemm64_k<<<dim3(1,4,NH),128>>>(za, tt, uu, ML,DHD,ML, ML,DHD,DHD,
                    sM,(long long)ML*DHD,(long long)ML*DHD, 1.f,0.f, nullptr,0.f, 1,ML,0,
                    uuh, uul);

        if(layer == 0){
            cudaStreamWaitEvent(0, evB, 0);
            gemm_mma_n64t_k<<<dim3(1, NPAD/128, NH),256,SM_N64>>>(Ph, Pl, uuh, uul,
                    Ob, ML, DHD, D, (long long)NPAD*ML, (long long)ML*DHD, 64LL,
                    Ob, 1.f, ML, 0);
            cvt_rows_k<<<NPAD*512/1024, 256>>>(Ob, Ah, Al);
            cvt_T_k<<<dim3(16,16),256>>>(ow1, Wth, Wtl, 512, 512);
            gemm_mma_k<<<dim3(4,79),256,SM_MMA>>>(Ah + (size_t)PADN*D, Al + (size_t)PADN*D,
                                                  Wth, Wtl, ob1, LN + (size_t)PADN*D, X,
                                                  NSEQ, 512, 512, D, 1, 1, 0, nullptr, nullptr);
            ppeg_k<<<dim3(13,13,16),256>>>(w7,b7,w5,b5,w3,b3);
            cls_copy_k<<<2,256>>>();
        } else {
            l2row_k<<<NH,256>>>(rw2, qw);
            final_head_k<<<1,256>>>(ow2, ob2, ng, nb, f2w, f2b, (float*)d_out);
        }
    }
}

// round 17
// speedup vs baseline: 1.1157x; 1.0591x over previous
#include <cuda_runtime.h>
#include <cuda_bf16.h>
#include <math.h>
#include <stdint.h>

#define D    512
#define H3   1536
#define NH   8
#define DHD  64
#define NSEQ 10001
#define NPAD 10240
#define PADN 239
#define ML   256
#define NSPL 8
#define KCH  (NPAD/NSPL)

typedef __nv_bfloat16 bf16;

// ------------------------- scratch (device globals) -------------------------
__device__ float g_X  [NSEQ*D];
__device__ float g_X2 [NSEQ*D];
__device__ float g_LN [NPAD*D];
__device__ float g_LNm[ML*D];
__device__ float g_QKV[(size_t)NPAD*H3];
__device__ float g_klT[NH*DHD*ML];
__device__ float g_ql [NH*ML*DHD];
__device__ float g_a1 [(size_t)NH*NPAD*ML];
__device__ float g_a3 [(size_t)NH*ML*NPAD];
__device__ float g_a2 [NH*ML*ML];
__device__ float g_Za [NH*ML*ML];
__device__ float g_Zb [NH*ML*ML];
__device__ float g_XZ [NH*ML*ML];
__device__ float g_M2 [NH*ML*ML];
__device__ float g_M4 [NH*ML*ML];
__device__ float g_ttp[(size_t)NH*NSPL*ML*DHD];
__device__ float g_tt [NH*ML*DHD];
__device__ float g_uu [NH*ML*DHD];
__device__ float g_O  [(size_t)NPAD*D];
__device__ float g_smx [NH*NPAD];
__device__ float g_sinv[NH*NPAD];
__device__ float g_orow[D];
__device__ float g_rsum[NH*ML];
__device__ float g_csum[NH*ML];
__device__ float g_invden;
// bf16 hi/lo operand buffers
__device__ bf16 g_Ah[(size_t)NPAD*1024];
__device__ bf16 g_Al[(size_t)NPAD*1024];
__device__ bf16 g_Wth[1536*512];
__device__ bf16 g_Wtl[1536*512];
__device__ bf16 g_KVh[(size_t)NPAD*H3];
__device__ bf16 g_KVl[(size_t)NPAD*H3];
__device__ bf16 g_qlh[NH*ML*DHD];
__device__ bf16 g_qll[NH*ML*DHD];
__device__ bf16 g_klh[NH*ML*DHD];
__device__ bf16 g_kll[NH*ML*DHD];
__device__ bf16 g_Ph [(size_t)NH*NPAD*ML];
__device__ bf16 g_Pl [(size_t)NH*NPAD*ML];
__device__ bf16 g_uuh[NH*ML*DHD];
__device__ bf16 g_uul[NH*ML*DHD];

// ------------------------- f32x2 helpers -------------------------
typedef unsigned long long ull;
__device__ __forceinline__ void fma2(ull& d, ull a, ull b){
    asm("fma.rn.f32x2 %0, %1, %2, %0;" : "+l"(d) : "l"(a), "l"(b));
}
__device__ __forceinline__ ull dup2(float b){
    ull r; asm("mov.b64 %0, {%1, %1};" : "=l"(r) : "f"(b)); return r;
}
__device__ __forceinline__ float lof(ull v){ return __uint_as_float((unsigned)v); }
__device__ __forceinline__ float hif(ull v){ return __uint_as_float((unsigned)(v>>32)); }

__device__ __forceinline__ uint32_t s2u(const void* p){
    uint32_t a;
    asm("{ .reg .u64 t; cvta.to.shared.u64 t, %1; cvt.u32.u64 %0, t; }" : "=r"(a) : "l"(p));
    return a;
}
#define LDSM4(r0,r1,r2,r3,addr) \
    asm volatile("ldmatrix.sync.aligned.m8n8.x4.shared.b16 {%0,%1,%2,%3}, [%4];" \
        : "=r"(r0),"=r"(r1),"=r"(r2),"=r"(r3) : "r"(addr))
#define LDSM4T(r0,r1,r2,r3,addr) \
    asm volatile("ldmatrix.sync.aligned.m8n8.x4.trans.shared.b16 {%0,%1,%2,%3}, [%4];" \
        : "=r"(r0),"=r"(r1),"=r"(r2),"=r"(r3) : "r"(addr))
#define MMA16816(d, a, b) \
    asm volatile("mma.sync.aligned.m16n8k16.row.col.f32.bf16.bf16.f32 " \
        "{%0,%1,%2,%3},{%4,%5,%6,%7},{%8,%9},{%0,%1,%2,%3};" \
        : "+f"((d)[0]),"+f"((d)[1]),"+f"((d)[2]),"+f"((d)[3]) \
        : "r"((a)[0]),"r"((a)[1]),"r"((a)[2]),"r"((a)[3]), "r"((b)[0]),"r"((b)[1]))
#define CPA(dst, src, sz) \
    asm volatile("cp.async.ca.shared.global [%0], [%1], 16, %2;" \
        :: "r"(dst), "l"(src), "r"(sz) : "memory")
#define CPA_COMMIT() asm volatile("cp.async.commit_group;" ::: "memory")
#define CPA_WAIT0()  asm volatile("cp.async.wait_group 0;" ::: "memory")

// ------------------------- block reductions (256 thr) -------------------------
__device__ __forceinline__ float blkSum256(float v, float* sh){
#pragma unroll
    for(int o=16;o;o>>=1) v += __shfl_xor_sync(0xffffffffu, v, o);
    __syncthreads();
    if((threadIdx.x&31)==0) sh[threadIdx.x>>5]=v;
    __syncthreads();
    float r = sh[0];
#pragma unroll
    for(int i=1;i<8;i++) r += sh[i];
    return r;
}
__device__ __forceinline__ float blkMax256(float v, float* sh){
#pragma unroll
    for(int o=16;o;o>>=1) v = fmaxf(v, __shfl_xor_sync(0xffffffffu, v, o));
    __syncthreads();
    if((threadIdx.x&31)==0) sh[threadIdx.x>>5]=v;
    __syncthreads();
    float r = sh[0];
#pragma unroll
    for(int i=1;i<8;i++) r = fmaxf(r, sh[i]);
    return r;
}

// ------------------------- bf16 hi/lo converters -------------------------
__device__ __forceinline__ void split_bf(float a, bf16& h, bf16& l){
    h = __float2bfloat16_rn(a);
    l = __float2bfloat16_rn(a - __bfloat162float(h));
}
__global__ void cvt_rows_k(const float* __restrict__ s, bf16* __restrict__ dh,
                           bf16* __restrict__ dl){
    size_t i = ((size_t)blockIdx.x*256 + threadIdx.x)*4;
    float4 v = *reinterpret_cast<const float4*>(s+i);
    bf16 h[4], l[4];
    split_bf(v.x,h[0],l[0]); split_bf(v.y,h[1],l[1]);
    split_bf(v.z,h[2],l[2]); split_bf(v.w,h[3],l[3]);
    *reinterpret_cast<uint2*>(dh+i) = *reinterpret_cast<uint2*>(h);
    *reinterpret_cast<uint2*>(dl+i) = *reinterpret_cast<uint2*>(l);
}
__global__ void cvt_T_k(const float* __restrict__ W, bf16* __restrict__ dh,
                        bf16* __restrict__ dl, int Kd, int Nd){
    __shared__ float sm[32][33];
    int k0 = blockIdx.x*32, n0 = blockIdx.y*32;
    int c = threadIdx.x & 31, r = threadIdx.x >> 5;
#pragma unroll
    for(int p=0;p<4;p++)
        sm[p*8+r][c] = W[(size_t)(k0+p*8+r)*Nd + n0 + c];
    __syncthreads();
#pragma unroll
    for(int p=0;p<4;p++){
        int nn = p*8 + r;
        float v = sm[c][nn];
        bf16 h,l; split_bf(v,h,l);
        dh[(size_t)(n0+nn)*Kd + k0 + c] = h;
        dl[(size_t)(n0+nn)*Kd + k0 + c] = l;
    }
}

// ---------- bf16x3 tensor-core GEMM, 2-stage cp.async pipeline (2 CTA/SM) ----------
#define MS  (128*40)
#define SM_MMA (2*4*MS*2)
__global__ __launch_bounds__(256,2)
void gemm_mma_k(const bf16* __restrict__ Ahp, const bf16* __restrict__ Alp,
                const bf16* __restrict__ Bhp, const bf16* __restrict__ Blp,
                const float* __restrict__ bias, const float* __restrict__ R,
                float* __restrict__ C, int M, int N, int K, int ldc,
                int DOBIAS, int DORES, int DORELU,
                bf16* __restrict__ Chp, bf16* __restrict__ Clp)
{
    extern __shared__ bf16 smp[];
    int tid = threadIdx.x, lane = tid & 31, wid = tid >> 5;
    int wm = wid >> 2, wn = wid & 3;
    int bm = blockIdx.y * 128, bn = blockIdx.x * 128;
    uint32_t sbase = s2u(smp);
    float acc[4][4][4];
#pragma unroll
    for(int i=0;i<4;i++)
#pragma unroll
        for(int j=0;j<4;j++)
#pragma unroll
            for(int q=0;q<4;q++) acc[i][j][q]=0.f;

    int lr = tid >> 1, ls = (tid & 1) * 16;
    int aok = (bm + lr < M) ? 16 : 0;
    const bf16* gAh = Ahp + (size_t)(bm+lr)*K + ls;
    const bf16* gAl = Alp + (size_t)(bm+lr)*K + ls;
    const bf16* gBh = Bhp + (size_t)(bn+lr)*K + ls;
    const bf16* gBl = Blp + (size_t)(bn+lr)*K + ls;
    uint32_t dOff = (uint32_t)((lr*40 + ls)*2);

    int aRow = wm*64 + (lane&7) + ((lane>>3)&1)*8;
    int aCol = (lane>>4)*8;
    int bRow = wn*32 + (lane&7) + (lane>>4)*8;
    int bCol = ((lane>>3)&1)*8;

    int nch = K >> 5;
#define PREF(ch, st) do{ \
    uint32_t db = sbase + (uint32_t)(st)*(4*MS*2) + dOff; \
    size_t go = (size_t)(ch)*32; \
    CPA(db,          gAh+go, aok); CPA(db+16,          gAh+go+8, aok); \
    CPA(db+MS*2,     gAl+go, aok); CPA(db+MS*2+16,     gAl+go+8, aok); \
    CPA(db+MS*4,     gBh+go, 16);  CPA(db+MS*4+16,     gBh+go+8, 16); \
    CPA(db+MS*6,     gBl+go, 16);  CPA(db+MS*6+16,     gBl+go+8, 16); \
    CPA_COMMIT(); }while(0)

    PREF(0, 0);

    for(int ch=0; ch<nch; ch++){
        CPA_WAIT0();
        __syncthreads();
        if(ch+1 < nch) PREF(ch+1, (ch+1)&1);
        uint32_t stb = sbase + (uint32_t)(ch&1)*(4*MS*2);
        uint32_t bAh = stb, bAl = stb + MS*2, bBh = stb + MS*4, bBl = stb + MS*6;
#pragma unroll
        for(int ks=0; ks<2; ks++){
            int kc = ks*16;
            uint32_t bh[4][2], bl[4][2];
#pragma unroll
            for(int ntp=0; ntp<2; ntp++){
                uint32_t off = (uint32_t)(((bRow + ntp*16)*40 + kc + bCol)*2);
                LDSM4(bh[2*ntp][0], bh[2*ntp][1], bh[2*ntp+1][0], bh[2*ntp+1][1], bBh + off);
                LDSM4(bl[2*ntp][0], bl[2*ntp][1], bl[2*ntp+1][0], bl[2*ntp+1][1], bBl + off);
            }
#pragma unroll
            for(int mt=0; mt<4; mt++){
                uint32_t off = (uint32_t)(((aRow + mt*16)*40 + kc + aCol)*2);
                uint32_t ah[4], al[4];
                LDSM4(ah[0],ah[1],ah[2],ah[3], bAh + off);
                LDSM4(al[0],al[1],al[2],al[3], bAl + off);
#pragma unroll
                for(int nt=0; nt<4; nt++){
                    MMA16816(acc[mt][nt], ah, bh[nt]);
                    MMA16816(acc[mt][nt], ah, bl[nt]);
                    MMA16816(acc[mt][nt], al, bh[nt]);
                }
            }
        }
    }
#undef PREF
#pragma unroll
    for(int mt=0; mt<4; mt++){
#pragma unroll
        for(int nt=0; nt<4; nt++){
            int n = bn + wn*32 + nt*8 + (lane&3)*2;
#pragma unroll
            for(int h=0; h<2; h++){
                int m = bm + wm*64 + mt*16 + (lane>>2) + h*8;
                if(m < M){
                    float v0 = acc[mt][nt][h*2], v1 = acc[mt][nt][h*2+1];
                    if(DOBIAS){ v0 += bias[n]; v1 += bias[n+1]; }
                    if(DORES){
                        const float* rp = R + (size_t)m*ldc + n;
                        v0 += rp[0]; v1 += rp[1];
                    }
                    if(DORELU){ v0 = fmaxf(v0,0.f); v1 = fmaxf(v1,0.f); }
                    float2 o; o.x = v0; o.y = v1;
                    *reinterpret_cast<float2*>(C + (size_t)m*ldc + n) = o;
                    if(Chp){
                        bf16 hh[2], ll[2];
                        split_bf(v0, hh[0], ll[0]);
                        split_bf(v1, hh[1], ll[1]);
                        *reinterpret_cast<uint32_t*>(Chp + (size_t)m*ldc + n) = *reinterpret_cast<uint32_t*>(hh);
                        *reinterpret_cast<uint32_t*>(Clp + (size_t)m*ldc + n) = *reinterpret_cast<uint32_t*>(ll);
                    }
                }
            }
        }
    }
}

// ---------- batched/strided bf16x3 MMA GEMM: C = scale*(A@B), B [N][K] rows ----------
__global__ __launch_bounds__(256,2)
void gemm_mma_b_k(const bf16* __restrict__ Ahp, const bf16* __restrict__ Alp,
                  const bf16* __restrict__ Bhp, const bf16* __restrict__ Blp,
                  float* __restrict__ C, int N, int K,
                  int lda, int ldb, int ldc,
                  long long sA, long long sB, long long sC, float scale)
{
    extern __shared__ bf16 smp[];
    int tid = threadIdx.x, lane = tid & 31, wid = tid >> 5;
    int wm = wid >> 2, wn = wid & 3;
    int bm = blockIdx.y * 128, bn = blockIdx.x * 128;
    int z = blockIdx.z;
    uint32_t sbase = s2u(smp);
    float acc[4][4][4];
#pragma unroll
    for(int i=0;i<4;i++)
#pragma unroll
        for(int j=0;j<4;j++)
#pragma unroll
            for(int q=0;q<4;q++) acc[i][j][q]=0.f;

    int lr = tid >> 1, ls = (tid & 1) * 16;
    const bf16* gAh = Ahp + (size_t)z*sA + (size_t)(bm+lr)*lda + ls;
    const bf16* gAl = Alp + (size_t)z*sA + (size_t)(bm+lr)*lda + ls;
    const bf16* gBh = Bhp + (size_t)z*sB + (size_t)(bn+lr)*ldb + ls;
    const bf16* gBl = Blp + (size_t)z*sB + (size_t)(bn+lr)*ldb + ls;
    uint32_t dOff = (uint32_t)((lr*40 + ls)*2);

    int aRow = wm*64 + (lane&7) + ((lane>>3)&1)*8;
    int aCol = (lane>>4)*8;
    int bRow = wn*32 + (lane&7) + (lane>>4)*8;
    int bCol = ((lane>>3)&1)*8;

    int nch = K >> 5;
#define PREF(ch, st) do{ \
    uint32_t db = sbase + (uint32_t)(st)*(4*MS*2) + dOff; \
    size_t go = (size_t)(ch)*32; \
    CPA(db,          gAh+go, 16); CPA(db+16,          gAh+go+8, 16); \
    CPA(db+MS*2,     gAl+go, 16); CPA(db+MS*2+16,     gAl+go+8, 16); \
    CPA(db+MS*4,     gBh+go, 16); CPA(db+MS*4+16,     gBh+go+8, 16); \
    CPA(db+MS*6,     gBl+go, 16); CPA(db+MS*6+16,     gBl+go+8, 16); \
    CPA_COMMIT(); }while(0)

    PREF(0, 0);

    for(int ch=0; ch<nch; ch++){
        CPA_WAIT0();
        __syncthreads();
        if(ch+1 < nch) PREF(ch+1, (ch+1)&1);
        uint32_t stb = sbase + (uint32_t)(ch&1)*(4*MS*2);
        uint32_t bAh = stb, bAl = stb + MS*2, bBh = stb + MS*4, bBl = stb + MS*6;
#pragma unroll
        for(int ks=0; ks<2; ks++){
            int kc = ks*16;
            uint32_t bh[4][2], bl[4][2];
#pragma unroll
            for(int ntp=0; ntp<2; ntp++){
                uint32_t off = (uint32_t)(((bRow + ntp*16)*40 + kc + bCol)*2);
                LDSM4(bh[2*ntp][0], bh[2*ntp][1], bh[2*ntp+1][0], bh[2*ntp+1][1], bBh + off);
                LDSM4(bl[2*ntp][0], bl[2*ntp][1], bl[2*ntp+1][0], bl[2*ntp+1][1], bBl + off);
            }
#pragma unroll
            for(int mt=0; mt<4; mt++){
                uint32_t off = (uint32_t)(((aRow + mt*16)*40 + kc + aCol)*2);
                uint32_t ah[4], al[4];
                LDSM4(ah[0],ah[1],ah[2],ah[3], bAh + off);
                LDSM4(al[0],al[1],al[2],al[3], bAl + off);
#pragma unroll
                for(int nt=0; nt<4; nt++){
                    MMA16816(acc[mt][nt], ah, bh[nt]);
                    MMA16816(acc[mt][nt], ah, bl[nt]);
                    MMA16816(acc[mt][nt], al, bh[nt]);
                }
            }
        }
    }
#undef PREF
    float* Cb = C + (size_t)z*sC;
#pragma unroll
    for(int mt=0; mt<4; mt++){
#pragma unroll
        for(int nt=0; nt<4; nt++){
            int n = bn + wn*32 + nt*8 + (lane&3)*2;
#pragma unroll
            for(int h=0; h<2; h++){
                int m = bm + wm*64 + mt*16 + (lane>>2) + h*8;
                float2 o;
                o.x = scale * acc[mt][nt][h*2];
                o.y = scale * acc[mt][nt][h*2+1];
                *reinterpret_cast<float2*>(Cb + (size_t)m*ldc + n) = o;
            }
        }
    }
}

// ---------- bf16x3 MMA GEMM, tile 128x64, B stored K-MAJOR (ldmatrix.trans) ----------
#define MSA (128*40)
#define MSB (32*72)
#define STG64 (2*MSA + 2*MSB)
#define SM_N64 (2*STG64*2)
__global__ __launch_bounds__(256,2)
void gemm_mma_n64t_k(const bf16* __restrict__ Ahp, const bf16* __restrict__ Alp,
                     const bf16* __restrict__ Bhp, const bf16* __restrict__ Blp,
                     float* __restrict__ C, int lda, int ldb, int ldc,
                     long long sA, long long sB, long long sC,
                     const float* __restrict__ AUX, float beta,
                     int kc, long long sSplit)
{
    extern __shared__ bf16 smp[];
    int tid = threadIdx.x, lane = tid & 31, wid = tid >> 5;
    int wm = wid >> 1, wn = wid & 1;
    int bm = blockIdx.y * 128;
    int sp = blockIdx.x, z = blockIdx.z;
    uint32_t sbase = s2u(smp);
    float acc[2][4][4];
#pragma unroll
    for(int i=0;i<2;i++)
#pragma unroll
        for(int j=0;j<4;j++)
#pragma unroll
            for(int q=0;q<4;q++) acc[i][j][q]=0.f;

    int ks = sp * kc;
    int lr = tid >> 1, lsa = (tid & 1) * 16;
    const bf16* gAh = Ahp + (size_t)z*sA + (size_t)(bm+lr)*lda + ks + lsa;
    const bf16* gAl = Alp + (size_t)z*sA + (size_t)(bm+lr)*lda + ks + lsa;
    uint32_t aOff = (uint32_t)((lr*40 + lsa)*2);
    int brow = tid >> 3, bcs = (tid & 7) * 8;
    const bf16* gBh = Bhp + (size_t)z*sB + (size_t)(ks+brow)*ldb + bcs;
    const bf16* gBl = Blp + (size_t)z*sB + (size_t)(ks+brow)*ldb + bcs;
    uint32_t bOff = (uint32_t)((brow*72 + bcs)*2);

    int aCol = (lane>>4)*8;
    int bKr = (lane&7) + ((lane>>3)&1)*8;
    int bNc = (lane>>4)*8;

    int nch = kc >> 5;
#define PREF(ch, st) do{ \
    uint32_t stb = sbase + (uint32_t)(st)*(STG64*2); \
    size_t goA = (size_t)(ch)*32; \
    size_t goB = (size_t)(ch)*32*ldb; \
    CPA(stb + aOff,             gAh+goA, 16); CPA(stb + aOff + 16,             gAh+goA+8, 16); \
    CPA(stb + MSA*2 + aOff,     gAl+goA, 16); CPA(stb + MSA*2 + aOff + 16,     gAl+goA+8, 16); \
    CPA(stb + MSA*4 + bOff,     gBh+goB, 16); \
    CPA(stb + MSA*4 + MSB*2 + bOff, gBl+goB, 16); \
    CPA_COMMIT(); }while(0)

    PREF(0, 0);

    for(int ch=0; ch<nch; ch++){
        CPA_WAIT0();
        __syncthreads();
        if(ch+1 < nch) PREF(ch+1, (ch+1)&1);
        uint32_t stb = sbase + (uint32_t)(ch&1)*(STG64*2);
        uint32_t bAh = stb, bAl = stb + MSA*2;
        uint32_t bBh = stb + MSA*4, bBl = stb + MSA*4 + MSB*2;
#pragma unroll
        for(int ksu=0; ksu<2; ksu++){
            int kb = ksu*16;
            uint32_t bh[4][2], bl[4][2];
#pragma unroll
            for(int ntp=0; ntp<2; ntp++){
                uint32_t off = (uint32_t)(((kb + bKr)*72 + wn*32 + ntp*16 + bNc)*2);
                LDSM4T(bh[2*ntp][0], bh[2*ntp][1], bh[2*ntp+1][0], bh[2*ntp+1][1], bBh + off);
                LDSM4T(bl[2*ntp][0], bl[2*ntp][1], bl[2*ntp+1][0], bl[2*ntp+1][1], bBl + off);
            }
#pragma unroll
            for(int mt=0; mt<2; mt++){
                uint32_t off = (uint32_t)(((wm*32 + mt*16 + (lane&7) + ((lane>>3)&1)*8)*40 + kb + aCol)*2);
                uint32_t ah[4], al[4];
                LDSM4(ah[0],ah[1],ah[2],ah[3], bAh + off);
                LDSM4(al[0],al[1],al[2],al[3], bAl + off);
#pragma unroll
                for(int nt=0; nt<4; nt++){
                    MMA16816(acc[mt][nt], ah, bh[nt]);
                    MMA16816(acc[mt][nt], ah, bl[nt]);
                    MMA16816(acc[mt][nt], al, bh[nt]);
                }
            }
        }
    }
#undef PREF
    float* Cb = C + (size_t)z*sC + (size_t)sp*sSplit;
    const float* Xb = AUX ? AUX + (size_t)z*sC : nullptr;
#pragma unroll
    for(int mt=0; mt<2; mt++){
#pragma unroll
        for(int nt=0; nt<4; nt++){
            int n = wn*32 + nt*8 + (lane&3)*2;
#pragma unroll
            for(int h=0; h<2; h++){
                int m = bm + wm*32 + mt*16 + (lane>>2) + h*8;
                float v0 = acc[mt][nt][h*2], v1 = acc[mt][nt][h*2+1];
                if(Xb){
                    const float* xp = Xb + (size_t)m*ldc + n;
                    v0 += beta*xp[0]; v1 += beta*xp[1];
                }
                float2 o; o.x = v0; o.y = v1;
                *reinterpret_cast<float2*>(Cb + (size_t)m*ldc + n) = o;
            }
        }
    }
}

// ---- batched strided GEMM 64x64 (f32x2): C = scale*(A@B) + beta*AUX + diag*I ----
__global__ __launch_bounds__(128,4)
void gemm64_k(const float* __restrict__ A, const float* __restrict__ B, float* __restrict__ C,
              int M, int N, int K, int lda, int ldb, int ldc,
              long long sA, long long sB, long long sC,
              float scale, float diag, const float* __restrict__ AUX, float beta,
              int nsplit, int kc, long long sSplit,
              bf16* __restrict__ Ch, bf16* __restrict__ Cl)
{
    __shared__ __align__(16) float As[16][64];
    __shared__ __align__(16) float Bs[16][64];
    int z = blockIdx.z;
    int sp = z % nsplit, bidx = z / nsplit;
    const float* Ab = A + (size_t)bidx * sA;
    const float* Bb = B + (size_t)bidx * sB;
    size_t cOff = (size_t)bidx * sC + (size_t)sp * sSplit;
    const float* Xb = AUX ? AUX + cOff : nullptr;
    int bm = blockIdx.y*64, bn = blockIdx.x*64;
    int tid = threadIdx.x;
    int tx = tid & 15, ty = tid >> 4;
    ull acc[4][4];
#pragma unroll
    for(int i=0;i<4;i++)
#pragma unroll
        for(int j=0;j<4;j++) acc[i][j]=0ull;

    int am = tid & 63, akq = (tid >> 6) * 8;
    int bkk = tid >> 4, bn4 = (tid & 15) * 4;
    int ks = sp*kc, ke = ks + kc;

    for(int k0=ks;k0<ke;k0+=16){
        {
            const float* p = Ab + (size_t)(bm+am)*lda + k0 + akq;
            float4 v0 = *reinterpret_cast<const float4*>(p);
            float4 v1 = *reinterpret_cast<const float4*>(p+4);
            As[akq+0][am]=v0.x; As[akq+1][am]=v0.y; As[akq+2][am]=v0.z; As[akq+3][am]=v0.w;
            As[akq+4][am]=v1.x; As[akq+5][am]=v1.y; As[akq+6][am]=v1.z; As[akq+7][am]=v1.w;
        }
        {
            float4 b0 = *reinterpret_cast<const float4*>(Bb + (size_t)(k0+bkk)*ldb + bn + bn4);
            float4 b1 = *reinterpret_cast<const float4*>(Bb + (size_t)(k0+bkk+8)*ldb + bn + bn4);
            *reinterpret_cast<float4*>(&Bs[bkk][bn4])   = b0;
            *reinterpret_cast<float4*>(&Bs[bkk+8][bn4]) = b1;
        }
        __syncthreads();
#pragma unroll
        for(int kk=0;kk<16;kk++){
            ulonglong2 a01 = *reinterpret_cast<const ulonglong2*>(&As[kk][ty*8]);
            ulonglong2 a23 = *reinterpret_cast<const ulonglong2*>(&As[kk][ty*8+4]);
            ull av[4] = {a01.x, a01.y, a23.x, a23.y};
            float4 b4 = *reinterpret_cast<const float4*>(&Bs[kk][tx*4]);
            ull bd[4] = {dup2(b4.x),dup2(b4.y),dup2(b4.z),dup2(b4.w)};
#pragma unroll
            for(int i=0;i<4;i++)
#pragma unroll
                for(int j=0;j<4;j++) fma2(acc[i][j], av[i], bd[j]);
        }
        __syncthreads();
    }
#pragma unroll
    for(int i=0;i<4;i++){
#pragma unroll
        for(int rr=0;rr<2;rr++){
            int m = bm + ty*8 + i*2 + rr;
            float v[4];
            float4 xv = make_float4(0,0,0,0);
            if(Xb) xv = *reinterpret_cast<const float4*>(Xb + (size_t)m*ldc + bn + tx*4);
            float xa[4] = {xv.x, xv.y, xv.z, xv.w};
#pragma unroll
            for(int j=0;j<4;j++){
                v[j] = scale * (rr ? hif(acc[i][j]) : lof(acc[i][j]));
                if(Xb) v[j] += beta * xa[j];
                if(m == bn + tx*4 + j) v[j] += diag;
            }
            size_t off = cOff + (size_t)m*ldc + bn + tx*4;
            *reinterpret_cast<float4*>(C + off) = make_float4(v[0],v[1],v[2],v[3]);
            if(Ch){
                bf16 h[4], l[4];
#pragma unroll
                for(int j=0;j<4;j++) split_bf(v[j], h[j], l[j]);
                *reinterpret_cast<uint2*>(Ch + off) = *reinterpret_cast<uint2*>(h);
                *reinterpret_cast<uint2*>(Cl + off) = *reinterpret_cast<uint2*>(l);
            }
        }
    }
}

// ------------------------- small kernels -------------------------
__global__ void zero_pad_k(){ g_LN[blockIdx.x*256 + threadIdx.x] = 0.f; }
__global__ void set_cls_k(const float* __restrict__ c){
    int i = blockIdx.x*256 + threadIdx.x; g_X[i] = c[i];
}
__global__ void cls_copy_k(){
    int i = blockIdx.x*256 + threadIdx.x; g_X2[i] = g_X[i];
}

__global__ void ln_k(const float* __restrict__ X, const float* __restrict__ g,
                     const float* __restrict__ b, float* __restrict__ Y)
{
    __shared__ float sh[8];
    int row = blockIdx.x, t = threadIdx.x;
    const float* x = X + (size_t)row*D;
    float2 v = *reinterpret_cast<const float2*>(x + 2*t);
    float mu = blkSum256(v.x+v.y, sh) * (1.f/(float)D);
    float d0 = v.x-mu, d1 = v.y-mu;
    float var = blkSum256(d0*d0 + d1*d1, sh) * (1.f/(float)D);
    float rs = rsqrtf(var + 1e-5f);
    float2 gg = *reinterpret_cast<const float2*>(g + 2*t);
    float2 bb = *reinterpret_cast<const float2*>(b + 2*t);
    float2 o; o.x = d0*rs*gg.x + bb.x; o.y = d1*rs*gg.y + bb.y;
    *reinterpret_cast<float2*>(Y + (size_t)row*D + 2*t) = o;
}

__global__ void landmarks_k(){
    int j = blockIdx.x, h = blockIdx.y, d = threadIdx.x;
    float sq = 0.f, sk = 0.f;
    const float* base = g_QKV + (size_t)(j*40)*H3 + h*64 + d;
#pragma unroll 8
    for(int t=0;t<40;t++){ sq += base[(size_t)t*H3]; sk += base[(size_t)t*H3 + 512]; }
    float qv = sq * (0.125f/40.f), kv = sk * (1.f/40.f);
    int idx = h*ML*DHD + j*DHD + d;
    g_ql [idx] = qv;
    g_klT[h*DHD*ML + d*ML + j] = kv;
    bf16 hh,ll;
    split_bf(qv,hh,ll); g_qlh[idx]=hh; g_qll[idx]=ll;
    split_bf(kv,hh,ll); g_klh[idx]=hh; g_kll[idx]=ll;
}
__global__ void landmarksK_k(){
    int j = blockIdx.x, h = blockIdx.y, d = threadIdx.x;
    float sk = 0.f;
    const float* base = g_QKV + (size_t)(j*40)*H3 + h*64 + d + 512;
#pragma unroll 8
    for(int t=0;t<40;t++) sk += base[(size_t)t*H3];
    float kv = sk * (1.f/40.f);
    g_klT[h*DHD*ML + d*ML + j] = kv;
    bf16 hh,ll; split_bf(kv,hh,ll);
    int idx = h*ML*DHD + j*DHD + d;
    g_klh[idx]=hh; g_kll[idx]=ll;
}
__global__ void meanrows_k(){
    int j = blockIdx.x, c = threadIdx.x;
    const float* base = g_LN + (size_t)j*40*D + c;
    float s0 = 0.f, s1 = 0.f;
#pragma unroll 8
    for(int t=0;t<40;t++){ s0 += base[(size_t)t*D]; s1 += base[(size_t)t*D + 256]; }
    g_LNm[j*D + c] = s0; g_LNm[j*D + c + 256] = s1;
}

__global__ void softmax256_k(float* __restrict__ Xp, long long hs){
    __shared__ float sh[8];
    float* x = Xp + (size_t)blockIdx.y*hs + (size_t)blockIdx.x*ML;
    float v = x[threadIdx.x];
    float mx = blkMax256(v, sh);
    float e = __expf(v-mx);
    float s = blkSum256(e, sh);
    x[threadIdx.x] = e/s;
}

// warp-per-row stats over ML-length rows: 8 rows per 256-thread block
__global__ void stats256_k(const float* __restrict__ Xp, long long hs, int rows){
    int warp = threadIdx.x >> 5, lane = threadIdx.x & 31;
    int row = blockIdx.x*8 + warp;
    size_t base = (size_t)blockIdx.y*hs + (size_t)row*ML;
    const float* x = Xp + base;
    float v[8]; float mx = -3.0e38f;
#pragma unroll
    for(int i=0;i<8;i++){ v[i] = x[lane + i*32]; mx = fmaxf(mx, v[i]); }
#pragma unroll
    for(int o=16;o;o>>=1) mx = fmaxf(mx, __shfl_xor_sync(0xffffffffu, mx, o));
    float s = 0.f;
#pragma unroll
    for(int i=0;i<8;i++){ v[i] = __expf(v[i]-mx); s += v[i]; }
#pragma unroll
    for(int o=16;o;o>>=1) s += __shfl_xor_sync(0xffffffffu, s, o);
    float inv = 1.f/s;
#pragma unroll
    for(int i=0;i<8;i++){
        float p = v[i]*inv;
        bf16 hh,ll; split_bf(p,hh,ll);
        g_Ph[base + lane + i*32] = hh;
        g_Pl[base + lane + i*32] = ll;
    }
    if(!lane){
        int g = blockIdx.y*rows + row;
        g_smx[g] = mx; g_sinv[g] = inv;
    }
}
__global__ void stats_long_k(const float* __restrict__ Xp, long long hs, int rows){
    __shared__ float sh[8];
    size_t base = (size_t)blockIdx.y*hs + (size_t)blockIdx.x*NPAD;
    const float* x = Xp + base;
    float sc[40]; float mx = -3.0e38f;
#pragma unroll
    for(int c=0;c<40;c++){ sc[c] = x[c*256+threadIdx.x]; mx = fmaxf(mx, sc[c]); }
    mx = blkMax256(mx, sh);
    float s = 0.f;
#pragma unroll
    for(int c=0;c<40;c++){ sc[c] = __expf(sc[c]-mx); s += sc[c]; }
    s = blkSum256(s, sh);
    float inv = 1.f/s;
#pragma unroll
    for(int c=0;c<40;c++){
        float p = sc[c]*inv;
        bf16 hh,ll; split_bf(p,hh,ll);
        g_Ph[base + c*256 + threadIdx.x] = hh;
        g_Pl[base + c*256 + threadIdx.x] = ll;
    }
    if(!threadIdx.x){
        int g = blockIdx.y*rows + blockIdx.x;
        g_smx[g] = mx; g_sinv[g] = 1.f/s;
    }
}

__global__ void rowsum_k(){
    __shared__ float sh[8];
    float v = fabsf(g_a2[(size_t)blockIdx.x*ML + threadIdx.x]);
    v = blkSum256(v, sh);
    if(!threadIdx.x) g_rsum[blockIdx.x] = v;
}
__global__ void colsum_k(){
    __shared__ float sm[8][33];
    int h = blockIdx.x, j0 = blockIdx.y*32;
    int c = threadIdx.x & 31, r0 = threadIdx.x >> 5;
    float acc = 0.f;
    for(int r=r0; r<ML; r+=8) acc += fabsf(g_a2[h*ML*ML + r*ML + j0 + c]);
    sm[r0][c] = acc; __syncthreads();
    if(threadIdx.x < 32){
        float s = 0.f;
#pragma unroll
        for(int q=0;q<8;q++) s += sm[q][threadIdx.x];
        g_csum[h*ML + j0 + threadIdx.x] = s;
    }
}
__global__ void maxred_k(){
    __shared__ float sh[8];
    float mr = 0.f, mc = 0.f;
    for(int i=threadIdx.x; i<NH*ML; i+=256){ mr = fmaxf(mr, g_rsum[i]); mc = fmaxf(mc, g_csum[i]); }
    mr = blkMax256(mr, sh);
    mc = blkMax256(mc, sh);
    if(!threadIdx.x) g_invden = 1.f/(mr*mc);
}

__global__ void zt_k(){
    __shared__ float t[32][33];
    int h = blockIdx.z, i0 = blockIdx.x*32, j0 = blockIdx.y*32;
    int tx = threadIdx.x & 31, ty = threadIdx.x >> 5;
    float inv = g_invden;
#pragma unroll
    for(int rr=0; rr<32; rr+=8)
        t[ty+rr][tx] = g_a2[h*ML*ML + (i0+ty+rr)*ML + j0+tx];
    __syncthreads();
#pragma unroll
    for(int rr=0; rr<32; rr+=8)
        g_Za[(size_t)h*ML*ML + (j0+ty+rr)*ML + i0+tx] = t[tx][ty+rr]*inv;
}

__global__ void reduce_tt_k(){
    int i = blockIdx.x*256 + threadIdx.x;
    int b = i >> 14, r = i & 16383;
    float s = 0.f;
#pragma unroll
    for(int t=0;t<NSPL;t++) s += g_ttp[((size_t)b*NSPL + t)*16384 + r];
    g_tt[(size_t)b*16384 + r] = s;
}

__global__ __launch_bounds__(256)
void conv_res_k(const float* __restrict__ w){
    __shared__ float sv[96][64];
    __shared__ float swt[33];
    int s0 = blockIdx.x*64, c0 = blockIdx.y*64, h = blockIdx.y;
    int tid = threadIdx.x;
    for(int idx=tid; idx<96*64; idx+=256){
        int r = idx >> 6, c = idx & 63;
        int sp = s0 - 16 + r;
        sv[r][c] = ((unsigned)sp < (unsigned)NPAD) ? g_QKV[(size_t)sp*H3 + 1024 + c0 + c] : 0.f;
    }
    if(tid < 33) swt[tid] = w[h*33 + tid];
    __syncthreads();
    int c = tid & 63, sg = tid >> 6;
    int sb2 = sg*16;
    float acc[16];
#pragma unroll
    for(int s=0;s<16;s++) acc[s] = 0.f;
    for(int r=0;r<48;r++){
        float v = sv[sb2 + r][c];
#pragma unroll
        for(int s=0;s<16;s++){
            int k = r - s;
            if(k >= 0 && k < 33) acc[s] += swt[k]*v;
        }
    }
#pragma unroll
    for(int s=0;s<16;s++) g_O[(size_t)(s0+sb2+s)*D + c0 + c] = acc[s];
}

__global__ __launch_bounds__(256)
void ppeg_k(const float* __restrict__ w7, const float* __restrict__ b7,
            const float* __restrict__ w5, const float* __restrict__ b5,
            const float* __restrict__ w3, const float* __restrict__ b3)
{
    __shared__ float st[14][14][32];
    __shared__ float sw[83][32];
    __shared__ float sb[32];
    int cg = blockIdx.z*32;
    int ti0 = blockIdx.y*8, tj0 = blockIdx.x*8;
    int tid = threadIdx.x;
    for(int idx=tid; idx<14*14*32; idx+=256){
        int r = idx/(14*32); int rem = idx - r*14*32; int col = rem>>5; int cc = rem&31;
        int gi = ti0-3+r, gj = tj0-3+col;
        float v = 0.f;
        if((unsigned)gi < 100u && (unsigned)gj < 100u)
            v = g_X[(size_t)(1 + gi*100 + gj)*D + cg + cc];
        st[r][col][cc] = v;
    }
    for(int idx=tid; idx<83*32; idx+=256){
        int t = idx>>5, cc = idx&31; int ch = cg+cc; float w;
        if(t<49) w = w7[ch*49 + t];
        else if(t<74) w = w5[ch*25 + t-49];
        else w = w3[ch*9 + t-74];
        sw[t][cc] = w;
    }
    if(tid < 32) sb[tid] = b7[cg+tid] + b5[cg+tid] + b3[cg+tid];
    __syncthreads();
    int c = tid & 31, i = tid >> 5;
    float acc[8];
#pragma unroll
    for(int j=0;j<8;j++) acc[j] = st[3+i][3+j][c] + sb[c];
#pragma unroll
    for(int di=-3; di<=3; di++){
        float rv[14];
#pragma unroll
        for(int q=0;q<14;q++) rv[q] = st[3+i+di][q][c];
#pragma unroll
        for(int dj=0;dj<7;dj++){
            float w = sw[(di+3)*7+dj][c];
#pragma unroll
            for(int j=0;j<8;j++) acc[j] += w*rv[j+dj];
        }
        if(di>=-2 && di<=2){
#pragma unroll
            for(int dj=0;dj<5;dj++){
                float w = sw[49+(di+2)*5+dj][c];
#pragma unroll
                for(int j=0;j<8;j++) acc[j] += w*rv[j+dj+1];
            }
        }
        if(di>=-1 && di<=1){
#pragma unroll
            for(int dj=0;dj<3;dj++){
                float w = sw[74+(di+1)*3+dj][c];
#pragma unroll
                for(int j=0;j<8;j++) acc[j] += w*rv[j+dj+2];
            }
        }
    }
    int gi = ti0+i;
    if(gi < 100){
#pragma unroll
        for(int j=0;j<8;j++){
            int gj = tj0+j;
            if(gj < 100) g_X2[(size_t)(1 + gi*100 + gj)*D + cg + c] = acc[j];
        }
    }
}

__global__ void l2row_k(const float* __restrict__ rw, const float* __restrict__ qw){
    __shared__ float q[64];
    __shared__ float p[256];
    __shared__ float sh[8];
    int h = blockIdx.x, j = threadIdx.x;
    if(j < 64){
        const float* x = g_LN + (size_t)PADN*D;
        const float* w = qw + h*64 + j;
        float a = 0.f;
        for(int c=0;c<512;c++) a += x[c]*w[(size_t)c*H3];
        q[j] = a;
    }
    __syncthreads();
    float s = 0.f;
#pragma unroll
    for(int d=0; d<64; d++) s += q[d]*g_klT[h*DHD*ML + d*ML + j];
    s *= 0.125f;
    float mx = blkMax256(s, sh);
    float e = __expf(s - mx);
    float sum = blkSum256(e, sh);
    p[j] = e/sum;
    __syncthreads();
    if(j < 64){
        float acc = 0.f;
        for(int t=0;t<256;t++) acc += p[t]*g_uu[h*ML*DHD + t*64 + j];
#pragma unroll
        for(int t=0;t<33;t++)
            acc += rw[h*33+t] * g_QKV[(size_t)(PADN-16+t)*H3 + 1024 + h*64 + j];
        g_orow[h*64 + j] = acc;
    }
}

__global__ void final_head_k(const float* __restrict__ ow, const float* __restrict__ ob,
                             const float* __restrict__ ng, const float* __restrict__ nb,
                             const float* __restrict__ fw, const float* __restrict__ fb,
                             float* __restrict__ out)
{
    __shared__ float o[512];
    __shared__ float f[512];
    __shared__ float sh[8];
    int t = threadIdx.x;
    o[t] = g_orow[t]; o[t+256] = g_orow[t+256];
    __syncthreads();
#pragma unroll
    for(int half=0; half<2; half++){
        int n = t + half*256;
        float v = ob[n] + g_LN[(size_t)PADN*D + n];
        for(int c=0;c<512;c++) v += o[c]*ow[(size_t)c*D + n];
        f[n] = v;
    }
    __syncthreads();
    float v0 = f[t], v1 = f[t+256];
    float mu = blkSum256(v0+v1, sh)*(1.f/512.f);
    float d0 = v0-mu, d1 = v1-mu;
    float var = blkSum256(d0*d0+d1*d1, sh)*(1.f/512.f);
    float rs = rsqrtf(var + 1e-5f);
    float l0 = d0*rs*ng[t]     + nb[t];
    float l1 = d1*rs*ng[t+256] + nb[t+256];
    float s0 = l0*fw[t*2]   + l1*fw[(t+256)*2];
    float s1 = l0*fw[t*2+1] + l1*fw[(t+256)*2+1];
    s0 = blkSum256(s0, sh);
    s1 = blkSum256(s1, sh);
    if(!t){ out[0] = s0 + fb[0]; out[1] = s1 + fb[1]; }
}

// ------------------------- host -------------------------
#define SYMADDR(T, p, s) do{ void* _t; cudaGetSymbolAddress(&_t, s); p = (T*)_t; }while(0)

extern "C" void kernel_launch(void* const* d_in, const int* in_sizes, int n_in,
                              void* d_out, int out_size)
{
    bool sig = (in_sizes[10] == 25088);
    const float* h_in = (const float*)d_in[0];
    const float* fc1w = (const float*)d_in[1];
    const float* fc1b = (const float*)d_in[2];
    const float* cls  = (const float*)d_in[3];
    const float* g1 = (const float*)d_in[4];
    const float* b1 = (const float*)d_in[5];
    const float* qkv1 = (const float*)d_in[6];
    const float* ow1 = (const float*)d_in[7];
    const float* ob1 = (const float*)d_in[8];
    const float* rw1 = (const float*)d_in[9];
    const float *w7,*b7,*w5,*b5,*w3,*b3,*g2,*b2,*qkv2,*ow2,*ob2,*rw2,*ng,*nb,*f2w,*f2b;
    if(sig){
        w7=(const float*)d_in[10]; b7=(const float*)d_in[11];
        w5=(const float*)d_in[12]; b5=(const float*)d_in[13];
        w3=(const float*)d_in[14]; b3=(const float*)d_in[15];
        g2=(const float*)d_in[16]; b2=(const float*)d_in[17];
        qkv2=(const float*)d_in[18]; ow2=(const float*)d_in[19];
        ob2=(const float*)d_in[20]; rw2=(const float*)d_in[21];
    } else {
        g2=(const float*)d_in[10]; b2=(const float*)d_in[11];
        qkv2=(const float*)d_in[12]; ow2=(const float*)d_in[13];
        ob2=(const float*)d_in[14]; rw2=(const float*)d_in[15];
        w7=(const float*)d_in[16]; b7=(const float*)d_in[17];
        w5=(const float*)d_in[18]; b5=(const float*)d_in[19];
        w3=(const float*)d_in[20]; b3=(const float*)d_in[21];
    }
    ng=(const float*)d_in[22]; nb=(const float*)d_in[23];
    f2w=(const float*)d_in[24]; f2b=(const float*)d_in[25];

    float *X,*X2,*LN,*LNm,*QKV,*klT,*ql,*a1,*a3,*a2,*Za,*Zb,*XZ,*M2p,*M4p,*ttp,*tt,*uu,*Ob,*smx,*sinv;
    bf16 *Ah,*Al,*Wth,*Wtl,*KVh,*KVl,*qlh,*qll,*klh,*kll,*Ph,*Pl,*uuh,*uul;
    SYMADDR(float,X,g_X); SYMADDR(float,X2,g_X2); SYMADDR(float,LN,g_LN); SYMADDR(float,LNm,g_LNm);
    SYMADDR(float,QKV,g_QKV); SYMADDR(float,klT,g_klT); SYMADDR(float,ql,g_ql);
    SYMADDR(float,a1,g_a1); SYMADDR(float,a3,g_a3); SYMADDR(float,a2,g_a2);
    SYMADDR(float,Za,g_Za); SYMADDR(float,Zb,g_Zb); SYMADDR(float,XZ,g_XZ);
    SYMADDR(float,M2p,g_M2); SYMADDR(float,M4p,g_M4); SYMADDR(float,ttp,g_ttp);
    SYMADDR(float,tt,g_tt); SYMADDR(float,uu,g_uu); SYMADDR(float,Ob,g_O);
    SYMADDR(float,smx,g_smx); SYMADDR(float,sinv,g_sinv);
    SYMADDR(bf16,Ah,g_Ah); SYMADDR(bf16,Al,g_Al); SYMADDR(bf16,Wth,g_Wth); SYMADDR(bf16,Wtl,g_Wtl);
    SYMADDR(bf16,KVh,g_KVh); SYMADDR(bf16,KVl,g_KVl);
    SYMADDR(bf16,qlh,g_qlh); SYMADDR(bf16,qll,g_qll);
    SYMADDR(bf16,klh,g_klh); SYMADDR(bf16,kll,g_kll);
    SYMADDR(bf16,Ph,g_Ph); SYMADDR(bf16,Pl,g_Pl);
    SYMADDR(bf16,uuh,g_uuh); SYMADDR(bf16,uul,g_uul);

    static cudaStream_t s1 = nullptr, s2 = nullptr;
    static cudaEvent_t ev[8];
    if(!s1){
        cudaStreamCreateWithFlags(&s1, cudaStreamNonBlocking);
        cudaStreamCreateWithFlags(&s2, cudaStreamNonBlocking);
        for(int i=0;i<8;i++) cudaEventCreateWithFlags(&ev[i], cudaEventDisableTiming);
        cudaFuncSetAttribute(gemm_mma_k, cudaFuncAttributeMaxDynamicSharedMemorySize, SM_MMA);
        cudaFuncSetAttribute(gemm_mma_b_k, cudaFuncAttributeMaxDynamicSharedMemorySize, SM_MMA);
        cudaFuncSetAttribute(gemm_mma_n64t_k, cudaFuncAttributeMaxDynamicSharedMemorySize, SM_N64);
    }
    cudaEvent_t evX = ev[6], evW = ev[7];

    zero_pad_k<<<PADN*D/256, 256>>>();
    cvt_rows_k<<<10000*1024/1024, 256>>>(h_in, Ah, Al);
    cvt_T_k<<<dim3(32,16),256>>>(fc1w, Wth, Wtl, 1024, 512);
    gemm_mma_k<<<dim3(4,79),256,SM_MMA>>>(Ah, Al, Wth, Wtl, fc1b, nullptr, X+D,
                                          10000, 512, 1024, D, 1, 0, 1, nullptr, nullptr);
    set_cls_k<<<2,256>>>(cls);

    long long sM = (long long)ML*ML;
    for(int layer=0; layer<2; layer++){
        const float* xin = layer ? X2 : X;
        const float* gg = layer ? g2 : g1;
        const float* bb = layer ? b2 : b1;
        const float* qw = layer ? qkv2 : qkv1;
        cudaEvent_t evF = ev[layer*3+0], evA = ev[layer*3+1], evB = ev[layer*3+2];

        ln_k<<<NSEQ,256>>>(xin, gg, bb, LN + (size_t)PADN*D);
        cvt_rows_k<<<NPAD*512/1024, 256>>>(LN, Ah, Al);

        const float* Aq; int ldaQ; long long sAQ;
        const bf16 *AqH, *AqL; int ldaQb; long long sAQb;
        if(layer == 0){
            cvt_T_k<<<dim3(16,48),256>>>(qw, Wth, Wtl, 512, 1536);
            gemm_mma_k<<<dim3(12,80),256,SM_MMA>>>(Ah, Al, Wth, Wtl, nullptr, nullptr, QKV,
                                                   NPAD, 1536, 512, H3, 0, 0, 0, KVh, KVl);
            landmarks_k<<<dim3(ML,NH),64>>>();
            Aq = ql; ldaQ = DHD; sAQ = (long long)ML*DHD;
            AqH = qlh; AqL = qll; ldaQb = DHD; sAQb = (long long)ML*DHD;
        } else {
            cvt_T_k<<<dim3(16,32),256>>>(qw+512, Wth, Wtl, 512, 1536);
            gemm_mma_k<<<dim3(8,80),256,SM_MMA>>>(Ah, Al, Wth, Wtl, nullptr, nullptr, QKV+512,
                                                  NPAD, 1024, 512, H3, 0, 0, 0, KVh+512, KVl+512);
            meanrows_k<<<ML,256>>>();
            gemm64_k<<<dim3(8,4,1),128>>>(LNm, qw, ql, ML, 512, 512, 512, H3, 512,
                        0,0,0, 0.125f/40.f, 0.f, nullptr, 0.f, 1, 512, 0, qlh, qll);
            landmarksK_k<<<dim3(ML,NH),64>>>();
            Aq = ql; ldaQ = 512; sAQ = 64;
            AqH = qlh; AqL = qll; ldaQb = 512; sAQb = 64;
        }

        // a2 = ql @ kl^T via tensor cores, then softmax
        gemm_mma_b_k<<<dim3(ML/128, ML/128, NH),256,SM_MMA>>>(AqH, AqL, klh, kll,
                    a2, ML, DHD, ldaQb, DHD, ML, sAQb, (long long)ML*DHD, sM, 1.f);
        softmax256_k<<<dim3(ML,NH),256>>>(a2, sM);

        // ---- fork: pinv chain on s1 (W sidecar on s2), conv on s2 first (layer 0) ----
        cudaEventRecord(evF, 0);
        cudaStreamWaitEvent(s1, evF, 0);
        if(layer == 0){
            cudaStreamWaitEvent(s2, evF, 0);
            conv_res_k<<<dim3(NPAD/64, NH),256,0,s2>>>(rw1);
            cudaEventRecord(evB, s2);
        } else {
            cudaStreamWaitEvent(s2, evF, 0);
        }
        rowsum_k<<<NH*ML,256,0,s1>>>();
        colsum_k<<<dim3(NH,8),256,0,s1>>>();
        maxred_k<<<1,256,0,s1>>>();
        zt_k<<<dim3(8,8,NH),256,0,s1>>>();
        float* za = Za; float* zb = Zb;
        for(int it=0; it<6; it++){
            gemm64_k<<<dim3(4,4,NH),128,0,s1>>>(a2, za, XZ, ML,ML,ML, ML,ML,ML, sM,sM,sM,
                        1.f,0.f, nullptr,0.f, 1,ML,0, nullptr,nullptr);
            cudaEventRecord(evX, s1);
            cudaStreamWaitEvent(s2, evX, 0);
            gemm64_k<<<dim3(4,4,NH),128,0,s2>>>(za, XZ, M4p, ML,ML,ML, ML,ML,ML, sM,sM,sM,
                        1.f,0.f, nullptr,0.f, 1,ML,0, nullptr,nullptr);
            cudaEventRecord(evW, s2);
            gemm64_k<<<dim3(4,4,NH),128,0,s1>>>(XZ, XZ, M2p, ML,ML,ML, ML,ML,ML, sM,sM,sM,
                        -1.f,-15.f, XZ,7.f, 1,ML,0, nullptr,nullptr);
            cudaStreamWaitEvent(s1, evW, 0);
            gemm64_k<<<dim3(4,4,NH),128,0,s1>>>(M4p, M2p, zb, ML,ML,ML, ML,ML,ML, sM,sM,sM,
                        0.25f,0.f, za,3.25f, 1,ML,0, nullptr,nullptr);
            float* tmp = za; za = zb; zb = tmp;
        }
        cudaEventRecord(evA, s1);

        // ---- main stream: a3 (MMA) -> stats+P3 -> tt (MMA, split-K) ----
        gemm_mma_b_k<<<dim3(NPAD/128, ML/128, NH),256,SM_MMA>>>(AqH, AqL, KVh+512, KVl+512,
                    a3, NPAD, DHD, ldaQb, H3, NPAD, sAQb, 64LL, (long long)ML*NPAD, 1.f);
        stats_long_k<<<dim3(ML,NH),256>>>(a3, (long long)ML*NPAD, ML);
        gemm_mma_n64t_k<<<dim3(NSPL, ML/128, NH),256,SM_N64>>>(Ph, Pl, KVh+1024, KVl+1024,
                    ttp, NPAD, H3, DHD, (long long)ML*NPAD, 64LL, (long long)NSPL*ML*DHD,
                    nullptr, 0.f, KCH, (long long)ML*DHD);
        reduce_tt_k<<<NH*ML*DHD/256,256>>>();
        if(layer == 0){
            gemm_mma_b_k<<<dim3(ML/128, NPAD/128, NH),256,SM_MMA>>>(KVh, KVl, klh, kll,
                    a1, ML, DHD, H3, DHD, ML, 64LL, (long long)ML*DHD, (long long)NPAD*ML, 0.125f);
            stats256_k<<<dim3(NPAD/8,NH),256>>>(a1, (long long)NPAD*ML, NPAD);
        }

        // ---- join pinv, compute uu (+bf16 split) ----
        cudaStreamWaitEvent(0, evA, 0);
        gemm64_k<<<dim3(1,4,NH),128>>>(za, tt, uu, ML,DHD,ML, ML,DHD,DHD,
                    sM,(long long)ML*DHD,(long long)ML*DHD, 1.f,0.f, nullptr,0.f, 1,ML,0,
                    uuh, uul);

        if(layer == 0){
            cudaStreamWaitEvent(0, evB, 0);
            gemm_mma_n64t_k<<<dim3(1, NPAD/128, NH),256,SM_N64>>>(Ph, Pl, uuh, uul,
                    Ob, ML, DHD, D, (long long)NPAD*ML, (long long)ML*DHD, 64LL,
                    Ob, 1.f, ML, 0);
            cvt_rows_k<<<NPAD*512/1024, 256>>>(Ob, Ah, Al);
            cvt_T_k<<<dim3(16,16),256>>>(ow1, Wth, Wtl, 512, 512);
            gemm_mma_k<<<dim3(4,79),256,SM_MMA>>>(Ah + (size_t)PADN*D, Al + (size_t)PADN*D,
                                                  Wth, Wtl, ob1, LN + (size_t)PADN*D, X,
                                                  NSEQ, 512, 512, D, 1, 1, 0, nullptr, nullptr);
            ppeg_k<<<dim3(13,13,16),256>>>(w7,b7,w5,b5,w3,b3);
            cls_copy_k<<<2,256>>>();
        } else {
            l2row_k<<<NH,256>>>(rw2, qw);
            final_head_k<<<1,256>>>(ow2, ob2, ng, nb, f2w, f2b, (float*)d_out);
        }
    }
}